// round 2
// baseline (speedup 1.0000x reference)
#include <cuda_runtime.h>
#include <math.h>

// ---------------- problem constants ----------------
#define BATCH 64
#define C0C   6          // 2*C
#define FC    96
#define KMIX  8
#define HWP   1024       // 32*32
#define SEQ   1024
#define COUT2 156        // 6+6+48+48+48

// ---------------- scratch (device globals; no allocs) ----------------
__device__ float g_z0 [BATCH*C0C*HWP];
__device__ float g_z1 [BATCH*C0C*HWP];
__device__ float g_x1 [BATCH*FC*HWP];          // conv1 out -> gated -> ln1 (in place)
__device__ float g_g  [BATCH*2*FC*HWP];        // gconv out
__device__ float g_xf [BATCH*SEQ*FC];          // token-major features (residual base)
__device__ float g_qkv[BATCH*SEQ*3*FC];
__device__ float g_sc [BATCH*SEQ*SEQ];         // attention scores (268MB)
__device__ float g_o  [BATCH*SEQ*FC];
__device__ float g_pr [BATCH*SEQ*2*FC];
__device__ float g_x2 [BATCH*FC*HWP];          // attn out channel-major -> ln2 in place
__device__ float g_par[BATCH*COUT2*HWP];

// ---------------- helpers ----------------
__device__ __forceinline__ float warp_sum(float v){
    #pragma unroll
    for (int o=16;o;o>>=1) v += __shfl_xor_sync(0xffffffffu, v, o);
    return v;
}
__device__ __forceinline__ float warp_max(float v){
    #pragma unroll
    for (int o=16;o;o>>=1) v = fmaxf(v, __shfl_xor_sync(0xffffffffu, v, o));
    return v;
}
__device__ __forceinline__ float sigf(float v){ return 1.0f/(1.0f+expf(-v)); }
// stable log(sigmoid(v))
__device__ __forceinline__ float logsigf(float v){ return fminf(v,0.0f) - log1pf(expf(-fabsf(v))); }

// ---------------- 1. checkerboard split ----------------
__global__ void split_kernel(const float* __restrict__ z){
    int idx = blockIdx.x*blockDim.x + threadIdx.x;   // (b,c,i,j) c<3
    if (idx >= BATCH*3*HWP) return;
    int j = idx & 31, i = (idx>>5) & 31;
    int c = (idx>>10) % 3;
    int b = idx / (3*HWP);
    const float* zb = z + ((long long)b*3 + c)*64*64;
    float p00 = zb[(2*i  )*64 + 2*j  ];
    float p01 = zb[(2*i  )*64 + 2*j+1];
    float p10 = zb[(2*i+1)*64 + 2*j  ];
    float p11 = zb[(2*i+1)*64 + 2*j+1];
    int base = ((b*C0C)+c)*HWP + i*32 + j;
    g_z0[base]          = p00;
    g_z0[base + 3*HWP]  = p11;
    g_z1[base]          = p01;
    g_z1[base + 3*HWP]  = p10;
}

// ---------------- 2. direct 3x3 conv (SAME), smem input tile ----------------
// grid: (ceil(Cout/8), B), block 256. Each thread: 4 spatial positions x 8 out ch.
template<int CIN>
__global__ void conv3x3_kernel(const float* __restrict__ in, const float* __restrict__ w,
                               const float* __restrict__ bias, float* __restrict__ out, int Cout){
    __shared__ float tile[34*34];
    __shared__ float wsh[8][9];
    int b  = blockIdx.y;
    int co0= blockIdx.x*8;
    int tid= threadIdx.x;
    float acc[8][4];
    #pragma unroll
    for (int a=0;a<8;a++) { acc[a][0]=acc[a][1]=acc[a][2]=acc[a][3]=0.f; }
    const float* inb = in + (long long)b*CIN*HWP;
    for (int ci=0; ci<CIN; ci++){
        for (int idx=tid; idx<34*34; idx+=256){
            int ty=idx/34, tx=idx-ty*34;
            int y=ty-1, x=tx-1;
            tile[idx] = (y>=0 && y<32 && x>=0 && x<32) ? inb[ci*HWP + y*32 + x] : 0.f;
        }
        if (tid < 72){
            int co=tid/9, j=tid-co*9;
            wsh[co][j] = (co0+co < Cout) ? w[((long long)(co0+co)*CIN + ci)*9 + j] : 0.f;
        }
        __syncthreads();
        #pragma unroll
        for (int p=0;p<4;p++){
            int pos = tid + 256*p;
            int y = pos>>5, x = pos&31;
            float v[9];
            #pragma unroll
            for (int dy=0;dy<3;dy++)
                #pragma unroll
                for (int dx=0;dx<3;dx++)
                    v[dy*3+dx] = tile[(y+dy)*34 + x+dx];
            #pragma unroll
            for (int co=0;co<8;co++){
                #pragma unroll
                for (int j=0;j<9;j++) acc[co][p] += v[j]*wsh[co][j];
            }
        }
        __syncthreads();
    }
    #pragma unroll
    for (int co=0;co<8;co++){
        if (co0+co < Cout){
            float bb = bias[co0+co];
            #pragma unroll
            for (int p=0;p<4;p++){
                int pos = tid + 256*p;
                out[((long long)b*Cout + co0+co)*HWP + pos] = acc[co][p] + bb;
            }
        }
    }
}

// ---------------- 3. conv gating: x += ga*sigmoid(gb) ----------------
__global__ void gate_conv_kernel(){
    int idx = blockIdx.x*blockDim.x + threadIdx.x;
    if (idx >= BATCH*FC*HWP) return;
    int b = idx/(FC*HWP);
    int r = idx - b*FC*HWP;
    int c = r/HWP, p = r - c*HWP;
    long long gb_base = ((long long)b*2*FC)*HWP;
    float ga = g_g[gb_base + (long long)c*HWP + p];
    float gs = g_g[gb_base + (long long)(c+FC)*HWP + p];
    g_x1[idx] += ga * sigf(gs);
}

// ---------------- 4. full-sample LayerNorm, per-element affine, in place ----------------
__global__ void layernorm_kernel(float* __restrict__ x, const float* __restrict__ gam,
                                 const float* __restrict__ bet){
    const int N = FC*HWP;
    int b = blockIdx.x;
    float* xb = x + (long long)b*N;
    float s=0.f, s2=0.f;
    for (int i=threadIdx.x;i<N;i+=blockDim.x){ float v=xb[i]; s+=v; s2+=v*v; }
    __shared__ float shs[32], shs2[32];
    int lane = threadIdx.x&31, wid = threadIdx.x>>5;
    s = warp_sum(s); s2 = warp_sum(s2);
    if (lane==0){ shs[wid]=s; shs2[wid]=s2; }
    __syncthreads();
    int nw = blockDim.x>>5;
    if (wid==0){
        float a = (lane<nw)? shs[lane]:0.f;
        float a2= (lane<nw)? shs2[lane]:0.f;
        a = warp_sum(a); a2 = warp_sum(a2);
        if (lane==0){ shs[0]=a; shs2[0]=a2; }
    }
    __syncthreads();
    float mean = shs[0]/(float)N;
    float var  = shs2[0]/(float)N - mean*mean;
    float inv  = rsqrtf(var + 1e-5f);
    for (int i=threadIdx.x;i<N;i+=blockDim.x)
        xb[i] = (xb[i]-mean)*inv*gam[i] + bet[i];
}

// ---------------- 5. transposes ----------------
__global__ void to_tokenmajor_kernel(){   // g_xf[b,t,f] = g_x1[b,f,t]
    int idx = blockIdx.x*blockDim.x + threadIdx.x;
    if (idx >= BATCH*SEQ*FC) return;
    int f = idx % FC;
    int t = (idx/FC) % SEQ;
    int b = idx/(SEQ*FC);
    g_xf[idx] = g_x1[((long long)b*FC + f)*HWP + t];
}
__global__ void to_chanmajor_kernel(){    // g_x2[b,f,t] = g_xf[b,t,f]
    int idx = blockIdx.x*blockDim.x + threadIdx.x;
    if (idx >= BATCH*FC*HWP) return;
    int t = idx % HWP;
    int f = (idx/HWP) % FC;
    int b = idx/(FC*HWP);
    g_x2[idx] = g_xf[((long long)b*SEQ + t)*FC + f];
}

// ---------------- 6. batched SGEMM, 64x64 tile, 4x4/thread ----------------
// C = alpha * A*op(B) + bias.  TB: B is (N,K) row-major (use B^T); else (K,N).
// Requires: M %64==0, K %16==0 (true for all uses here). N guarded.
template<bool TB>
__global__ void gemm_kernel(const float* __restrict__ A, const float* __restrict__ Bm,
                            float* __restrict__ C,
                            int M, int N, int K, int lda, int ldb, int ldc,
                            long long sA, long long sB, long long sC,
                            const float* __restrict__ bias, float alpha){
    __shared__ float As[16][64];
    __shared__ float Bs[16][64];
    A += blockIdx.z * sA;
    Bm+= blockIdx.z * sB;
    C += blockIdx.z * sC;
    int n0 = blockIdx.x*64;
    int m0 = blockIdx.y*64;
    int tid = threadIdx.x;
    int tx = tid & 15, ty = tid >> 4;
    float acc[4][4];
    #pragma unroll
    for (int i=0;i<4;i++){ acc[i][0]=acc[i][1]=acc[i][2]=acc[i][3]=0.f; }

    int ra = tid>>2;            // 0..63
    int ca = (tid&3)*4;         // 0,4,8,12
    int rb = tid>>4;            // 0..15 (NN)
    int cb = (tid&15)*4;        // 0..60 (NN)

    for (int k0=0; k0<K; k0+=16){
        #pragma unroll
        for (int j=0;j<4;j++)
            As[ca+j][ra] = A[(long long)(m0+ra)*lda + (k0+ca+j)];
        if (TB){
            int n = n0 + ra;
            #pragma unroll
            for (int j=0;j<4;j++)
                Bs[ca+j][ra] = (n<N) ? Bm[(long long)n*ldb + (k0+ca+j)] : 0.f;
        } else {
            #pragma unroll
            for (int j=0;j<4;j++){
                int n = n0 + cb + j;
                Bs[rb][cb+j] = (n<N) ? Bm[(long long)(k0+rb)*ldb + n] : 0.f;
            }
        }
        __syncthreads();
        #pragma unroll
        for (int kk=0;kk<16;kk++){
            float4 av = *(const float4*)&As[kk][ty*4];
            float4 bv = *(const float4*)&Bs[kk][tx*4];
            float a[4] = {av.x,av.y,av.z,av.w};
            float bb[4]= {bv.x,bv.y,bv.z,bv.w};
            #pragma unroll
            for (int i=0;i<4;i++)
                #pragma unroll
                for (int j=0;j<4;j++)
                    acc[i][j] += a[i]*bb[j];
        }
        __syncthreads();
    }
    #pragma unroll
    for (int i=0;i<4;i++){
        int m = m0 + ty*4 + i;
        #pragma unroll
        for (int j=0;j<4;j++){
            int n = n0 + tx*4 + j;
            if (n < N){
                float v = alpha*acc[i][j];
                if (bias) v += bias[n];
                C[(long long)m*ldc + n] = v;
            }
        }
    }
}

// ---------------- 7. row softmax over 1024 ----------------
__global__ void softmax_kernel(float* __restrict__ s){
    long long row = blockIdx.x;
    float* p = s + row*SEQ;
    int t = threadIdx.x;                 // 128 threads
    __shared__ float sh[4];
    float m = -1e30f;
    for (int i=t;i<SEQ;i+=128) m = fmaxf(m, p[i]);
    m = warp_max(m);
    if ((t&31)==0) sh[t>>5] = m;
    __syncthreads();
    m = fmaxf(fmaxf(sh[0],sh[1]), fmaxf(sh[2],sh[3]));
    float sum = 0.f;
    for (int i=t;i<SEQ;i+=128){ float e = __expf(p[i]-m); p[i]=e; sum+=e; }
    sum = warp_sum(sum);
    if ((t&31)==0) sh[t>>5] = sum;
    __syncthreads();
    sum = sh[0]+sh[1]+sh[2]+sh[3];
    float inv = 1.0f/sum;
    for (int i=t;i<SEQ;i+=128) p[i] *= inv;
}

// ---------------- 8. attention gating (residual) ----------------
__global__ void gate_attn_kernel(){
    int idx = blockIdx.x*blockDim.x + threadIdx.x;
    if (idx >= BATCH*SEQ*FC) return;
    int f = idx % FC;
    int t = (idx/FC) % SEQ;
    int b = idx/(SEQ*FC);
    long long pr = ((long long)b*SEQ + t)*2*FC;
    float ga = g_pr[pr + f];
    float gb = g_pr[pr + FC + f];
    g_xf[idx] += ga * sigf(gb);
}

// ---------------- 9. logdet init ----------------
__global__ void init_log_kernel(const float* __restrict__ ldf, float* __restrict__ out_log){
    int b = threadIdx.x;
    if (b < BATCH) out_log[b] = ldf[b];
}

// ---------------- 10. mixture-of-logistics + logit + affine + merge ----------------
__global__ void mixture_kernel(const float* __restrict__ als, const float* __restrict__ ab,
                               float* __restrict__ out_z, float* __restrict__ out_log){
    int b  = blockIdx.x;
    int c0 = blockIdx.y;             // 0..5
    int p  = threadIdx.x;            // 0..1023
    const float* P = g_par + (long long)b*COUT2*HWP;

    float aRaw = P[(long long)c0*HWP + p];
    float bRaw = P[(long long)(6+c0)*HWP + p];
    float lp[KMIX], mu[KMIX], ss[KMIX];
    #pragma unroll
    for (int k=0;k<KMIX;k++){
        lp[k] = P[(long long)(12 + k*C0C + c0)*HWP + p];
        mu[k] = P[(long long)(60 + k*C0C + c0)*HWP + p];
        ss[k] = P[(long long)(108+ k*C0C + c0)*HWP + p];
    }
    float a = tanhf(aRaw)*als[0] + ab[0];

    // log_softmax over k
    float mx = lp[0];
    #pragma unroll
    for (int k=1;k<KMIX;k++) mx = fmaxf(mx, lp[k]);
    float se = 0.f;
    #pragma unroll
    for (int k=0;k<KMIX;k++) se += expf(lp[k]-mx);
    float lse = mx + logf(se);

    float z0v = g_z0[((long long)b*C0C + c0)*HWP + p];
    float tvals[KMIX];
    float xsum = 0.f;
    #pragma unroll
    for (int k=0;k<KMIX;k++){
        float lpn = lp[k] - lse;
        float u   = (z0v - mu[k]) * expf(-ss[k]);
        xsum += expf(lpn) * sigf(u);
        tvals[k] = lpn - ss[k] + logsigf(u) + logsigf(-u);
    }
    float tm = tvals[0];
    #pragma unroll
    for (int k=1;k<KMIX;k++) tm = fmaxf(tm, tvals[k]);
    float tse = 0.f;
    #pragma unroll
    for (int k=0;k<KMIX;k++) tse += expf(tvals[k]-tm);
    float logpdf = tm + logf(tse);

    float x = fminf(fmaxf(xsum, 1e-6f), 1.0f-1e-6f);
    float lx  = logf(x);
    float l1x = log1pf(-x);
    float z0n = (lx - l1x) * expf(a) + bRaw;
    float contrib = logpdf + (-lx - l1x) + a;

    // merge write
    int i = p>>5, j = p&31;
    float z1v = g_z1[((long long)b*C0C + c0)*HWP + p];
    if (c0 < 3){
        float* ob = out_z + ((long long)b*3 + c0)*64*64;
        ob[(2*i)*64 + 2*j    ] = z0n;   // p00
        ob[(2*i)*64 + 2*j + 1] = z1v;   // p01
    } else {
        float* ob = out_z + ((long long)b*3 + (c0-3))*64*64;
        ob[(2*i+1)*64 + 2*j + 1] = z0n; // p11
        ob[(2*i+1)*64 + 2*j    ] = z1v; // p10
    }

    // block reduce contrib -> atomicAdd
    __shared__ float sh[32];
    int lane = p&31, wid = p>>5;
    float v = warp_sum(contrib);
    if (lane==0) sh[wid]=v;
    __syncthreads();
    if (wid==0){
        float w = (lane<32)? sh[lane] : 0.f;
        w = warp_sum(w);
        if (lane==0) atomicAdd(&out_log[b], w);
    }
}

// ---------------- host launcher ----------------
extern "C" void kernel_launch(void* const* d_in, const int* in_sizes, int n_in,
                              void* d_out, int out_size){
    const float* z        = (const float*)d_in[0];
    const float* log_df   = (const float*)d_in[1];
    const float* conv1_w  = (const float*)d_in[2];
    const float* conv1_b  = (const float*)d_in[3];
    const float* gconv_w  = (const float*)d_in[4];
    const float* gconv_b  = (const float*)d_in[5];
    const float* ln1_g    = (const float*)d_in[6];
    const float* ln1_b    = (const float*)d_in[7];
    const float* qkv_w    = (const float*)d_in[8];
    const float* qkv_b    = (const float*)d_in[9];
    const float* proj_w   = (const float*)d_in[10];
    const float* proj_b   = (const float*)d_in[11];
    const float* ln2_g    = (const float*)d_in[12];
    const float* ln2_b    = (const float*)d_in[13];
    const float* conv2_w  = (const float*)d_in[14];
    const float* conv2_b  = (const float*)d_in[15];
    const float* a_ls     = (const float*)d_in[16];
    const float* a_bias   = (const float*)d_in[17];

    float* out_z   = (float*)d_out;
    float* out_log = (float*)d_out + (long long)BATCH*3*64*64;

    float *p_z1, *p_x1, *p_g, *p_xf, *p_qkv, *p_sc, *p_o, *p_pr, *p_x2, *p_par;
    cudaGetSymbolAddress((void**)&p_z1,  g_z1);
    cudaGetSymbolAddress((void**)&p_x1,  g_x1);
    cudaGetSymbolAddress((void**)&p_g,   g_g);
    cudaGetSymbolAddress((void**)&p_xf,  g_xf);
    cudaGetSymbolAddress((void**)&p_qkv, g_qkv);
    cudaGetSymbolAddress((void**)&p_sc,  g_sc);
    cudaGetSymbolAddress((void**)&p_o,   g_o);
    cudaGetSymbolAddress((void**)&p_pr,  g_pr);
    cudaGetSymbolAddress((void**)&p_x2,  g_x2);
    cudaGetSymbolAddress((void**)&p_par, g_par);

    // 1. split
    split_kernel<<<(BATCH*3*HWP+255)/256, 256>>>(z);
    // 2. conv1: 6 -> 96
    conv3x3_kernel<6><<<dim3(12, BATCH), 256>>>(p_z1, conv1_w, conv1_b, p_x1, FC);
    // 3. gconv: 96 -> 192
    conv3x3_kernel<96><<<dim3(24, BATCH), 256>>>(p_x1, gconv_w, gconv_b, p_g, 2*FC);
    // 4. gate
    gate_conv_kernel<<<(BATCH*FC*HWP+255)/256, 256>>>();
    // 5. ln1
    layernorm_kernel<<<BATCH, 1024>>>(p_x1, ln1_g, ln1_b);
    // 6. to token-major
    to_tokenmajor_kernel<<<(BATCH*SEQ*FC+255)/256, 256>>>();
    // 7. qkv = xf @ qkv_w^T + b   (M=1024,N=288,K=96)
    gemm_kernel<true><<<dim3(5,16,BATCH), 256>>>(p_xf, qkv_w, p_qkv,
        SEQ, 3*FC, FC, FC, FC, 3*FC,
        (long long)SEQ*FC, 0LL, (long long)SEQ*3*FC, qkv_b, 1.0f);
    // 8. scores = q @ k^T / sqrt(F)  (M=N=1024,K=96)
    gemm_kernel<true><<<dim3(16,16,BATCH), 256>>>(p_qkv, p_qkv + FC, p_sc,
        SEQ, SEQ, FC, 3*FC, 3*FC, SEQ,
        (long long)SEQ*3*FC, (long long)SEQ*3*FC, (long long)SEQ*SEQ,
        nullptr, rsqrtf((float)FC));
    // 9. softmax rows
    softmax_kernel<<<BATCH*SEQ, 128>>>(p_sc);
    // 10. o = attn @ v  (M=1024,N=96,K=1024)
    gemm_kernel<false><<<dim3(2,16,BATCH), 256>>>(p_sc, p_qkv + 2*FC, p_o,
        SEQ, FC, SEQ, SEQ, 3*FC, FC,
        (long long)SEQ*SEQ, (long long)SEQ*3*FC, (long long)SEQ*FC,
        nullptr, 1.0f);
    // 11. proj = o @ proj_w^T + b  (M=1024,N=192,K=96)
    gemm_kernel<true><<<dim3(3,16,BATCH), 256>>>(p_o, proj_w, p_pr,
        SEQ, 2*FC, FC, FC, FC, 2*FC,
        (long long)SEQ*FC, 0LL, (long long)SEQ*2*FC, proj_b, 1.0f);
    // 12. attn gate (residual into xf)
    gate_attn_kernel<<<(BATCH*SEQ*FC+255)/256, 256>>>();
    // 13. back to channel-major
    to_chanmajor_kernel<<<(BATCH*FC*HWP+255)/256, 256>>>();
    // 14. ln2
    layernorm_kernel<<<BATCH, 1024>>>(p_x2, ln2_g, ln2_b);
    // 15. conv2: 96 -> 156
    conv3x3_kernel<96><<<dim3(20, BATCH), 256>>>(p_x2, conv2_w, conv2_b, p_par, COUT2);
    // 16. logdet init + mixture/merge
    init_log_kernel<<<1, 64>>>(log_df, out_log);
    mixture_kernel<<<dim3(BATCH, C0C), 1024>>>(a_ls, a_bias, out_z, out_log);
}

// round 4
// speedup vs baseline: 1.2639x; 1.2639x over previous
#include <cuda_runtime.h>
#include <math.h>

// ---------------- problem constants ----------------
#define BATCH 64
#define C0C   6
#define FC    96
#define KMIX  8
#define HWP   1024
#define SEQ   1024
#define COUT2 156

// flash tile config
#define QT    128
#define QS_LD 132
#define KS_LD 68
#define VS_LD 100
#define PS_LD 68

// ---------------- scratch ----------------
__device__ float g_z0 [BATCH*C0C*HWP];
__device__ float g_z1 [BATCH*C0C*HWP];
__device__ float g_x1 [BATCH*FC*HWP];      // conv1 output (read-only during gconv)
__device__ float g_xg [BATCH*FC*HWP];      // gated output -> ln1 (in place) -> token transpose src
__device__ float g_xf [BATCH*SEQ*FC];
__device__ float g_qkv[BATCH*SEQ*3*FC];
__device__ float g_o  [BATCH*SEQ*FC];
__device__ float g_pr [BATCH*SEQ*2*FC];
__device__ float g_x2 [BATCH*FC*HWP];
__device__ float g_par[BATCH*COUT2*HWP];

// ---------------- helpers ----------------
__device__ __forceinline__ float warp_sum(float v){
    #pragma unroll
    for (int o=16;o;o>>=1) v += __shfl_xor_sync(0xffffffffu, v, o);
    return v;
}
__device__ __forceinline__ float sigf(float v){ return 1.0f/(1.0f+__expf(-v)); }
__device__ __forceinline__ float logsigf(float v){ return fminf(v,0.0f) - log1pf(__expf(-fabsf(v))); }

// ---------------- 1. checkerboard split ----------------
__global__ void split_kernel(const float* __restrict__ z){
    int idx = blockIdx.x*blockDim.x + threadIdx.x;
    if (idx >= BATCH*3*HWP) return;
    int j = idx & 31, i = (idx>>5) & 31;
    int c = (idx>>10) % 3;
    int b = idx / (3*HWP);
    const float* zb = z + ((long long)b*3 + c)*64*64;
    float p00 = zb[(2*i  )*64 + 2*j  ];
    float p01 = zb[(2*i  )*64 + 2*j+1];
    float p10 = zb[(2*i+1)*64 + 2*j  ];
    float p11 = zb[(2*i+1)*64 + 2*j+1];
    int base = ((b*C0C)+c)*HWP + i*32 + j;
    g_z0[base]          = p00;
    g_z0[base + 3*HWP]  = p11;
    g_z1[base]          = p01;
    g_z1[base + 3*HWP]  = p10;
}

// ---------------- 2. generic direct 3x3 conv ----------------
template<int CIN>
__global__ void conv3x3_kernel(const float* __restrict__ in, const float* __restrict__ w,
                               const float* __restrict__ bias, float* __restrict__ out, int Cout){
    __shared__ float tile[34*34];
    __shared__ float wsh[8][9];
    int b  = blockIdx.y;
    int co0= blockIdx.x*8;
    int tid= threadIdx.x;
    int y  = tid>>3;
    int x0 = (tid&7)*4;
    float acc[8][4];
    #pragma unroll
    for (int a=0;a<8;a++){ acc[a][0]=acc[a][1]=acc[a][2]=acc[a][3]=0.f; }
    const float* inb = in + (long long)b*CIN*HWP;
    for (int ci=0; ci<CIN; ci++){
        for (int idx=tid; idx<34*34; idx+=256){
            int ty=idx/34, tx=idx-ty*34;
            int yy=ty-1, xx=tx-1;
            tile[idx] = (yy>=0 && yy<32 && xx>=0 && xx<32) ? inb[ci*HWP + yy*32 + xx] : 0.f;
        }
        if (tid < 72){
            int co=tid/9, j=tid-co*9;
            wsh[co][j] = (co0+co < Cout) ? w[((long long)(co0+co)*CIN + ci)*9 + j] : 0.f;
        }
        __syncthreads();
        float v[3][6];
        #pragma unroll
        for (int r=0;r<3;r++)
            #pragma unroll
            for (int c=0;c<6;c++)
                v[r][c] = tile[(y+r)*34 + x0 + c];
        #pragma unroll
        for (int co=0;co<8;co++){
            #pragma unroll
            for (int p=0;p<4;p++){
                float s = acc[co][p];
                #pragma unroll
                for (int dy=0;dy<3;dy++)
                    #pragma unroll
                    for (int dx=0;dx<3;dx++)
                        s += v[dy][p+dx]*wsh[co][dy*3+dx];
                acc[co][p] = s;
            }
        }
        __syncthreads();
    }
    #pragma unroll
    for (int co=0;co<8;co++){
        if (co0+co < Cout){
            float bb = bias[co0+co];
            float4 r = make_float4(acc[co][0]+bb, acc[co][1]+bb, acc[co][2]+bb, acc[co][3]+bb);
            *(float4*)&out[((long long)b*Cout + co0+co)*HWP + y*32 + x0] = r;
        }
    }
}

// ---------------- 3. gconv (96->192) fused with gating ----------------
// reads g_x1 (conv1 out), writes g_xg = x1 + ga*sigmoid(gb). NO in-place write.
__global__ void gconv_gate_kernel(const float* __restrict__ w, const float* __restrict__ bias){
    __shared__ float tile[34*34];
    __shared__ float wsh[16][9];
    int b  = blockIdx.y;
    int co0= blockIdx.x*8;
    int tid= threadIdx.x;
    int y  = tid>>3;
    int x0 = (tid&7)*4;
    float acc[16][4];
    #pragma unroll
    for (int a=0;a<16;a++){ acc[a][0]=acc[a][1]=acc[a][2]=acc[a][3]=0.f; }
    const float* inb = g_x1 + (long long)b*FC*HWP;
    for (int ci=0; ci<FC; ci++){
        for (int idx=tid; idx<34*34; idx+=256){
            int ty=idx/34, tx=idx-ty*34;
            int yy=ty-1, xx=tx-1;
            tile[idx] = (yy>=0 && yy<32 && xx>=0 && xx<32) ? inb[ci*HWP + yy*32 + xx] : 0.f;
        }
        if (tid < 144){
            int co=tid/9, j=tid-co*9;
            int oc = (co<8) ? (co0+co) : (FC + co0 + co - 8);
            wsh[co][j] = w[((long long)oc*FC + ci)*9 + j];
        }
        __syncthreads();
        float v[3][6];
        #pragma unroll
        for (int r=0;r<3;r++)
            #pragma unroll
            for (int c=0;c<6;c++)
                v[r][c] = tile[(y+r)*34 + x0 + c];
        #pragma unroll
        for (int co=0;co<16;co++){
            #pragma unroll
            for (int p=0;p<4;p++){
                float s = acc[co][p];
                #pragma unroll
                for (int dy=0;dy<3;dy++)
                    #pragma unroll
                    for (int dx=0;dx<3;dx++)
                        s += v[dy][p+dx]*wsh[co][dy*3+dx];
                acc[co][p] = s;
            }
        }
        __syncthreads();
    }
    #pragma unroll
    for (int co=0;co<8;co++){
        float ba = bias[co0+co];
        float bg = bias[FC+co0+co];
        long long off = ((long long)b*FC + co0+co)*HWP + y*32 + x0;
        float4 xv = *(const float4*)&g_x1[off];
        float r[4];
        #pragma unroll
        for (int p=0;p<4;p++){
            float ga = acc[co][p]   + ba;
            float gb = acc[co+8][p] + bg;
            r[p] = ga * sigf(gb);
        }
        xv.x += r[0]; xv.y += r[1]; xv.z += r[2]; xv.w += r[3];
        *(float4*)&g_xg[off] = xv;
    }
}

// ---------------- 4. LayerNorm (full sample) ----------------
__global__ void layernorm_kernel(float* __restrict__ x, const float* __restrict__ gam,
                                 const float* __restrict__ bet){
    const int N = FC*HWP;
    int b = blockIdx.x;
    float* xb = x + (long long)b*N;
    float s=0.f, s2=0.f;
    for (int i=threadIdx.x;i<N;i+=blockDim.x){ float v=xb[i]; s+=v; s2+=v*v; }
    __shared__ float shs[32], shs2[32];
    int lane = threadIdx.x&31, wid = threadIdx.x>>5;
    s = warp_sum(s); s2 = warp_sum(s2);
    if (lane==0){ shs[wid]=s; shs2[wid]=s2; }
    __syncthreads();
    int nw = blockDim.x>>5;
    if (wid==0){
        float a = (lane<nw)? shs[lane]:0.f;
        float a2= (lane<nw)? shs2[lane]:0.f;
        a = warp_sum(a); a2 = warp_sum(a2);
        if (lane==0){ shs[0]=a; shs2[0]=a2; }
    }
    __syncthreads();
    float mean = shs[0]/(float)N;
    float var  = shs2[0]/(float)N - mean*mean;
    float inv  = rsqrtf(var + 1e-5f);
    for (int i=threadIdx.x;i<N;i+=blockDim.x)
        xb[i] = (xb[i]-mean)*inv*gam[i] + bet[i];
}

// ---------------- 5. transposes ----------------
__global__ void to_tokenmajor_kernel(){
    int idx = blockIdx.x*blockDim.x + threadIdx.x;
    if (idx >= BATCH*SEQ*FC) return;
    int f = idx % FC;
    int t = (idx/FC) % SEQ;
    int b = idx/(SEQ*FC);
    g_xf[idx] = g_xg[((long long)b*FC + f)*HWP + t];
}
__global__ void to_chanmajor_kernel(){
    int idx = blockIdx.x*blockDim.x + threadIdx.x;
    if (idx >= BATCH*FC*HWP) return;
    int t = idx % HWP;
    int f = (idx/HWP) % FC;
    int b = idx/(FC*HWP);
    g_x2[idx] = g_xf[((long long)b*SEQ + t)*FC + f];
}

// ---------------- 6. batched SGEMM (qkv / proj) ----------------
template<bool TB>
__global__ void gemm_kernel(const float* __restrict__ A, const float* __restrict__ Bm,
                            float* __restrict__ C,
                            int M, int N, int K, int lda, int ldb, int ldc,
                            long long sA, long long sB, long long sC,
                            const float* __restrict__ bias, float alpha){
    __shared__ float As[16][64];
    __shared__ float Bs[16][64];
    A += blockIdx.z * sA;
    Bm+= blockIdx.z * sB;
    C += blockIdx.z * sC;
    int n0 = blockIdx.x*64;
    int m0 = blockIdx.y*64;
    int tid = threadIdx.x;
    int tx = tid & 15, ty = tid >> 4;
    float acc[4][4];
    #pragma unroll
    for (int i=0;i<4;i++){ acc[i][0]=acc[i][1]=acc[i][2]=acc[i][3]=0.f; }
    int ra = tid>>2;
    int ca = (tid&3)*4;
    int rb = tid>>4;
    int cb = (tid&15)*4;
    for (int k0=0; k0<K; k0+=16){
        #pragma unroll
        for (int j=0;j<4;j++)
            As[ca+j][ra] = A[(long long)(m0+ra)*lda + (k0+ca+j)];
        if (TB){
            int n = n0 + ra;
            #pragma unroll
            for (int j=0;j<4;j++)
                Bs[ca+j][ra] = (n<N) ? Bm[(long long)n*ldb + (k0+ca+j)] : 0.f;
        } else {
            #pragma unroll
            for (int j=0;j<4;j++){
                int n = n0 + cb + j;
                Bs[rb][cb+j] = (n<N) ? Bm[(long long)(k0+rb)*ldb + n] : 0.f;
            }
        }
        __syncthreads();
        #pragma unroll
        for (int kk=0;kk<16;kk++){
            float4 av = *(const float4*)&As[kk][ty*4];
            float4 bv = *(const float4*)&Bs[kk][tx*4];
            float a[4] = {av.x,av.y,av.z,av.w};
            float bb[4]= {bv.x,bv.y,bv.z,bv.w};
            #pragma unroll
            for (int i=0;i<4;i++)
                #pragma unroll
                for (int j=0;j<4;j++)
                    acc[i][j] += a[i]*bb[j];
        }
        __syncthreads();
    }
    #pragma unroll
    for (int i=0;i<4;i++){
        int m = m0 + ty*4 + i;
        #pragma unroll
        for (int j=0;j<4;j++){
            int n = n0 + tx*4 + j;
            if (n < N){
                float v = alpha*acc[i][j];
                if (bias) v += bias[n];
                C[(long long)m*ldc + n] = v;
            }
        }
    }
}

// ---------------- 7. flash attention (fp32, online softmax) ----------------
__global__ void flash_kernel(){
    extern __shared__ float sm[];
    float* Qs = sm;                          // [96][QS_LD]
    float* Ks = Qs + 96*QS_LD;               // [96][KS_LD]
    float* Vs = Ks + 96*KS_LD;               // [64][VS_LD]
    float* Ps = Vs + 64*VS_LD;               // [128][PS_LD]

    int b   = blockIdx.y;
    int t0  = blockIdx.x*QT;
    int tid = threadIdx.x;
    int ty  = tid>>4, tx = tid&15;
    int mrow= ty*8;
    const float scale = rsqrtf((float)FC);

    const float* qkvb = g_qkv + (long long)b*SEQ*3*FC;

    for (int idx=tid; idx<QT*FC; idx+=256){
        int m = idx/FC, k = idx - m*FC;
        Qs[k*QS_LD + m] = qkvb[(long long)(t0+m)*3*FC + k] * scale;
    }

    float O[8][6];
    float mold[8], l[8];
    #pragma unroll
    for (int i=0;i<8;i++){
        mold[i] = -1e30f; l[i] = 0.f;
        #pragma unroll
        for (int c=0;c<6;c++) O[i][c] = 0.f;
    }
    __syncthreads();

    for (int it=0; it<16; it++){
        int kv0 = it*64;
        for (int idx=tid; idx<64*FC; idx+=256){
            int n = idx/FC, k = idx - n*FC;
            Ks[k*KS_LD + n] = qkvb[(long long)(kv0+n)*3*FC + FC + k];
        }
        for (int idx=tid; idx<64*FC; idx+=256){
            int n = idx/FC, f = idx - n*FC;
            Vs[n*VS_LD + f] = qkvb[(long long)(kv0+n)*3*FC + 2*FC + f];
        }
        __syncthreads();

        float accS[8][4];
        #pragma unroll
        for (int i=0;i<8;i++){ accS[i][0]=accS[i][1]=accS[i][2]=accS[i][3]=0.f; }
        #pragma unroll 4
        for (int kk=0;kk<FC;kk++){
            float4 a0 = *(const float4*)&Qs[kk*QS_LD + mrow];
            float4 a1 = *(const float4*)&Qs[kk*QS_LD + mrow + 4];
            float4 bv = *(const float4*)&Ks[kk*KS_LD + tx*4];
            float a[8] = {a0.x,a0.y,a0.z,a0.w,a1.x,a1.y,a1.z,a1.w};
            float bb[4] = {bv.x,bv.y,bv.z,bv.w};
            #pragma unroll
            for (int i=0;i<8;i++)
                #pragma unroll
                for (int j=0;j<4;j++)
                    accS[i][j] += a[i]*bb[j];
        }

        #pragma unroll
        for (int i=0;i<8;i++){
            float mloc = fmaxf(fmaxf(accS[i][0],accS[i][1]), fmaxf(accS[i][2],accS[i][3]));
            #pragma unroll
            for (int o=1;o<16;o<<=1) mloc = fmaxf(mloc, __shfl_xor_sync(0xffffffffu, mloc, o));
            float mnew = fmaxf(mold[i], mloc);
            float alpha = __expf(mold[i]-mnew);
            float s = 0.f;
            #pragma unroll
            for (int j=0;j<4;j++){
                float p = __expf(accS[i][j]-mnew);
                accS[i][j] = p; s += p;
            }
            #pragma unroll
            for (int o=1;o<16;o<<=1) s += __shfl_xor_sync(0xffffffffu, s, o);
            l[i] = l[i]*alpha + s;
            mold[i] = mnew;
            #pragma unroll
            for (int c=0;c<6;c++) O[i][c] *= alpha;
            *(float4*)&Ps[(mrow+i)*PS_LD + tx*4] = make_float4(accS[i][0],accS[i][1],accS[i][2],accS[i][3]);
        }
        __syncthreads();

        #pragma unroll 2
        for (int n=0;n<64;n++){
            float vv[6];
            #pragma unroll
            for (int c=0;c<6;c++) vv[c] = Vs[n*VS_LD + tx + 16*c];
            #pragma unroll
            for (int i=0;i<8;i++){
                float p = Ps[(mrow+i)*PS_LD + n];
                #pragma unroll
                for (int c=0;c<6;c++) O[i][c] += p*vv[c];
            }
        }
        __syncthreads();
    }

    float* ob = g_o + ((long long)b*SEQ + t0)*FC;
    #pragma unroll
    for (int i=0;i<8;i++){
        float inv = 1.0f/l[i];
        #pragma unroll
        for (int c=0;c<6;c++)
            ob[(long long)(mrow+i)*FC + tx + 16*c] = O[i][c]*inv;
    }
}

// ---------------- 8. attention gating (residual) ----------------
__global__ void gate_attn_kernel(){
    int idx = blockIdx.x*blockDim.x + threadIdx.x;
    if (idx >= BATCH*SEQ*FC) return;
    int f = idx % FC;
    int t = (idx/FC) % SEQ;
    int b = idx/(SEQ*FC);
    long long pr = ((long long)b*SEQ + t)*2*FC;
    float ga = g_pr[pr + f];
    float gb = g_pr[pr + FC + f];
    g_xf[idx] += ga * sigf(gb);
}

// ---------------- 9. logdet init ----------------
__global__ void init_log_kernel(const float* __restrict__ ldf, float* __restrict__ out_log){
    int b = threadIdx.x;
    if (b < BATCH) out_log[b] = ldf[b];
}

// ---------------- 10. mixture + logit + affine + merge ----------------
__global__ void mixture_kernel(const float* __restrict__ als, const float* __restrict__ ab,
                               float* __restrict__ out_z, float* __restrict__ out_log){
    int b  = blockIdx.x;
    int c0 = blockIdx.y;
    int p  = threadIdx.x;
    const float* P = g_par + (long long)b*COUT2*HWP;

    float aRaw = P[(long long)c0*HWP + p];
    float bRaw = P[(long long)(6+c0)*HWP + p];
    float lp[KMIX], mu[KMIX], ss[KMIX];
    #pragma unroll
    for (int k=0;k<KMIX;k++){
        lp[k] = P[(long long)(12 + k*C0C + c0)*HWP + p];
        mu[k] = P[(long long)(60 + k*C0C + c0)*HWP + p];
        ss[k] = P[(long long)(108+ k*C0C + c0)*HWP + p];
    }
    float a = tanhf(aRaw)*als[0] + ab[0];

    float mx = lp[0];
    #pragma unroll
    for (int k=1;k<KMIX;k++) mx = fmaxf(mx, lp[k]);
    float se = 0.f;
    #pragma unroll
    for (int k=0;k<KMIX;k++) se += __expf(lp[k]-mx);
    float lse = mx + __logf(se);

    float z0v = g_z0[((long long)b*C0C + c0)*HWP + p];
    float tvals[KMIX];
    float xsum = 0.f;
    #pragma unroll
    for (int k=0;k<KMIX;k++){
        float lpn = lp[k] - lse;
        float u   = (z0v - mu[k]) * __expf(-ss[k]);
        xsum += __expf(lpn) * sigf(u);
        tvals[k] = lpn - ss[k] + logsigf(u) + logsigf(-u);
    }
    float tm = tvals[0];
    #pragma unroll
    for (int k=1;k<KMIX;k++) tm = fmaxf(tm, tvals[k]);
    float tse = 0.f;
    #pragma unroll
    for (int k=0;k<KMIX;k++) tse += __expf(tvals[k]-tm);
    float logpdf = tm + __logf(tse);

    float x = fminf(fmaxf(xsum, 1e-6f), 1.0f-1e-6f);
    float lx  = __logf(x);
    float l1x = log1pf(-x);
    float z0n = (lx - l1x) * __expf(a) + bRaw;
    float contrib = logpdf + (-lx - l1x) + a;

    int i = p>>5, j = p&31;
    float z1v = g_z1[((long long)b*C0C + c0)*HWP + p];
    if (c0 < 3){
        float* ob = out_z + ((long long)b*3 + c0)*64*64;
        ob[(2*i)*64 + 2*j    ] = z0n;
        ob[(2*i)*64 + 2*j + 1] = z1v;
    } else {
        float* ob = out_z + ((long long)b*3 + (c0-3))*64*64;
        ob[(2*i+1)*64 + 2*j + 1] = z0n;
        ob[(2*i+1)*64 + 2*j    ] = z1v;
    }

    __shared__ float sh[32];
    int lane = p&31, wid = p>>5;
    float v = warp_sum(contrib);
    if (lane==0) sh[wid]=v;
    __syncthreads();
    if (wid==0){
        float w = (lane<32)? sh[lane] : 0.f;
        w = warp_sum(w);
        if (lane==0) atomicAdd(&out_log[b], w);
    }
}

// ---------------- host launcher ----------------
extern "C" void kernel_launch(void* const* d_in, const int* in_sizes, int n_in,
                              void* d_out, int out_size){
    const float* z        = (const float*)d_in[0];
    const float* log_df   = (const float*)d_in[1];
    const float* conv1_w  = (const float*)d_in[2];
    const float* conv1_b  = (const float*)d_in[3];
    const float* gconv_w  = (const float*)d_in[4];
    const float* gconv_b  = (const float*)d_in[5];
    const float* ln1_g    = (const float*)d_in[6];
    const float* ln1_b    = (const float*)d_in[7];
    const float* qkv_w    = (const float*)d_in[8];
    const float* qkv_b    = (const float*)d_in[9];
    const float* proj_w   = (const float*)d_in[10];
    const float* proj_b   = (const float*)d_in[11];
    const float* ln2_g    = (const float*)d_in[12];
    const float* ln2_b    = (const float*)d_in[13];
    const float* conv2_w  = (const float*)d_in[14];
    const float* conv2_b  = (const float*)d_in[15];
    const float* a_ls     = (const float*)d_in[16];
    const float* a_bias   = (const float*)d_in[17];

    float* out_z   = (float*)d_out;
    float* out_log = (float*)d_out + (long long)BATCH*3*64*64;

    float *p_z1, *p_x1, *p_xg, *p_xf, *p_qkv, *p_o, *p_pr, *p_x2, *p_par;
    cudaGetSymbolAddress((void**)&p_z1,  g_z1);
    cudaGetSymbolAddress((void**)&p_x1,  g_x1);
    cudaGetSymbolAddress((void**)&p_xg,  g_xg);
    cudaGetSymbolAddress((void**)&p_xf,  g_xf);
    cudaGetSymbolAddress((void**)&p_qkv, g_qkv);
    cudaGetSymbolAddress((void**)&p_o,   g_o);
    cudaGetSymbolAddress((void**)&p_pr,  g_pr);
    cudaGetSymbolAddress((void**)&p_x2,  g_x2);
    cudaGetSymbolAddress((void**)&p_par, g_par);

    static int smem_set = 0;
    const int FLASH_SMEM = (96*QS_LD + 96*KS_LD + 64*VS_LD + 128*PS_LD)*4;
    if (!smem_set){
        cudaFuncSetAttribute(flash_kernel, cudaFuncAttributeMaxDynamicSharedMemorySize, FLASH_SMEM);
        smem_set = 1;
    }

    split_kernel<<<(BATCH*3*HWP+255)/256, 256>>>(z);
    conv3x3_kernel<6><<<dim3(12, BATCH), 256>>>(p_z1, conv1_w, conv1_b, p_x1, FC);
    gconv_gate_kernel<<<dim3(12, BATCH), 256>>>(gconv_w, gconv_b);
    layernorm_kernel<<<BATCH, 1024>>>(p_xg, ln1_g, ln1_b);
    to_tokenmajor_kernel<<<(BATCH*SEQ*FC+255)/256, 256>>>();
    gemm_kernel<true><<<dim3(5,16,BATCH), 256>>>(p_xf, qkv_w, p_qkv,
        SEQ, 3*FC, FC, FC, FC, 3*FC,
        (long long)SEQ*FC, 0LL, (long long)SEQ*3*FC, qkv_b, 1.0f);
    flash_kernel<<<dim3(8, BATCH), 256, FLASH_SMEM>>>();
    gemm_kernel<true><<<dim3(3,16,BATCH), 256>>>(p_o, proj_w, p_pr,
        SEQ, 2*FC, FC, FC, FC, 2*FC,
        (long long)SEQ*FC, 0LL, (long long)SEQ*2*FC, proj_b, 1.0f);
    gate_attn_kernel<<<(BATCH*SEQ*FC+255)/256, 256>>>();
    to_chanmajor_kernel<<<(BATCH*FC*HWP+255)/256, 256>>>();
    layernorm_kernel<<<BATCH, 1024>>>(p_x2, ln2_g, ln2_b);
    conv3x3_kernel<96><<<dim3(20, BATCH), 256>>>(p_x2, conv2_w, conv2_b, p_par, COUT2);
    init_log_kernel<<<1, 64>>>(log_df, out_log);
    mixture_kernel<<<dim3(BATCH, C0C), 1024>>>(a_ls, a_bias, out_z, out_log);
}

// round 5
// speedup vs baseline: 1.3865x; 1.0970x over previous
#include <cuda_runtime.h>
#include <math.h>
#include <stdint.h>

// ---------------- problem constants ----------------
#define BATCH 64
#define C0C   6
#define FC    96
#define KMIX  8
#define HWP   1024
#define SEQ   1024
#define COUT2 156

// ---------------- scratch ----------------
__device__ float g_z0 [BATCH*C0C*HWP];
__device__ float g_z1 [BATCH*C0C*HWP];
__device__ float g_x1 [BATCH*FC*HWP];
__device__ float g_xg [BATCH*FC*HWP];
__device__ float g_xf [BATCH*SEQ*FC];
__device__ float g_qkv[BATCH*SEQ*3*FC];
__device__ float g_o  [BATCH*SEQ*FC];
__device__ float g_pr [BATCH*SEQ*2*FC];
__device__ float g_x2 [BATCH*FC*HWP];
__device__ float g_par[BATCH*COUT2*HWP];
__device__ float g_st1[BATCH*2];
__device__ float g_st2[BATCH*2];

// ---------------- helpers ----------------
__device__ __forceinline__ float warp_sum(float v){
    #pragma unroll
    for (int o=16;o;o>>=1) v += __shfl_xor_sync(0xffffffffu, v, o);
    return v;
}
__device__ __forceinline__ float sigf(float v){ return 1.0f/(1.0f+__expf(-v)); }
__device__ __forceinline__ float logsigf(float v){ return fminf(v,0.0f) - log1pf(__expf(-fabsf(v))); }
__device__ __forceinline__ float cvt_tf32(float x){
    uint32_t r; asm("cvt.rna.tf32.f32 %0, %1;" : "=r"(r) : "f"(x)); return __uint_as_float(r);
}
__device__ __forceinline__ void mma_tf32(float* c, float a0,float a1,float a2,float a3,
                                         float b0,float b1){
    asm volatile("mma.sync.aligned.m16n8k8.row.col.f32.tf32.tf32.f32 "
        "{%0,%1,%2,%3}, {%4,%5,%6,%7}, {%8,%9}, {%0,%1,%2,%3};\n"
        : "+f"(c[0]),"+f"(c[1]),"+f"(c[2]),"+f"(c[3])
        : "r"(__float_as_uint(a0)),"r"(__float_as_uint(a1)),
          "r"(__float_as_uint(a2)),"r"(__float_as_uint(a3)),
          "r"(__float_as_uint(b0)),"r"(__float_as_uint(b1)));
}

// ---------------- 1. checkerboard split ----------------
__global__ void split_kernel(const float* __restrict__ z){
    int idx = blockIdx.x*blockDim.x + threadIdx.x;
    if (idx >= BATCH*3*HWP) return;
    int j = idx & 31, i = (idx>>5) & 31;
    int c = (idx>>10) % 3;
    int b = idx / (3*HWP);
    const float* zb = z + ((long long)b*3 + c)*64*64;
    float p00 = zb[(2*i  )*64 + 2*j  ];
    float p01 = zb[(2*i  )*64 + 2*j+1];
    float p10 = zb[(2*i+1)*64 + 2*j  ];
    float p11 = zb[(2*i+1)*64 + 2*j+1];
    int base = ((b*C0C)+c)*HWP + i*32 + j;
    g_z0[base]          = p00;
    g_z0[base + 3*HWP]  = p11;
    g_z1[base]          = p01;
    g_z1[base + 3*HWP]  = p10;
}

// ---------------- 2. generic direct 3x3 conv (conv1) ----------------
template<int CIN>
__global__ void conv3x3_kernel(const float* __restrict__ in, const float* __restrict__ w,
                               const float* __restrict__ bias, float* __restrict__ out, int Cout){
    __shared__ float tile[34*34];
    __shared__ float wsh[8][9];
    int b  = blockIdx.y;
    int co0= blockIdx.x*8;
    int tid= threadIdx.x;
    int y  = tid>>3;
    int x0 = (tid&7)*4;
    float acc[8][4];
    #pragma unroll
    for (int a=0;a<8;a++){ acc[a][0]=acc[a][1]=acc[a][2]=acc[a][3]=0.f; }
    const float* inb = in + (long long)b*CIN*HWP;
    for (int ci=0; ci<CIN; ci++){
        for (int idx=tid; idx<34*34; idx+=256){
            int ty=idx/34, tx=idx-ty*34;
            int yy=ty-1, xx=tx-1;
            tile[idx] = (yy>=0 && yy<32 && xx>=0 && xx<32) ? inb[ci*HWP + yy*32 + xx] : 0.f;
        }
        if (tid < 72){
            int co=tid/9, j=tid-co*9;
            wsh[co][j] = (co0+co < Cout) ? w[((long long)(co0+co)*CIN + ci)*9 + j] : 0.f;
        }
        __syncthreads();
        float v[3][6];
        #pragma unroll
        for (int r=0;r<3;r++)
            #pragma unroll
            for (int c=0;c<6;c++)
                v[r][c] = tile[(y+r)*34 + x0 + c];
        #pragma unroll
        for (int co=0;co<8;co++){
            #pragma unroll
            for (int p=0;p<4;p++){
                float s = acc[co][p];
                #pragma unroll
                for (int dy=0;dy<3;dy++)
                    #pragma unroll
                    for (int dx=0;dx<3;dx++)
                        s += v[dy][p+dx]*wsh[co][dy*3+dx];
                acc[co][p] = s;
            }
        }
        __syncthreads();
    }
    #pragma unroll
    for (int co=0;co<8;co++){
        if (co0+co < Cout){
            float bb = bias[co0+co];
            float4 r = make_float4(acc[co][0]+bb, acc[co][1]+bb, acc[co][2]+bb, acc[co][3]+bb);
            *(float4*)&out[((long long)b*Cout + co0+co)*HWP + y*32 + x0] = r;
        }
    }
}

// ---------------- 3. gconv (96->192) fused with gating -> g_xg ----------------
__global__ void gconv_gate_kernel(const float* __restrict__ w, const float* __restrict__ bias){
    __shared__ float tile[34*34];
    __shared__ float wsh[16][9];
    int b  = blockIdx.y;
    int co0= blockIdx.x*8;
    int tid= threadIdx.x;
    int y  = tid>>3;
    int x0 = (tid&7)*4;
    float acc[16][4];
    #pragma unroll
    for (int a=0;a<16;a++){ acc[a][0]=acc[a][1]=acc[a][2]=acc[a][3]=0.f; }
    const float* inb = g_x1 + (long long)b*FC*HWP;
    for (int ci=0; ci<FC; ci++){
        for (int idx=tid; idx<34*34; idx+=256){
            int ty=idx/34, tx=idx-ty*34;
            int yy=ty-1, xx=tx-1;
            tile[idx] = (yy>=0 && yy<32 && xx>=0 && xx<32) ? inb[ci*HWP + yy*32 + xx] : 0.f;
        }
        if (tid < 144){
            int co=tid/9, j=tid-co*9;
            int oc = (co<8) ? (co0+co) : (FC + co0 + co - 8);
            wsh[co][j] = w[((long long)oc*FC + ci)*9 + j];
        }
        __syncthreads();
        float v[3][6];
        #pragma unroll
        for (int r=0;r<3;r++)
            #pragma unroll
            for (int c=0;c<6;c++)
                v[r][c] = tile[(y+r)*34 + x0 + c];
        #pragma unroll
        for (int co=0;co<16;co++){
            #pragma unroll
            for (int p=0;p<4;p++){
                float s = acc[co][p];
                #pragma unroll
                for (int dy=0;dy<3;dy++)
                    #pragma unroll
                    for (int dx=0;dx<3;dx++)
                        s += v[dy][p+dx]*wsh[co][dy*3+dx];
                acc[co][p] = s;
            }
        }
        __syncthreads();
    }
    #pragma unroll
    for (int co=0;co<8;co++){
        float ba = bias[co0+co];
        float bg = bias[FC+co0+co];
        long long off = ((long long)b*FC + co0+co)*HWP + y*32 + x0;
        float4 xv = *(const float4*)&g_x1[off];
        float r[4];
        #pragma unroll
        for (int p=0;p<4;p++){
            float ga = acc[co][p]   + ba;
            float gb = acc[co+8][p] + bg;
            r[p] = ga * sigf(gb);
        }
        xv.x += r[0]; xv.y += r[1]; xv.z += r[2]; xv.w += r[3];
        *(float4*)&g_xg[off] = xv;
    }
}

// ---------------- 4. LN stats only ----------------
__global__ void ln_stats_kernel(const float* __restrict__ x, float* __restrict__ st){
    const int N = FC*HWP;
    int b = blockIdx.x;
    const float4* xb = (const float4*)(x + (long long)b*N);
    float s=0.f, s2=0.f;
    for (int i=threadIdx.x;i<N/4;i+=blockDim.x){
        float4 v = xb[i];
        s  += v.x+v.y+v.z+v.w;
        s2 += v.x*v.x+v.y*v.y+v.z*v.z+v.w*v.w;
    }
    __shared__ float shs[32], shs2[32];
    int lane = threadIdx.x&31, wid = threadIdx.x>>5;
    s = warp_sum(s); s2 = warp_sum(s2);
    if (lane==0){ shs[wid]=s; shs2[wid]=s2; }
    __syncthreads();
    int nw = blockDim.x>>5;
    if (wid==0){
        float a = (lane<nw)? shs[lane]:0.f;
        float a2= (lane<nw)? shs2[lane]:0.f;
        a = warp_sum(a); a2 = warp_sum(a2);
        if (lane==0){
            float mean = a/(float)N;
            float var  = a2/(float)N - mean*mean;
            st[2*b]   = mean;
            st[2*b+1] = rsqrtf(var + 1e-5f);
        }
    }
}

// ---------------- 5a. ln1 apply + transpose to token-major ----------------
// grid (32, 3, B), block 256 (32x8)
__global__ void ln1_transpose_kernel(const float* __restrict__ gam, const float* __restrict__ bet){
    __shared__ float t[32][33];
    int b  = blockIdx.z;
    int f0 = blockIdx.y*32;
    int p0 = blockIdx.x*32;
    float mean = g_st1[2*b], inv = g_st1[2*b+1];
    int tx = threadIdx.x&31, ty = threadIdx.x>>5;
    #pragma unroll
    for (int k=0;k<4;k++){
        int f = f0 + ty + 8*k;
        int col = p0 + tx;
        float v = g_xg[((long long)b*FC + f)*HWP + col];
        t[ty+8*k][tx] = (v-mean)*inv*gam[f*HWP + col] + bet[f*HWP + col];
    }
    __syncthreads();
    #pragma unroll
    for (int k=0;k<4;k++){
        int p = p0 + ty + 8*k;
        g_xf[((long long)b*SEQ + p)*FC + f0 + tx] = t[tx][ty+8*k];
    }
}

// ---------------- 5b. attn gate + transpose to channel-major ----------------
__global__ void gate_transpose_kernel(){
    __shared__ float t[32][33];
    int b  = blockIdx.z;
    int f0 = blockIdx.y*32;
    int p0 = blockIdx.x*32;
    int tx = threadIdx.x&31, ty = threadIdx.x>>5;
    #pragma unroll
    for (int k=0;k<4;k++){
        int p = p0 + ty + 8*k;
        long long base = ((long long)b*SEQ + p);
        float xv = g_xf[base*FC + f0 + tx];
        float ga = g_pr[base*2*FC + f0 + tx];
        float gb = g_pr[base*2*FC + FC + f0 + tx];
        t[ty+8*k][tx] = xv + ga*sigf(gb);
    }
    __syncthreads();
    #pragma unroll
    for (int k=0;k<4;k++){
        int f = f0 + ty + 8*k;
        g_x2[((long long)b*FC + f)*HWP + p0 + tx] = t[tx][ty+8*k];
    }
}

// ---------------- 6. batched SGEMM (qkv / proj) ----------------
template<bool TB>
__global__ void gemm_kernel(const float* __restrict__ A, const float* __restrict__ Bm,
                            float* __restrict__ C,
                            int M, int N, int K, int lda, int ldb, int ldc,
                            long long sA, long long sB, long long sC,
                            const float* __restrict__ bias, float alpha){
    __shared__ float As[16][64];
    __shared__ float Bs[16][64];
    A += blockIdx.z * sA;
    Bm+= blockIdx.z * sB;
    C += blockIdx.z * sC;
    int n0 = blockIdx.x*64;
    int m0 = blockIdx.y*64;
    int tid = threadIdx.x;
    int tx = tid & 15, ty = tid >> 4;
    float acc[4][4];
    #pragma unroll
    for (int i=0;i<4;i++){ acc[i][0]=acc[i][1]=acc[i][2]=acc[i][3]=0.f; }
    int ra = tid>>2;
    int ca = (tid&3)*4;
    int rb = tid>>4;
    int cb = (tid&15)*4;
    for (int k0=0; k0<K; k0+=16){
        #pragma unroll
        for (int j=0;j<4;j++)
            As[ca+j][ra] = A[(long long)(m0+ra)*lda + (k0+ca+j)];
        if (TB){
            int n = n0 + ra;
            #pragma unroll
            for (int j=0;j<4;j++)
                Bs[ca+j][ra] = (n<N) ? Bm[(long long)n*ldb + (k0+ca+j)] : 0.f;
        } else {
            #pragma unroll
            for (int j=0;j<4;j++){
                int n = n0 + cb + j;
                Bs[rb][cb+j] = (n<N) ? Bm[(long long)(k0+rb)*ldb + n] : 0.f;
            }
        }
        __syncthreads();
        #pragma unroll
        for (int kk=0;kk<16;kk++){
            float4 av = *(const float4*)&As[kk][ty*4];
            float4 bv = *(const float4*)&Bs[kk][tx*4];
            float a[4] = {av.x,av.y,av.z,av.w};
            float bb[4]= {bv.x,bv.y,bv.z,bv.w};
            #pragma unroll
            for (int i=0;i<4;i++)
                #pragma unroll
                for (int j=0;j<4;j++)
                    acc[i][j] += a[i]*bb[j];
        }
        __syncthreads();
    }
    #pragma unroll
    for (int i=0;i<4;i++){
        int m = m0 + ty*4 + i;
        #pragma unroll
        for (int j=0;j<4;j++){
            int n = n0 + tx*4 + j;
            if (n < N){
                float v = alpha*acc[i][j];
                if (bias) v += bias[n];
                C[(long long)m*ldc + n] = v;
            }
        }
    }
}

// ---------------- 7. flash attention, tf32 mma ----------------
// block 128 thr (4 warps), Q tile 64 rows, warp w: rows 16w..16w+15. KV tiles of 64.
#define QLD 100
#define KLD 100
#define VLD 104
#define PLD 68
__global__ void flash_tf32_kernel(){
    extern __shared__ float sm[];
    float* Qs = sm;                 // [64][QLD]
    float* Ks = Qs + 64*QLD;        // [64][KLD]
    float* Vs = Ks + 64*KLD;        // [64][VLD]  V[k][n]
    float* Ps = Vs + 64*VLD;        // [64][PLD]

    int b   = blockIdx.y;
    int t0  = blockIdx.x*64;
    int tid = threadIdx.x;
    int w   = tid>>5, lane = tid&31;
    int gid = lane>>2, tig = lane&3;
    const float scale = rsqrtf((float)FC);
    const float* qkvb = g_qkv + (long long)b*SEQ*3*FC;

    for (int i=tid;i<64*FC;i+=128){
        int m=i/FC, k=i-m*FC;
        Qs[m*QLD+k] = cvt_tf32(qkvb[(long long)(t0+m)*3*FC + k]*scale);
    }

    float O[12][4];
    #pragma unroll
    for (int j=0;j<12;j++){ O[j][0]=O[j][1]=O[j][2]=O[j][3]=0.f; }
    float mA=-1e30f, mB=-1e30f, lA=0.f, lB=0.f;
    __syncthreads();

    for (int it=0; it<16; it++){
        int kv0 = it*64;
        for (int i=tid;i<64*FC;i+=128){
            int n=i/FC, k=i-n*FC;
            Ks[n*KLD+k] = cvt_tf32(qkvb[(long long)(kv0+n)*3*FC + FC + k]);
        }
        for (int i=tid;i<64*FC;i+=128){
            int k=i/FC, n=i-k*FC;
            Vs[k*VLD+n] = cvt_tf32(qkvb[(long long)(kv0+k)*3*FC + 2*FC + n]);
        }
        __syncthreads();

        // S = Q K^T : per warp 16x64 in 8 n-tiles
        float c[8][4];
        #pragma unroll
        for (int j=0;j<8;j++){ c[j][0]=c[j][1]=c[j][2]=c[j][3]=0.f; }
        #pragma unroll
        for (int kk=0;kk<12;kk++){
            int k0=kk*8;
            float a0 = Qs[(16*w+gid  )*QLD + k0+tig];
            float a1 = Qs[(16*w+gid+8)*QLD + k0+tig];
            float a2 = Qs[(16*w+gid  )*QLD + k0+tig+4];
            float a3 = Qs[(16*w+gid+8)*QLD + k0+tig+4];
            #pragma unroll
            for (int j=0;j<8;j++){
                float b0 = Ks[(j*8+gid)*KLD + k0+tig];
                float b1 = Ks[(j*8+gid)*KLD + k0+tig+4];
                mma_tf32(c[j], a0,a1,a2,a3, b0,b1);
            }
        }

        // online softmax (rows gid and gid+8 of this warp's 16)
        float mlA=-1e30f, mlB=-1e30f;
        #pragma unroll
        for (int j=0;j<8;j++){
            mlA = fmaxf(mlA, fmaxf(c[j][0],c[j][1]));
            mlB = fmaxf(mlB, fmaxf(c[j][2],c[j][3]));
        }
        mlA = fmaxf(mlA, __shfl_xor_sync(0xffffffffu, mlA, 1));
        mlA = fmaxf(mlA, __shfl_xor_sync(0xffffffffu, mlA, 2));
        mlB = fmaxf(mlB, __shfl_xor_sync(0xffffffffu, mlB, 1));
        mlB = fmaxf(mlB, __shfl_xor_sync(0xffffffffu, mlB, 2));
        float mnA = fmaxf(mA, mlA), mnB = fmaxf(mB, mlB);
        float alA = __expf(mA-mnA), alB = __expf(mB-mnB);
        float sA=0.f, sB=0.f;
        #pragma unroll
        for (int j=0;j<8;j++){
            c[j][0] = __expf(c[j][0]-mnA); sA += c[j][0];
            c[j][1] = __expf(c[j][1]-mnA); sA += c[j][1];
            c[j][2] = __expf(c[j][2]-mnB); sB += c[j][2];
            c[j][3] = __expf(c[j][3]-mnB); sB += c[j][3];
        }
        sA += __shfl_xor_sync(0xffffffffu, sA, 1);
        sA += __shfl_xor_sync(0xffffffffu, sA, 2);
        sB += __shfl_xor_sync(0xffffffffu, sB, 1);
        sB += __shfl_xor_sync(0xffffffffu, sB, 2);
        lA = lA*alA + sA; mA = mnA;
        lB = lB*alB + sB; mB = mnB;
        #pragma unroll
        for (int j=0;j<12;j++){
            O[j][0]*=alA; O[j][1]*=alA; O[j][2]*=alB; O[j][3]*=alB;
        }
        // store P (tf32-rounded)
        #pragma unroll
        for (int j=0;j<8;j++){
            int colp = j*8 + 2*tig;
            float2 v0 = make_float2(cvt_tf32(c[j][0]), cvt_tf32(c[j][1]));
            float2 v1 = make_float2(cvt_tf32(c[j][2]), cvt_tf32(c[j][3]));
            *(float2*)&Ps[(16*w+gid  )*PLD + colp] = v0;
            *(float2*)&Ps[(16*w+gid+8)*PLD + colp] = v1;
        }
        __syncwarp();

        // O += P V
        #pragma unroll
        for (int kk=0;kk<8;kk++){
            int k0=kk*8;
            float a0 = Ps[(16*w+gid  )*PLD + k0+tig];
            float a1 = Ps[(16*w+gid+8)*PLD + k0+tig];
            float a2 = Ps[(16*w+gid  )*PLD + k0+tig+4];
            float a3 = Ps[(16*w+gid+8)*PLD + k0+tig+4];
            #pragma unroll
            for (int j=0;j<12;j++){
                float b0 = Vs[(k0+tig  )*VLD + j*8+gid];
                float b1 = Vs[(k0+tig+4)*VLD + j*8+gid];
                mma_tf32(O[j], a0,a1,a2,a3, b0,b1);
            }
        }
        __syncthreads();
    }

    float iA = 1.0f/lA, iB = 1.0f/lB;
    float* ob = g_o + ((long long)b*SEQ + t0)*FC;
    #pragma unroll
    for (int j=0;j<12;j++){
        int n = j*8 + 2*tig;
        *(float2*)&ob[(long long)(16*w+gid  )*FC + n] = make_float2(O[j][0]*iA, O[j][1]*iA);
        *(float2*)&ob[(long long)(16*w+gid+8)*FC + n] = make_float2(O[j][2]*iB, O[j][3]*iB);
    }
}

// ---------------- 8. conv2 with fused ln2 on input ----------------
__global__ void conv2_ln_kernel(const float* __restrict__ w, const float* __restrict__ bias,
                                const float* __restrict__ gam, const float* __restrict__ bet){
    __shared__ float tile[34*34];
    __shared__ float wsh[8][9];
    int b  = blockIdx.y;
    int co0= blockIdx.x*8;
    int tid= threadIdx.x;
    int y  = tid>>3;
    int x0 = (tid&7)*4;
    float mean = g_st2[2*b], inv = g_st2[2*b+1];
    float acc[8][4];
    #pragma unroll
    for (int a=0;a<8;a++){ acc[a][0]=acc[a][1]=acc[a][2]=acc[a][3]=0.f; }
    const float* inb = g_x2 + (long long)b*FC*HWP;
    for (int ci=0; ci<FC; ci++){
        for (int idx=tid; idx<34*34; idx+=256){
            int ty=idx/34, tx=idx-ty*34;
            int yy=ty-1, xx=tx-1;
            float v = 0.f;
            if (yy>=0 && yy<32 && xx>=0 && xx<32){
                int pos = yy*32+xx;
                v = (inb[ci*HWP + pos]-mean)*inv*gam[ci*HWP+pos] + bet[ci*HWP+pos];
            }
            tile[idx] = v;
        }
        if (tid < 72){
            int co=tid/9, j=tid-co*9;
            wsh[co][j] = (co0+co < COUT2) ? w[((long long)(co0+co)*FC + ci)*9 + j] : 0.f;
        }
        __syncthreads();
        float v[3][6];
        #pragma unroll
        for (int r=0;r<3;r++)
            #pragma unroll
            for (int c=0;c<6;c++)
                v[r][c] = tile[(y+r)*34 + x0 + c];
        #pragma unroll
        for (int co=0;co<8;co++){
            #pragma unroll
            for (int p=0;p<4;p++){
                float s = acc[co][p];
                #pragma unroll
                for (int dy=0;dy<3;dy++)
                    #pragma unroll
                    for (int dx=0;dx<3;dx++)
                        s += v[dy][p+dx]*wsh[co][dy*3+dx];
                acc[co][p] = s;
            }
        }
        __syncthreads();
    }
    #pragma unroll
    for (int co=0;co<8;co++){
        if (co0+co < COUT2){
            float bb = bias[co0+co];
            float4 r = make_float4(acc[co][0]+bb, acc[co][1]+bb, acc[co][2]+bb, acc[co][3]+bb);
            *(float4*)&g_par[((long long)b*COUT2 + co0+co)*HWP + y*32 + x0] = r;
        }
    }
}

// ---------------- 9. logdet init ----------------
__global__ void init_log_kernel(const float* __restrict__ ldf, float* __restrict__ out_log){
    int b = threadIdx.x;
    if (b < BATCH) out_log[b] = ldf[b];
}

// ---------------- 10. mixture + logit + affine + merge ----------------
__global__ void mixture_kernel(const float* __restrict__ als, const float* __restrict__ ab,
                               float* __restrict__ out_z, float* __restrict__ out_log){
    int b  = blockIdx.x;
    int c0 = blockIdx.y;
    int p  = threadIdx.x;
    const float* P = g_par + (long long)b*COUT2*HWP;

    float aRaw = P[(long long)c0*HWP + p];
    float bRaw = P[(long long)(6+c0)*HWP + p];
    float lp[KMIX], mu[KMIX], ss[KMIX];
    #pragma unroll
    for (int k=0;k<KMIX;k++){
        lp[k] = P[(long long)(12 + k*C0C + c0)*HWP + p];
        mu[k] = P[(long long)(60 + k*C0C + c0)*HWP + p];
        ss[k] = P[(long long)(108+ k*C0C + c0)*HWP + p];
    }
    float a = tanhf(aRaw)*als[0] + ab[0];

    float mx = lp[0];
    #pragma unroll
    for (int k=1;k<KMIX;k++) mx = fmaxf(mx, lp[k]);
    float se = 0.f;
    #pragma unroll
    for (int k=0;k<KMIX;k++) se += __expf(lp[k]-mx);
    float lse = mx + __logf(se);

    float z0v = g_z0[((long long)b*C0C + c0)*HWP + p];
    float tvals[KMIX];
    float xsum = 0.f;
    #pragma unroll
    for (int k=0;k<KMIX;k++){
        float lpn = lp[k] - lse;
        float u   = (z0v - mu[k]) * __expf(-ss[k]);
        xsum += __expf(lpn) * sigf(u);
        tvals[k] = lpn - ss[k] + logsigf(u) + logsigf(-u);
    }
    float tm = tvals[0];
    #pragma unroll
    for (int k=1;k<KMIX;k++) tm = fmaxf(tm, tvals[k]);
    float tse = 0.f;
    #pragma unroll
    for (int k=0;k<KMIX;k++) tse += __expf(tvals[k]-tm);
    float logpdf = tm + __logf(tse);

    float x = fminf(fmaxf(xsum, 1e-6f), 1.0f-1e-6f);
    float lx  = __logf(x);
    float l1x = log1pf(-x);
    float z0n = (lx - l1x) * __expf(a) + bRaw;
    float contrib = logpdf + (-lx - l1x) + a;

    int i = p>>5, j = p&31;
    float z1v = g_z1[((long long)b*C0C + c0)*HWP + p];
    if (c0 < 3){
        float* ob = out_z + ((long long)b*3 + c0)*64*64;
        ob[(2*i)*64 + 2*j    ] = z0n;
        ob[(2*i)*64 + 2*j + 1] = z1v;
    } else {
        float* ob = out_z + ((long long)b*3 + (c0-3))*64*64;
        ob[(2*i+1)*64 + 2*j + 1] = z0n;
        ob[(2*i+1)*64 + 2*j    ] = z1v;
    }

    __shared__ float sh[32];
    int lane = p&31, wid = p>>5;
    float v = warp_sum(contrib);
    if (lane==0) sh[wid]=v;
    __syncthreads();
    if (wid==0){
        float w = (lane<32)? sh[lane] : 0.f;
        w = warp_sum(w);
        if (lane==0) atomicAdd(&out_log[b], w);
    }
}

// ---------------- host launcher ----------------
extern "C" void kernel_launch(void* const* d_in, const int* in_sizes, int n_in,
                              void* d_out, int out_size){
    const float* z        = (const float*)d_in[0];
    const float* log_df   = (const float*)d_in[1];
    const float* conv1_w  = (const float*)d_in[2];
    const float* conv1_b  = (const float*)d_in[3];
    const float* gconv_w  = (const float*)d_in[4];
    const float* gconv_b  = (const float*)d_in[5];
    const float* ln1_g    = (const float*)d_in[6];
    const float* ln1_b    = (const float*)d_in[7];
    const float* qkv_w    = (const float*)d_in[8];
    const float* qkv_b    = (const float*)d_in[9];
    const float* proj_w   = (const float*)d_in[10];
    const float* proj_b   = (const float*)d_in[11];
    const float* ln2_g    = (const float*)d_in[12];
    const float* ln2_b    = (const float*)d_in[13];
    const float* conv2_w  = (const float*)d_in[14];
    const float* conv2_b  = (const float*)d_in[15];
    const float* a_ls     = (const float*)d_in[16];
    const float* a_bias   = (const float*)d_in[17];

    float* out_z   = (float*)d_out;
    float* out_log = (float*)d_out + (long long)BATCH*3*64*64;

    float *p_z1, *p_x1, *p_xg, *p_xf, *p_qkv, *p_o, *p_x2, *p_st1, *p_st2;
    cudaGetSymbolAddress((void**)&p_z1,  g_z1);
    cudaGetSymbolAddress((void**)&p_x1,  g_x1);
    cudaGetSymbolAddress((void**)&p_xg,  g_xg);
    cudaGetSymbolAddress((void**)&p_xf,  g_xf);
    cudaGetSymbolAddress((void**)&p_qkv, g_qkv);
    cudaGetSymbolAddress((void**)&p_o,   g_o);
    cudaGetSymbolAddress((void**)&p_x2,  g_x2);
    cudaGetSymbolAddress((void**)&p_st1, g_st1);
    cudaGetSymbolAddress((void**)&p_st2, g_st2);
    float* p_pr;  cudaGetSymbolAddress((void**)&p_pr, g_pr);

    static int smem_set = 0;
    const int FLASH_SMEM = (64*QLD + 64*KLD + 64*VLD + 64*PLD)*4;
    if (!smem_set){
        cudaFuncSetAttribute(flash_tf32_kernel, cudaFuncAttributeMaxDynamicSharedMemorySize, FLASH_SMEM);
        smem_set = 1;
    }

    split_kernel<<<(BATCH*3*HWP+255)/256, 256>>>(z);
    conv3x3_kernel<6><<<dim3(12, BATCH), 256>>>(p_z1, conv1_w, conv1_b, p_x1, FC);
    gconv_gate_kernel<<<dim3(12, BATCH), 256>>>(gconv_w, gconv_b);
    ln_stats_kernel<<<BATCH, 1024>>>(p_xg, p_st1);
    ln1_transpose_kernel<<<dim3(32, 3, BATCH), 256>>>(ln1_g, ln1_b);
    gemm_kernel<true><<<dim3(5,16,BATCH), 256>>>(p_xf, qkv_w, p_qkv,
        SEQ, 3*FC, FC, FC, FC, 3*FC,
        (long long)SEQ*FC, 0LL, (long long)SEQ*3*FC, qkv_b, 1.0f);
    flash_tf32_kernel<<<dim3(16, BATCH), 128, FLASH_SMEM>>>();
    gemm_kernel<true><<<dim3(3,16,BATCH), 256>>>(p_o, proj_w, p_pr,
        SEQ, 2*FC, FC, FC, FC, 2*FC,
        (long long)SEQ*FC, 0LL, (long long)SEQ*2*FC, proj_b, 1.0f);
    gate_transpose_kernel<<<dim3(32, 3, BATCH), 256>>>();
    ln_stats_kernel<<<BATCH, 1024>>>(p_x2, p_st2);
    conv2_ln_kernel<<<dim3(20, BATCH), 256>>>(conv2_w, conv2_b, ln2_g, ln2_b);
    init_log_kernel<<<1, 64>>>(log_df, out_log);
    mixture_kernel<<<dim3(BATCH, C0C), 1024>>>(a_ls, a_bias, out_z, out_log);
}

// round 7
// speedup vs baseline: 2.0839x; 1.5030x over previous
#include <cuda_runtime.h>
#include <math.h>
#include <stdint.h>

// ---------------- problem constants ----------------
#define BATCH 64
#define C0C   6
#define FC    96
#define KMIX  8
#define HWP   1024
#define SEQ   1024
#define COUT2 156

// ---------------- scratch ----------------
__device__ float g_z0 [BATCH*C0C*HWP];
__device__ float g_z1 [BATCH*C0C*HWP];
__device__ float g_x1 [BATCH*FC*HWP];
__device__ float g_xg [BATCH*FC*HWP];
__device__ float g_xf [BATCH*SEQ*FC];
__device__ float g_qkv[BATCH*SEQ*3*FC];
__device__ float g_o  [BATCH*SEQ*FC];
__device__ float g_pr [BATCH*SEQ*2*FC];
__device__ float g_x2 [BATCH*FC*HWP];
__device__ float g_par[BATCH*COUT2*HWP];
__device__ float g_st2[BATCH*2];
__device__ float g_st1[BATCH*2];

// ---------------- helpers ----------------
__device__ __forceinline__ float warp_sum(float v){
    #pragma unroll
    for (int o=16;o;o>>=1) v += __shfl_xor_sync(0xffffffffu, v, o);
    return v;
}
__device__ __forceinline__ float sigf(float v){ return 1.0f/(1.0f+__expf(-v)); }
__device__ __forceinline__ float logsigf(float v){ return fminf(v,0.0f) - log1pf(__expf(-fabsf(v))); }
__device__ __forceinline__ float cvt_tf32(float x){
    uint32_t r; asm("cvt.rna.tf32.f32 %0, %1;" : "=r"(r) : "f"(x)); return __uint_as_float(r);
}
__device__ __forceinline__ void mma_tf32(float* c, float a0,float a1,float a2,float a3,
                                         float b0,float b1){
    asm volatile("mma.sync.aligned.m16n8k8.row.col.f32.tf32.tf32.f32 "
        "{%0,%1,%2,%3}, {%4,%5,%6,%7}, {%8,%9}, {%0,%1,%2,%3};\n"
        : "+f"(c[0]),"+f"(c[1]),"+f"(c[2]),"+f"(c[3])
        : "r"(__float_as_uint(a0)),"r"(__float_as_uint(a1)),
          "r"(__float_as_uint(a2)),"r"(__float_as_uint(a3)),
          "r"(__float_as_uint(b0)),"r"(__float_as_uint(b1)));
}

// ---------------- 1. checkerboard split ----------------
__global__ void split_kernel(const float* __restrict__ z){
    int idx = blockIdx.x*blockDim.x + threadIdx.x;
    if (idx >= BATCH*3*HWP) return;
    int j = idx & 31, i = (idx>>5) & 31;
    int c = (idx>>10) % 3;
    int b = idx / (3*HWP);
    const float* zb = z + ((long long)b*3 + c)*64*64;
    float p00 = zb[(2*i  )*64 + 2*j  ];
    float p01 = zb[(2*i  )*64 + 2*j+1];
    float p10 = zb[(2*i+1)*64 + 2*j  ];
    float p11 = zb[(2*i+1)*64 + 2*j+1];
    int base = ((b*C0C)+c)*HWP + i*32 + j;
    g_z0[base]          = p00;
    g_z0[base + 3*HWP]  = p11;
    g_z1[base]          = p01;
    g_z1[base + 3*HWP]  = p10;
}

// ---------------- 2. conv1 (6 -> 96), scalar ----------------
template<int CIN>
__global__ void conv3x3_kernel(const float* __restrict__ in, const float* __restrict__ w,
                               const float* __restrict__ bias, float* __restrict__ out, int Cout){
    __shared__ float tile[34*34];
    __shared__ float wsh[8][9];
    int b  = blockIdx.y;
    int co0= blockIdx.x*8;
    int tid= threadIdx.x;
    int y  = tid>>3;
    int x0 = (tid&7)*4;
    float acc[8][4];
    #pragma unroll
    for (int a=0;a<8;a++){ acc[a][0]=acc[a][1]=acc[a][2]=acc[a][3]=0.f; }
    const float* inb = in + (long long)b*CIN*HWP;
    for (int ci=0; ci<CIN; ci++){
        for (int idx=tid; idx<34*34; idx+=256){
            int ty=idx/34, tx=idx-ty*34;
            int yy=ty-1, xx=tx-1;
            tile[idx] = (yy>=0 && yy<32 && xx>=0 && xx<32) ? inb[ci*HWP + yy*32 + xx] : 0.f;
        }
        if (tid < 72){
            int co=tid/9, j=tid-co*9;
            wsh[co][j] = (co0+co < Cout) ? w[((long long)(co0+co)*CIN + ci)*9 + j] : 0.f;
        }
        __syncthreads();
        float v[3][6];
        #pragma unroll
        for (int r=0;r<3;r++)
            #pragma unroll
            for (int c=0;c<6;c++)
                v[r][c] = tile[(y+r)*34 + x0 + c];
        #pragma unroll
        for (int co=0;co<8;co++){
            #pragma unroll
            for (int p=0;p<4;p++){
                float s = acc[co][p];
                #pragma unroll
                for (int dy=0;dy<3;dy++)
                    #pragma unroll
                    for (int dx=0;dx<3;dx++)
                        s += v[dy][p+dx]*wsh[co][dy*3+dx];
                acc[co][p] = s;
            }
        }
        __syncthreads();
    }
    #pragma unroll
    for (int co=0;co<8;co++){
        if (co0+co < Cout){
            float bb = bias[co0+co];
            float4 r = make_float4(acc[co][0]+bb, acc[co][1]+bb, acc[co][2]+bb, acc[co][3]+bb);
            *(float4*)&out[((long long)b*Cout + co0+co)*HWP + y*32 + x0] = r;
        }
    }
}

// ---------------- 3. tf32 implicit-GEMM 3x3 conv (96-ch input) ----------------
// GATE=true : in = g_x1, out = g_xg = x1 + ga*sigmoid(gb), co-tile = 32 pairs
// GATE=false: in = g_x2 with LN2 applied on load, out = g_par (co<156)
// block 256 thr / 8 warps. Output tile: M=64 co x N=256 positions (8 image rows)
#define WS_SZ   (9*8*72)        // 5184
#define TILE_SZ (8*10*36)       // 2880
#define SB_LD   258             // staging stride (even -> float2-aligned)
template<bool GATE>
__global__ void conv_mma_kernel(const float* __restrict__ w, const float* __restrict__ bias,
                                const float* __restrict__ gam, const float* __restrict__ bet){
    extern __shared__ float sm[];
    float* ws   = sm;             // [tap][cil][72]
    float* tile = sm + WS_SZ;     // [cil][10][36]

    int b   = blockIdx.z;
    int ct  = blockIdx.y;
    int r0  = blockIdx.x*8;       // image row base
    int tid = threadIdx.x;
    int wp  = tid>>5, lane = tid&31;
    int gid = lane>>2, tig = lane&3;
    int mrow  = (wp&3)*16;
    int nhalf = wp>>2;

    const float* inb = (GATE ? g_x1 : g_x2) + (long long)b*FC*HWP;
    float mean=0.f, inv=0.f;
    if (!GATE){ mean = g_st2[2*b]; inv = g_st2[2*b+1]; }

    float c[16][4];
    #pragma unroll
    for (int j=0;j<16;j++){ c[j][0]=c[j][1]=c[j][2]=c[j][3]=0.f; }

    for (int chunk=0; chunk<12; chunk++){
        int ci0 = chunk*8;
        // weights: ws[tap][cil][r], r = 0..63 output row
        for (int i=tid; i<9*8*64; i+=256){
            int tap = i/(8*64); int rem = i - tap*8*64;
            int cil = rem>>6;    int r   = rem&63;
            int co;
            float v = 0.f;
            if (GATE){
                co = (r<32) ? (ct*32 + r) : (FC + ct*32 + (r-32));
                v = w[((long long)co*FC + ci0+cil)*9 + tap];
            } else {
                co = ct*64 + r;
                if (co < COUT2) v = w[((long long)co*FC + ci0+cil)*9 + tap];
            }
            ws[tap*576 + cil*72 + r] = cvt_tf32(v);
        }
        // input tile: [cil][ry 0..9][cx 0..35], image rows r0-1..r0+8, cols -1..32
        for (int i=tid; i<TILE_SZ; i+=256){
            int cil = i/360; int rem = i - cil*360;
            int ry = rem/36; int cx = rem - ry*36;
            float v = 0.f;
            int iy = r0-1+ry, ix = cx-1;
            if (cx<34 && iy>=0 && iy<32 && ix>=0 && ix<32){
                int pos = iy*32+ix;
                v = inb[(ci0+cil)*HWP + pos];
                if (!GATE) v = (v-mean)*inv*gam[(ci0+cil)*HWP+pos] + bet[(ci0+cil)*HWP+pos];
            }
            tile[i] = cvt_tf32(v);
        }
        __syncthreads();

        #pragma unroll
        for (int tap=0;tap<9;tap++){
            int dy = tap/3, dx = tap - dy*3;
            float a0 = ws[tap*576 + tig*72     + mrow+gid];
            float a1 = ws[tap*576 + tig*72     + mrow+gid+8];
            float a2 = ws[tap*576 + (tig+4)*72 + mrow+gid];
            float a3 = ws[tap*576 + (tig+4)*72 + mrow+gid+8];
            #pragma unroll
            for (int j=0;j<16;j++){
                int lr = nhalf*4 + (j>>2);
                int cg = (j&3)*8;
                float b0 = tile[tig*360     + (lr+dy)*36 + cg+gid+dx];
                float b1 = tile[(tig+4)*360 + (lr+dy)*36 + cg+gid+dx];
                mma_tf32(c[j], a0,a1,a2,a3, b0,b1);
            }
        }
        __syncthreads();
    }

    if (GATE){
        // stage all 64 rows x 256 cols in smem, then gate
        float* sbuf = sm;   // [64][SB_LD]
        #pragma unroll
        for (int j=0;j<16;j++){
            int lr = nhalf*4 + (j>>2);
            int cg = (j&3)*8;
            int n  = lr*32 + cg + 2*tig;
            *(float2*)&sbuf[(mrow+gid  )*SB_LD + n] = make_float2(c[j][0], c[j][1]);
            *(float2*)&sbuf[(mrow+gid+8)*SB_LD + n] = make_float2(c[j][2], c[j][3]);
        }
        __syncthreads();
        for (int i=tid; i<32*256; i+=256){
            int r = i>>8, n = i&255;
            float val = sbuf[r*SB_LD+n]      + bias[ct*32+r];
            float gat = sbuf[(r+32)*SB_LD+n] + bias[FC+ct*32+r];
            long long off = ((long long)b*FC + ct*32 + r)*HWP + r0*32 + n;
            g_xg[off] = g_x1[off] + val*sigf(gat);
        }
    } else {
        #pragma unroll
        for (int j=0;j<16;j++){
            int lr = nhalf*4 + (j>>2);
            int cg = (j&3)*8;
            int pos = (r0+lr)*32 + cg + 2*tig;
            int row0 = ct*64 + mrow + gid;
            int row1 = row0 + 8;
            if (row0 < COUT2){
                float bb = bias[row0];
                *(float2*)&g_par[((long long)b*COUT2 + row0)*HWP + pos] =
                    make_float2(c[j][0]+bb, c[j][1]+bb);
            }
            if (row1 < COUT2){
                float bb = bias[row1];
                *(float2*)&g_par[((long long)b*COUT2 + row1)*HWP + pos] =
                    make_float2(c[j][2]+bb, c[j][3]+bb);
            }
        }
    }
}

// ---------------- 4. LN stats only ----------------
__global__ void ln_stats_kernel(const float* __restrict__ x, float* __restrict__ st){
    const int N = FC*HWP;
    int b = blockIdx.x;
    const float4* xb = (const float4*)(x + (long long)b*N);
    float s=0.f, s2=0.f;
    for (int i=threadIdx.x;i<N/4;i+=blockDim.x){
        float4 v = xb[i];
        s  += v.x+v.y+v.z+v.w;
        s2 += v.x*v.x+v.y*v.y+v.z*v.z+v.w*v.w;
    }
    __shared__ float shs[32], shs2[32];
    int lane = threadIdx.x&31, wid = threadIdx.x>>5;
    s = warp_sum(s); s2 = warp_sum(s2);
    if (lane==0){ shs[wid]=s; shs2[wid]=s2; }
    __syncthreads();
    int nw = blockDim.x>>5;
    if (wid==0){
        float a = (lane<nw)? shs[lane]:0.f;
        float a2= (lane<nw)? shs2[lane]:0.f;
        a = warp_sum(a); a2 = warp_sum(a2);
        if (lane==0){
            float mean = a/(float)N;
            float var  = a2/(float)N - mean*mean;
            st[2*b]   = mean;
            st[2*b+1] = rsqrtf(var + 1e-5f);
        }
    }
}

// ---------------- 5a. ln1 apply + transpose to token-major ----------------
__global__ void ln1_transpose_kernel(const float* __restrict__ gam, const float* __restrict__ bet){
    __shared__ float t[32][33];
    int b  = blockIdx.z;
    int f0 = blockIdx.y*32;
    int p0 = blockIdx.x*32;
    float mean = g_st1[2*b], inv = g_st1[2*b+1];
    int tx = threadIdx.x&31, ty = threadIdx.x>>5;
    #pragma unroll
    for (int k=0;k<4;k++){
        int f = f0 + ty + 8*k;
        int col = p0 + tx;
        float v = g_xg[((long long)b*FC + f)*HWP + col];
        t[ty+8*k][tx] = (v-mean)*inv*gam[f*HWP + col] + bet[f*HWP + col];
    }
    __syncthreads();
    #pragma unroll
    for (int k=0;k<4;k++){
        int p = p0 + ty + 8*k;
        g_xf[((long long)b*SEQ + p)*FC + f0 + tx] = t[tx][ty+8*k];
    }
}

// ---------------- 5b. attn gate + transpose to channel-major ----------------
__global__ void gate_transpose_kernel(){
    __shared__ float t[32][33];
    int b  = blockIdx.z;
    int f0 = blockIdx.y*32;
    int p0 = blockIdx.x*32;
    int tx = threadIdx.x&31, ty = threadIdx.x>>5;
    #pragma unroll
    for (int k=0;k<4;k++){
        int p = p0 + ty + 8*k;
        long long base = ((long long)b*SEQ + p);
        float xv = g_xf[base*FC + f0 + tx];
        float ga = g_pr[base*2*FC + f0 + tx];
        float gb = g_pr[base*2*FC + FC + f0 + tx];
        t[ty+8*k][tx] = xv + ga*sigf(gb);
    }
    __syncthreads();
    #pragma unroll
    for (int k=0;k<4;k++){
        int f = f0 + ty + 8*k;
        g_x2[((long long)b*FC + f)*HWP + p0 + tx] = t[tx][ty+8*k];
    }
}

// ---------------- 6. batched SGEMM (qkv / proj) ----------------
template<bool TB>
__global__ void gemm_kernel(const float* __restrict__ A, const float* __restrict__ Bm,
                            float* __restrict__ C,
                            int M, int N, int K, int lda, int ldb, int ldc,
                            long long sA, long long sB, long long sC,
                            const float* __restrict__ bias, float alpha){
    __shared__ float As[16][64];
    __shared__ float Bs[16][64];
    A += blockIdx.z * sA;
    Bm+= blockIdx.z * sB;
    C += blockIdx.z * sC;
    int n0 = blockIdx.x*64;
    int m0 = blockIdx.y*64;
    int tid = threadIdx.x;
    int tx = tid & 15, ty = tid >> 4;
    float acc[4][4];
    #pragma unroll
    for (int i=0;i<4;i++){ acc[i][0]=acc[i][1]=acc[i][2]=acc[i][3]=0.f; }
    int ra = tid>>2;
    int ca = (tid&3)*4;
    int rb = tid>>4;
    int cb = (tid&15)*4;
    for (int k0=0; k0<K; k0+=16){
        #pragma unroll
        for (int j=0;j<4;j++)
            As[ca+j][ra] = A[(long long)(m0+ra)*lda + (k0+ca+j)];
        if (TB){
            int n = n0 + ra;
            #pragma unroll
            for (int j=0;j<4;j++)
                Bs[ca+j][ra] = (n<N) ? Bm[(long long)n*ldb + (k0+ca+j)] : 0.f;
        } else {
            #pragma unroll
            for (int j=0;j<4;j++){
                int n = n0 + cb + j;
                Bs[rb][cb+j] = (n<N) ? Bm[(long long)(k0+rb)*ldb + n] : 0.f;
            }
        }
        __syncthreads();
        #pragma unroll
        for (int kk=0;kk<16;kk++){
            float4 av = *(const float4*)&As[kk][ty*4];
            float4 bv = *(const float4*)&Bs[kk][tx*4];
            float a[4] = {av.x,av.y,av.z,av.w};
            float bb[4]= {bv.x,bv.y,bv.z,bv.w};
            #pragma unroll
            for (int i=0;i<4;i++)
                #pragma unroll
                for (int j=0;j<4;j++)
                    acc[i][j] += a[i]*bb[j];
        }
        __syncthreads();
    }
    #pragma unroll
    for (int i=0;i<4;i++){
        int m = m0 + ty*4 + i;
        #pragma unroll
        for (int j=0;j<4;j++){
            int n = n0 + tx*4 + j;
            if (n < N){
                float v = alpha*acc[i][j];
                if (bias) v += bias[n];
                C[(long long)m*ldc + n] = v;
            }
        }
    }
}

// ---------------- 7. flash attention, tf32 mma ----------------
#define QLD 100
#define KLD 100
#define VLD 104
#define PLD 68
__global__ void flash_tf32_kernel(){
    extern __shared__ float sm[];
    float* Qs = sm;
    float* Ks = Qs + 64*QLD;
    float* Vs = Ks + 64*KLD;
    float* Ps = Vs + 64*VLD;

    int b   = blockIdx.y;
    int t0  = blockIdx.x*64;
    int tid = threadIdx.x;
    int w   = tid>>5, lane = tid&31;
    int gid = lane>>2, tig = lane&3;
    const float scale = rsqrtf((float)FC);
    const float* qkvb = g_qkv + (long long)b*SEQ*3*FC;

    for (int i=tid;i<64*FC;i+=128){
        int m=i/FC, k=i-m*FC;
        Qs[m*QLD+k] = cvt_tf32(qkvb[(long long)(t0+m)*3*FC + k]*scale);
    }

    float O[12][4];
    #pragma unroll
    for (int j=0;j<12;j++){ O[j][0]=O[j][1]=O[j][2]=O[j][3]=0.f; }
    float mA=-1e30f, mB=-1e30f, lA=0.f, lB=0.f;
    __syncthreads();

    for (int it=0; it<16; it++){
        int kv0 = it*64;
        for (int i=tid;i<64*FC;i+=128){
            int n=i/FC, k=i-n*FC;
            Ks[n*KLD+k] = cvt_tf32(qkvb[(long long)(kv0+n)*3*FC + FC + k]);
        }
        for (int i=tid;i<64*FC;i+=128){
            int k=i/FC, n=i-k*FC;
            Vs[k*VLD+n] = cvt_tf32(qkvb[(long long)(kv0+k)*3*FC + 2*FC + n]);
        }
        __syncthreads();

        float c[8][4];
        #pragma unroll
        for (int j=0;j<8;j++){ c[j][0]=c[j][1]=c[j][2]=c[j][3]=0.f; }
        #pragma unroll
        for (int kk=0;kk<12;kk++){
            int k0=kk*8;
            float a0 = Qs[(16*w+gid  )*QLD + k0+tig];
            float a1 = Qs[(16*w+gid+8)*QLD + k0+tig];
            float a2 = Qs[(16*w+gid  )*QLD + k0+tig+4];
            float a3 = Qs[(16*w+gid+8)*QLD + k0+tig+4];
            #pragma unroll
            for (int j=0;j<8;j++){
                float b0 = Ks[(j*8+gid)*KLD + k0+tig];
                float b1 = Ks[(j*8+gid)*KLD + k0+tig+4];
                mma_tf32(c[j], a0,a1,a2,a3, b0,b1);
            }
        }

        float mlA=-1e30f, mlB=-1e30f;
        #pragma unroll
        for (int j=0;j<8;j++){
            mlA = fmaxf(mlA, fmaxf(c[j][0],c[j][1]));
            mlB = fmaxf(mlB, fmaxf(c[j][2],c[j][3]));
        }
        mlA = fmaxf(mlA, __shfl_xor_sync(0xffffffffu, mlA, 1));
        mlA = fmaxf(mlA, __shfl_xor_sync(0xffffffffu, mlA, 2));
        mlB = fmaxf(mlB, __shfl_xor_sync(0xffffffffu, mlB, 1));
        mlB = fmaxf(mlB, __shfl_xor_sync(0xffffffffu, mlB, 2));
        float mnA = fmaxf(mA, mlA), mnB = fmaxf(mB, mlB);
        float alA = __expf(mA-mnA), alB = __expf(mB-mnB);
        float sA=0.f, sB=0.f;
        #pragma unroll
        for (int j=0;j<8;j++){
            c[j][0] = __expf(c[j][0]-mnA); sA += c[j][0];
            c[j][1] = __expf(c[j][1]-mnA); sA += c[j][1];
            c[j][2] = __expf(c[j][2]-mnB); sB += c[j][2];
            c[j][3] = __expf(c[j][3]-mnB); sB += c[j][3];
        }
        sA += __shfl_xor_sync(0xffffffffu, sA, 1);
        sA += __shfl_xor_sync(0xffffffffu, sA, 2);
        sB += __shfl_xor_sync(0xffffffffu, sB, 1);
        sB += __shfl_xor_sync(0xffffffffu, sB, 2);
        lA = lA*alA + sA; mA = mnA;
        lB = lB*alB + sB; mB = mnB;
        #pragma unroll
        for (int j=0;j<12;j++){
            O[j][0]*=alA; O[j][1]*=alA; O[j][2]*=alB; O[j][3]*=alB;
        }
        #pragma unroll
        for (int j=0;j<8;j++){
            int colp = j*8 + 2*tig;
            float2 v0 = make_float2(cvt_tf32(c[j][0]), cvt_tf32(c[j][1]));
            float2 v1 = make_float2(cvt_tf32(c[j][2]), cvt_tf32(c[j][3]));
            *(float2*)&Ps[(16*w+gid  )*PLD + colp] = v0;
            *(float2*)&Ps[(16*w+gid+8)*PLD + colp] = v1;
        }
        __syncwarp();

        #pragma unroll
        for (int kk=0;kk<8;kk++){
            int k0=kk*8;
            float a0 = Ps[(16*w+gid  )*PLD + k0+tig];
            float a1 = Ps[(16*w+gid+8)*PLD + k0+tig];
            float a2 = Ps[(16*w+gid  )*PLD + k0+tig+4];
            float a3 = Ps[(16*w+gid+8)*PLD + k0+tig+4];
            #pragma unroll
            for (int j=0;j<12;j++){
                float b0 = Vs[(k0+tig  )*VLD + j*8+gid];
                float b1 = Vs[(k0+tig+4)*VLD + j*8+gid];
                mma_tf32(O[j], a0,a1,a2,a3, b0,b1);
            }
        }
        __syncthreads();
    }

    float iA = 1.0f/lA, iB = 1.0f/lB;
    float* ob = g_o + ((long long)b*SEQ + t0)*FC;
    #pragma unroll
    for (int j=0;j<12;j++){
        int n = j*8 + 2*tig;
        *(float2*)&ob[(long long)(16*w+gid  )*FC + n] = make_float2(O[j][0]*iA, O[j][1]*iA);
        *(float2*)&ob[(long long)(16*w+gid+8)*FC + n] = make_float2(O[j][2]*iB, O[j][3]*iB);
    }
}

// ---------------- 9. logdet init ----------------
__global__ void init_log_kernel(const float* __restrict__ ldf, float* __restrict__ out_log){
    int b = threadIdx.x;
    if (b < BATCH) out_log[b] = ldf[b];
}

// ---------------- 10. mixture + logit + affine + merge ----------------
__global__ void mixture_kernel(const float* __restrict__ als, const float* __restrict__ ab,
                               float* __restrict__ out_z, float* __restrict__ out_log){
    int b  = blockIdx.x;
    int c0 = blockIdx.y;
    int p  = threadIdx.x;
    const float* P = g_par + (long long)b*COUT2*HWP;

    float aRaw = P[(long long)c0*HWP + p];
    float bRaw = P[(long long)(6+c0)*HWP + p];
    float lp[KMIX], mu[KMIX], ss[KMIX];
    #pragma unroll
    for (int k=0;k<KMIX;k++){
        lp[k] = P[(long long)(12 + k*C0C + c0)*HWP + p];
        mu[k] = P[(long long)(60 + k*C0C + c0)*HWP + p];
        ss[k] = P[(long long)(108+ k*C0C + c0)*HWP + p];
    }
    float a = tanhf(aRaw)*als[0] + ab[0];

    float mx = lp[0];
    #pragma unroll
    for (int k=1;k<KMIX;k++) mx = fmaxf(mx, lp[k]);
    float se = 0.f;
    #pragma unroll
    for (int k=0;k<KMIX;k++) se += __expf(lp[k]-mx);
    float lse = mx + __logf(se);

    float z0v = g_z0[((long long)b*C0C + c0)*HWP + p];
    float tvals[KMIX];
    float xsum = 0.f;
    #pragma unroll
    for (int k=0;k<KMIX;k++){
        float lpn = lp[k] - lse;
        float u   = (z0v - mu[k]) * __expf(-ss[k]);
        xsum += __expf(lpn) * sigf(u);
        tvals[k] = lpn - ss[k] + logsigf(u) + logsigf(-u);
    }
    float tm = tvals[0];
    #pragma unroll
    for (int k=1;k<KMIX;k++) tm = fmaxf(tm, tvals[k]);
    float tse = 0.f;
    #pragma unroll
    for (int k=0;k<KMIX;k++) tse += __expf(tvals[k]-tm);
    float logpdf = tm + __logf(tse);

    float x = fminf(fmaxf(xsum, 1e-6f), 1.0f-1e-6f);
    float lx  = __logf(x);
    float l1x = log1pf(-x);
    float z0n = (lx - l1x) * __expf(a) + bRaw;
    float contrib = logpdf + (-lx - l1x) + a;

    int i = p>>5, j = p&31;
    float z1v = g_z1[((long long)b*C0C + c0)*HWP + p];
    if (c0 < 3){
        float* ob = out_z + ((long long)b*3 + c0)*64*64;
        ob[(2*i)*64 + 2*j    ] = z0n;
        ob[(2*i)*64 + 2*j + 1] = z1v;
    } else {
        float* ob = out_z + ((long long)b*3 + (c0-3))*64*64;
        ob[(2*i+1)*64 + 2*j + 1] = z0n;
        ob[(2*i+1)*64 + 2*j    ] = z1v;
    }

    __shared__ float sh[32];
    int lane = p&31, wid = p>>5;
    float v = warp_sum(contrib);
    if (lane==0) sh[wid]=v;
    __syncthreads();
    if (wid==0){
        float w = (lane<32)? sh[lane] : 0.f;
        w = warp_sum(w);
        if (lane==0) atomicAdd(&out_log[b], w);
    }
}

// ---------------- host launcher ----------------
extern "C" void kernel_launch(void* const* d_in, const int* in_sizes, int n_in,
                              void* d_out, int out_size){
    const float* z        = (const float*)d_in[0];
    const float* log_df   = (const float*)d_in[1];
    const float* conv1_w  = (const float*)d_in[2];
    const float* conv1_b  = (const float*)d_in[3];
    const float* gconv_w  = (const float*)d_in[4];
    const float* gconv_b  = (const float*)d_in[5];
    const float* ln1_g    = (const float*)d_in[6];
    const float* ln1_b    = (const float*)d_in[7];
    const float* qkv_w    = (const float*)d_in[8];
    const float* qkv_b    = (const float*)d_in[9];
    const float* proj_w   = (const float*)d_in[10];
    const float* proj_b   = (const float*)d_in[11];
    const float* ln2_g    = (const float*)d_in[12];
    const float* ln2_b    = (const float*)d_in[13];
    const float* conv2_w  = (const float*)d_in[14];
    const float* conv2_b  = (const float*)d_in[15];
    const float* a_ls     = (const float*)d_in[16];
    const float* a_bias   = (const float*)d_in[17];

    float* out_z   = (float*)d_out;
    float* out_log = (float*)d_out + (long long)BATCH*3*64*64;

    float *p_z1, *p_x1, *p_xg, *p_xf, *p_qkv, *p_o, *p_x2, *p_st1, *p_st2, *p_pr;
    cudaGetSymbolAddress((void**)&p_z1,  g_z1);
    cudaGetSymbolAddress((void**)&p_x1,  g_x1);
    cudaGetSymbolAddress((void**)&p_xg,  g_xg);
    cudaGetSymbolAddress((void**)&p_xf,  g_xf);
    cudaGetSymbolAddress((void**)&p_qkv, g_qkv);
    cudaGetSymbolAddress((void**)&p_o,   g_o);
    cudaGetSymbolAddress((void**)&p_x2,  g_x2);
    cudaGetSymbolAddress((void**)&p_st1, g_st1);
    cudaGetSymbolAddress((void**)&p_st2, g_st2);
    cudaGetSymbolAddress((void**)&p_pr,  g_pr);

    const int FLASH_SMEM = (64*QLD + 64*KLD + 64*VLD + 64*PLD)*4;
    const int GCONV_SMEM = 64*SB_LD*4;               // staging dominates
    const int CONV2_SMEM = (WS_SZ + TILE_SZ)*4;
    static int smem_set = 0;
    if (!smem_set){
        cudaFuncSetAttribute(flash_tf32_kernel, cudaFuncAttributeMaxDynamicSharedMemorySize, FLASH_SMEM);
        cudaFuncSetAttribute(conv_mma_kernel<true>,  cudaFuncAttributeMaxDynamicSharedMemorySize, GCONV_SMEM);
        cudaFuncSetAttribute(conv_mma_kernel<false>, cudaFuncAttributeMaxDynamicSharedMemorySize, CONV2_SMEM);
        smem_set = 1;
    }

    split_kernel<<<(BATCH*3*HWP+255)/256, 256>>>(z);
    conv3x3_kernel<6><<<dim3(12, BATCH), 256>>>(p_z1, conv1_w, conv1_b, p_x1, FC);
    conv_mma_kernel<true><<<dim3(4, 3, BATCH), 256, GCONV_SMEM>>>(gconv_w, gconv_b, nullptr, nullptr);
    ln_stats_kernel<<<BATCH, 1024>>>(p_xg, p_st1);
    ln1_transpose_kernel<<<dim3(32, 3, BATCH), 256>>>(ln1_g, ln1_b);
    gemm_kernel<true><<<dim3(5,16,BATCH), 256>>>(p_xf, qkv_w, p_qkv,
        SEQ, 3*FC, FC, FC, FC, 3*FC,
        (long long)SEQ*FC, 0LL, (long long)SEQ*3*FC, qkv_b, 1.0f);
    flash_tf32_kernel<<<dim3(16, BATCH), 128, FLASH_SMEM>>>();
    gemm_kernel<true><<<dim3(3,16,BATCH), 256>>>(p_o, proj_w, p_pr,
        SEQ, 2*FC, FC, FC, FC, 2*FC,
        (long long)SEQ*FC, 0LL, (long long)SEQ*2*FC, proj_b, 1.0f);
    gate_transpose_kernel<<<dim3(32, 3, BATCH), 256>>>();
    ln_stats_kernel<<<BATCH, 1024>>>(p_x2, p_st2);
    conv_mma_kernel<false><<<dim3(4, 3, BATCH), 256, CONV2_SMEM>>>(conv2_w, conv2_b, ln2_g, ln2_b);
    init_log_kernel<<<1, 64>>>(log_df, out_log);
    mixture_kernel<<<dim3(BATCH, C0C), 1024>>>(a_ls, a_bias, out_z, out_log);
}

// round 8
// speedup vs baseline: 3.1089x; 1.4918x over previous
#include <cuda_runtime.h>
#include <math.h>
#include <stdint.h>

// ---------------- problem constants ----------------
#define BATCH 64
#define C0C   6
#define FC    96
#define KMIX  8
#define HWP   1024
#define SEQ   1024
#define COUT2 156

// ---------------- scratch ----------------
__device__ float g_z0 [BATCH*C0C*HWP];
__device__ float g_z1 [BATCH*C0C*HWP];
__device__ float g_x1 [BATCH*FC*HWP];
__device__ float g_xg [BATCH*FC*HWP];
__device__ float g_xf [BATCH*SEQ*FC];
__device__ float g_qkv[BATCH*SEQ*3*FC];
__device__ float g_o  [BATCH*SEQ*FC];
__device__ float g_pr [BATCH*SEQ*2*FC];
__device__ float g_x2 [BATCH*FC*HWP];
__device__ float g_par[BATCH*COUT2*HWP];
__device__ float g_st2[BATCH*2];
__device__ float g_st1[BATCH*2];

// ---------------- helpers ----------------
__device__ __forceinline__ float warp_sum(float v){
    #pragma unroll
    for (int o=16;o;o>>=1) v += __shfl_xor_sync(0xffffffffu, v, o);
    return v;
}
__device__ __forceinline__ float sigf(float v){ return 1.0f/(1.0f+__expf(-v)); }
__device__ __forceinline__ float logsigf(float v){ return fminf(v,0.0f) - log1pf(__expf(-fabsf(v))); }
__device__ __forceinline__ float cvt_tf32(float x){
    uint32_t r; asm("cvt.rna.tf32.f32 %0, %1;" : "=r"(r) : "f"(x)); return __uint_as_float(r);
}
__device__ __forceinline__ void mma_tf32(float* c, float a0,float a1,float a2,float a3,
                                         float b0,float b1){
    asm volatile("mma.sync.aligned.m16n8k8.row.col.f32.tf32.tf32.f32 "
        "{%0,%1,%2,%3}, {%4,%5,%6,%7}, {%8,%9}, {%0,%1,%2,%3};\n"
        : "+f"(c[0]),"+f"(c[1]),"+f"(c[2]),"+f"(c[3])
        : "r"(__float_as_uint(a0)),"r"(__float_as_uint(a1)),
          "r"(__float_as_uint(a2)),"r"(__float_as_uint(a3)),
          "r"(__float_as_uint(b0)),"r"(__float_as_uint(b1)));
}

// ---------------- 1. checkerboard split ----------------
__global__ void split_kernel(const float* __restrict__ z){
    int idx = blockIdx.x*blockDim.x + threadIdx.x;
    if (idx >= BATCH*3*HWP) return;
    int j = idx & 31, i = (idx>>5) & 31;
    int c = (idx>>10) % 3;
    int b = idx / (3*HWP);
    const float* zb = z + ((long long)b*3 + c)*64*64;
    float p00 = zb[(2*i  )*64 + 2*j  ];
    float p01 = zb[(2*i  )*64 + 2*j+1];
    float p10 = zb[(2*i+1)*64 + 2*j  ];
    float p11 = zb[(2*i+1)*64 + 2*j+1];
    int base = ((b*C0C)+c)*HWP + i*32 + j;
    g_z0[base]          = p00;
    g_z0[base + 3*HWP]  = p11;
    g_z1[base]          = p01;
    g_z1[base + 3*HWP]  = p10;
}

// ---------------- 2. conv1 (6 -> 96), scalar ----------------
template<int CIN>
__global__ void conv3x3_kernel(const float* __restrict__ in, const float* __restrict__ w,
                               const float* __restrict__ bias, float* __restrict__ out, int Cout){
    __shared__ float tile[34*34];
    __shared__ float wsh[8][9];
    int b  = blockIdx.y;
    int co0= blockIdx.x*8;
    int tid= threadIdx.x;
    int y  = tid>>3;
    int x0 = (tid&7)*4;
    float acc[8][4];
    #pragma unroll
    for (int a=0;a<8;a++){ acc[a][0]=acc[a][1]=acc[a][2]=acc[a][3]=0.f; }
    const float* inb = in + (long long)b*CIN*HWP;
    for (int ci=0; ci<CIN; ci++){
        for (int idx=tid; idx<34*34; idx+=256){
            int ty=idx/34, tx=idx-ty*34;
            int yy=ty-1, xx=tx-1;
            tile[idx] = (yy>=0 && yy<32 && xx>=0 && xx<32) ? inb[ci*HWP + yy*32 + xx] : 0.f;
        }
        if (tid < 72){
            int co=tid/9, j=tid-co*9;
            wsh[co][j] = (co0+co < Cout) ? w[((long long)(co0+co)*CIN + ci)*9 + j] : 0.f;
        }
        __syncthreads();
        float v[3][6];
        #pragma unroll
        for (int r=0;r<3;r++)
            #pragma unroll
            for (int c=0;c<6;c++)
                v[r][c] = tile[(y+r)*34 + x0 + c];
        #pragma unroll
        for (int co=0;co<8;co++){
            #pragma unroll
            for (int p=0;p<4;p++){
                float s = acc[co][p];
                #pragma unroll
                for (int dy=0;dy<3;dy++)
                    #pragma unroll
                    for (int dx=0;dx<3;dx++)
                        s += v[dy][p+dx]*wsh[co][dy*3+dx];
                acc[co][p] = s;
            }
        }
        __syncthreads();
    }
    #pragma unroll
    for (int co=0;co<8;co++){
        if (co0+co < Cout){
            float bb = bias[co0+co];
            float4 r = make_float4(acc[co][0]+bb, acc[co][1]+bb, acc[co][2]+bb, acc[co][3]+bb);
            *(float4*)&out[((long long)b*Cout + co0+co)*HWP + y*32 + x0] = r;
        }
    }
}

// ---------------- 3. tf32 implicit-GEMM 3x3 conv (96-ch input) ----------------
#define WS_SZ   (9*8*72)
#define TILE_SZ (8*10*36)
#define SB_LD   258
template<bool GATE>
__global__ void conv_mma_kernel(const float* __restrict__ w, const float* __restrict__ bias,
                                const float* __restrict__ gam, const float* __restrict__ bet){
    extern __shared__ float sm[];
    float* ws   = sm;
    float* tile = sm + WS_SZ;

    int b   = blockIdx.z;
    int ct  = blockIdx.y;
    int r0  = blockIdx.x*8;
    int tid = threadIdx.x;
    int wp  = tid>>5, lane = tid&31;
    int gid = lane>>2, tig = lane&3;
    int mrow  = (wp&3)*16;
    int nhalf = wp>>2;

    const float* inb = (GATE ? g_x1 : g_x2) + (long long)b*FC*HWP;
    float mean=0.f, inv=0.f;
    if (!GATE){ mean = g_st2[2*b]; inv = g_st2[2*b+1]; }

    float c[16][4];
    #pragma unroll
    for (int j=0;j<16;j++){ c[j][0]=c[j][1]=c[j][2]=c[j][3]=0.f; }

    for (int chunk=0; chunk<12; chunk++){
        int ci0 = chunk*8;
        for (int i=tid; i<9*8*64; i+=256){
            int tap = i/(8*64); int rem = i - tap*8*64;
            int cil = rem>>6;    int r   = rem&63;
            int co;
            float v = 0.f;
            if (GATE){
                co = (r<32) ? (ct*32 + r) : (FC + ct*32 + (r-32));
                v = w[((long long)co*FC + ci0+cil)*9 + tap];
            } else {
                co = ct*64 + r;
                if (co < COUT2) v = w[((long long)co*FC + ci0+cil)*9 + tap];
            }
            ws[tap*576 + cil*72 + r] = cvt_tf32(v);
        }
        for (int i=tid; i<TILE_SZ; i+=256){
            int cil = i/360; int rem = i - cil*360;
            int ry = rem/36; int cx = rem - ry*36;
            float v = 0.f;
            int iy = r0-1+ry, ix = cx-1;
            if (cx<34 && iy>=0 && iy<32 && ix>=0 && ix<32){
                int pos = iy*32+ix;
                v = inb[(ci0+cil)*HWP + pos];
                if (!GATE) v = (v-mean)*inv*gam[(ci0+cil)*HWP+pos] + bet[(ci0+cil)*HWP+pos];
            }
            tile[i] = cvt_tf32(v);
        }
        __syncthreads();

        #pragma unroll
        for (int tap=0;tap<9;tap++){
            int dy = tap/3, dx = tap - dy*3;
            float a0 = ws[tap*576 + tig*72     + mrow+gid];
            float a1 = ws[tap*576 + tig*72     + mrow+gid+8];
            float a2 = ws[tap*576 + (tig+4)*72 + mrow+gid];
            float a3 = ws[tap*576 + (tig+4)*72 + mrow+gid+8];
            #pragma unroll
            for (int j=0;j<16;j++){
                int lr = nhalf*4 + (j>>2);
                int cg = (j&3)*8;
                float b0 = tile[tig*360     + (lr+dy)*36 + cg+gid+dx];
                float b1 = tile[(tig+4)*360 + (lr+dy)*36 + cg+gid+dx];
                mma_tf32(c[j], a0,a1,a2,a3, b0,b1);
            }
        }
        __syncthreads();
    }

    if (GATE){
        float* sbuf = sm;   // [64][SB_LD]
        #pragma unroll
        for (int j=0;j<16;j++){
            int lr = nhalf*4 + (j>>2);
            int cg = (j&3)*8;
            int n  = lr*32 + cg + 2*tig;
            *(float2*)&sbuf[(mrow+gid  )*SB_LD + n] = make_float2(c[j][0], c[j][1]);
            *(float2*)&sbuf[(mrow+gid+8)*SB_LD + n] = make_float2(c[j][2], c[j][3]);
        }
        __syncthreads();
        for (int i=tid; i<32*256; i+=256){
            int r = i>>8, n = i&255;
            float val = sbuf[r*SB_LD+n]      + bias[ct*32+r];
            float gat = sbuf[(r+32)*SB_LD+n] + bias[FC+ct*32+r];
            long long off = ((long long)b*FC + ct*32 + r)*HWP + r0*32 + n;
            g_xg[off] = g_x1[off] + val*sigf(gat);
        }
    } else {
        #pragma unroll
        for (int j=0;j<16;j++){
            int lr = nhalf*4 + (j>>2);
            int cg = (j&3)*8;
            int pos = (r0+lr)*32 + cg + 2*tig;
            int row0 = ct*64 + mrow + gid;
            int row1 = row0 + 8;
            if (row0 < COUT2){
                float bb = bias[row0];
                *(float2*)&g_par[((long long)b*COUT2 + row0)*HWP + pos] =
                    make_float2(c[j][0]+bb, c[j][1]+bb);
            }
            if (row1 < COUT2){
                float bb = bias[row1];
                *(float2*)&g_par[((long long)b*COUT2 + row1)*HWP + pos] =
                    make_float2(c[j][2]+bb, c[j][3]+bb);
            }
        }
    }
}

// ---------------- 4. LN stats only ----------------
__global__ void ln_stats_kernel(const float* __restrict__ x, float* __restrict__ st){
    const int N = FC*HWP;
    int b = blockIdx.x;
    const float4* xb = (const float4*)(x + (long long)b*N);
    float s=0.f, s2=0.f;
    for (int i=threadIdx.x;i<N/4;i+=blockDim.x){
        float4 v = xb[i];
        s  += v.x+v.y+v.z+v.w;
        s2 += v.x*v.x+v.y*v.y+v.z*v.z+v.w*v.w;
    }
    __shared__ float shs[32], shs2[32];
    int lane = threadIdx.x&31, wid = threadIdx.x>>5;
    s = warp_sum(s); s2 = warp_sum(s2);
    if (lane==0){ shs[wid]=s; shs2[wid]=s2; }
    __syncthreads();
    int nw = blockDim.x>>5;
    if (wid==0){
        float a = (lane<nw)? shs[lane]:0.f;
        float a2= (lane<nw)? shs2[lane]:0.f;
        a = warp_sum(a); a2 = warp_sum(a2);
        if (lane==0){
            float mean = a/(float)N;
            float var  = a2/(float)N - mean*mean;
            st[2*b]   = mean;
            st[2*b+1] = rsqrtf(var + 1e-5f);
        }
    }
}

// ---------------- 5a. ln1 apply + transpose to token-major ----------------
__global__ void ln1_transpose_kernel(const float* __restrict__ gam, const float* __restrict__ bet){
    __shared__ float t[32][33];
    int b  = blockIdx.z;
    int f0 = blockIdx.y*32;
    int p0 = blockIdx.x*32;
    float mean = g_st1[2*b], inv = g_st1[2*b+1];
    int tx = threadIdx.x&31, ty = threadIdx.x>>5;
    #pragma unroll
    for (int k=0;k<4;k++){
        int f = f0 + ty + 8*k;
        int col = p0 + tx;
        float v = g_xg[((long long)b*FC + f)*HWP + col];
        t[ty+8*k][tx] = (v-mean)*inv*gam[f*HWP + col] + bet[f*HWP + col];
    }
    __syncthreads();
    #pragma unroll
    for (int k=0;k<4;k++){
        int p = p0 + ty + 8*k;
        g_xf[((long long)b*SEQ + p)*FC + f0 + tx] = t[tx][ty+8*k];
    }
}

// ---------------- 5b. attn gate + transpose to channel-major ----------------
__global__ void gate_transpose_kernel(){
    __shared__ float t[32][33];
    int b  = blockIdx.z;
    int f0 = blockIdx.y*32;
    int p0 = blockIdx.x*32;
    int tx = threadIdx.x&31, ty = threadIdx.x>>5;
    #pragma unroll
    for (int k=0;k<4;k++){
        int p = p0 + ty + 8*k;
        long long base = ((long long)b*SEQ + p);
        float xv = g_xf[base*FC + f0 + tx];
        float ga = g_pr[base*2*FC + f0 + tx];
        float gb = g_pr[base*2*FC + FC + f0 + tx];
        t[ty+8*k][tx] = xv + ga*sigf(gb);
    }
    __syncthreads();
    #pragma unroll
    for (int k=0;k<4;k++){
        int f = f0 + ty + 8*k;
        g_x2[((long long)b*FC + f)*HWP + p0 + tx] = t[tx][ty+8*k];
    }
}

// ---------------- 6. tf32 MMA GEMM: C[m][n] = A[m][:96] . W[n][:96] + bias ----------------
// block 128 thr / 4 warps, tile M=64, N=96. N must be multiple of 96.
__global__ void gemm_tf32_kernel(const float* __restrict__ A, const float* __restrict__ W,
                                 float* __restrict__ C, int N, const float* __restrict__ bias){
    extern __shared__ float sm[];
    float* As = sm;              // [64][100]
    float* Ws = sm + 64*100;     // [96][100]
    int b  = blockIdx.z;
    int m0 = blockIdx.y*64;
    int n0 = blockIdx.x*96;
    A += (long long)b*SEQ*FC;
    C += (long long)b*SEQ*N;
    int tid = threadIdx.x, w = tid>>5, lane = tid&31;
    int gid = lane>>2, tig = lane&3;

    for (int i=tid; i<64*FC; i+=128){
        int m=i/FC, k=i-m*FC;
        As[m*100+k] = cvt_tf32(A[(long long)(m0+m)*FC + k]);
    }
    for (int i=tid; i<96*FC; i+=128){
        int n=i/FC, k=i-n*FC;
        Ws[n*100+k] = cvt_tf32(W[(long long)(n0+n)*FC + k]);
    }
    __syncthreads();

    float c[12][4];
    #pragma unroll
    for (int j=0;j<12;j++){ c[j][0]=c[j][1]=c[j][2]=c[j][3]=0.f; }
    #pragma unroll
    for (int kk=0;kk<12;kk++){
        int k0 = kk*8;
        float a0 = As[(16*w+gid  )*100 + k0+tig];
        float a1 = As[(16*w+gid+8)*100 + k0+tig];
        float a2 = As[(16*w+gid  )*100 + k0+tig+4];
        float a3 = As[(16*w+gid+8)*100 + k0+tig+4];
        #pragma unroll
        for (int j=0;j<12;j++){
            float b0 = Ws[(j*8+gid)*100 + k0+tig];
            float b1 = Ws[(j*8+gid)*100 + k0+tig+4];
            mma_tf32(c[j], a0,a1,a2,a3, b0,b1);
        }
    }

    #pragma unroll
    for (int j=0;j<12;j++){
        int n = n0 + j*8 + 2*tig;
        float b0 = bias[n], b1 = bias[n+1];
        int row0 = m0 + 16*w + gid;
        *(float2*)&C[(long long)row0*N + n]     = make_float2(c[j][0]+b0, c[j][1]+b1);
        *(float2*)&C[(long long)(row0+8)*N + n] = make_float2(c[j][2]+b0, c[j][3]+b1);
    }
}

// ---------------- 7. flash attention v2: Q tile 128, 256 thr, shuffle P ----------------
#define QLD 100
#define KLD 100
#define VLD 104
__global__ void __launch_bounds__(256,2) flash_tf32_kernel(){
    extern __shared__ float sm[];
    float* Qs = sm;                 // [128][QLD]
    float* Ks = Qs + 128*QLD;       // [64][KLD]
    float* Vs = Ks + 64*KLD;        // [64][VLD]

    int b   = blockIdx.y;
    int t0  = blockIdx.x*128;
    int tid = threadIdx.x;
    int w   = tid>>5, lane = tid&31;
    int gid = lane>>2, tig = lane&3;
    int qh  = tig>>1, rp = tig&1;
    int srcLo = gid*4 + qh, srcHi = srcLo + 2;
    const float scale = rsqrtf((float)FC);
    const float* qkvb = g_qkv + (long long)b*SEQ*3*FC;

    for (int i=tid;i<128*FC;i+=256){
        int m=i/FC, k=i-m*FC;
        Qs[m*QLD+k] = cvt_tf32(qkvb[(long long)(t0+m)*3*FC + k]*scale);
    }

    float O[12][4];
    #pragma unroll
    for (int j=0;j<12;j++){ O[j][0]=O[j][1]=O[j][2]=O[j][3]=0.f; }
    float mA=-1e30f, mB=-1e30f, lA=0.f, lB=0.f;
    __syncthreads();

    for (int it=0; it<16; it++){
        int kv0 = it*64;
        for (int i=tid;i<64*FC;i+=256){
            int n=i/FC, k=i-n*FC;
            Ks[n*KLD+k] = cvt_tf32(qkvb[(long long)(kv0+n)*3*FC + FC + k]);
        }
        for (int i=tid;i<64*FC;i+=256){
            int k=i/FC, n=i-k*FC;
            Vs[k*VLD+n] = cvt_tf32(qkvb[(long long)(kv0+k)*3*FC + 2*FC + n]);
        }
        __syncthreads();

        float c[8][4];
        #pragma unroll
        for (int j=0;j<8;j++){ c[j][0]=c[j][1]=c[j][2]=c[j][3]=0.f; }
        #pragma unroll
        for (int kk=0;kk<12;kk++){
            int k0=kk*8;
            float a0 = Qs[(16*w+gid  )*QLD + k0+tig];
            float a1 = Qs[(16*w+gid+8)*QLD + k0+tig];
            float a2 = Qs[(16*w+gid  )*QLD + k0+tig+4];
            float a3 = Qs[(16*w+gid+8)*QLD + k0+tig+4];
            #pragma unroll
            for (int j=0;j<8;j++){
                float b0 = Ks[(j*8+gid)*KLD + k0+tig];
                float b1 = Ks[(j*8+gid)*KLD + k0+tig+4];
                mma_tf32(c[j], a0,a1,a2,a3, b0,b1);
            }
        }

        // online softmax over this 64-col slab
        float mlA=-1e30f, mlB=-1e30f;
        #pragma unroll
        for (int j=0;j<8;j++){
            mlA = fmaxf(mlA, fmaxf(c[j][0],c[j][1]));
            mlB = fmaxf(mlB, fmaxf(c[j][2],c[j][3]));
        }
        mlA = fmaxf(mlA, __shfl_xor_sync(0xffffffffu, mlA, 1));
        mlA = fmaxf(mlA, __shfl_xor_sync(0xffffffffu, mlA, 2));
        mlB = fmaxf(mlB, __shfl_xor_sync(0xffffffffu, mlB, 1));
        mlB = fmaxf(mlB, __shfl_xor_sync(0xffffffffu, mlB, 2));
        float mnA = fmaxf(mA, mlA), mnB = fmaxf(mB, mlB);
        float alA = __expf(mA-mnA), alB = __expf(mB-mnB);
        float sA=0.f, sB=0.f;
        #pragma unroll
        for (int j=0;j<8;j++){
            c[j][0] = __expf(c[j][0]-mnA); sA += c[j][0];
            c[j][1] = __expf(c[j][1]-mnA); sA += c[j][1];
            c[j][2] = __expf(c[j][2]-mnB); sB += c[j][2];
            c[j][3] = __expf(c[j][3]-mnB); sB += c[j][3];
        }
        sA += __shfl_xor_sync(0xffffffffu, sA, 1);
        sA += __shfl_xor_sync(0xffffffffu, sA, 2);
        sB += __shfl_xor_sync(0xffffffffu, sB, 1);
        sB += __shfl_xor_sync(0xffffffffu, sB, 2);
        lA = lA*alA + sA; mA = mnA;
        lB = lB*alB + sB; mB = mnB;
        #pragma unroll
        for (int j=0;j<12;j++){
            O[j][0]*=alA; O[j][1]*=alA; O[j][2]*=alB; O[j][3]*=alB;
        }

        // O += P V : convert C-frag -> A-frag via intra-quad shuffles
        #pragma unroll
        for (int kk=0;kk<8;kk++){
            float v0 = __shfl_sync(0xffffffffu, c[kk][0], srcLo);
            float v1 = __shfl_sync(0xffffffffu, c[kk][1], srcLo);
            float v2 = __shfl_sync(0xffffffffu, c[kk][2], srcLo);
            float v3 = __shfl_sync(0xffffffffu, c[kk][3], srcLo);
            float w0 = __shfl_sync(0xffffffffu, c[kk][0], srcHi);
            float w1 = __shfl_sync(0xffffffffu, c[kk][1], srcHi);
            float w2 = __shfl_sync(0xffffffffu, c[kk][2], srcHi);
            float w3 = __shfl_sync(0xffffffffu, c[kk][3], srcHi);
            float a0 = cvt_tf32(rp ? v1 : v0);
            float a1 = cvt_tf32(rp ? v3 : v2);
            float a2 = cvt_tf32(rp ? w1 : w0);
            float a3 = cvt_tf32(rp ? w3 : w2);
            int k0 = kk*8;
            #pragma unroll
            for (int j=0;j<12;j++){
                float b0 = Vs[(k0+tig  )*VLD + j*8+gid];
                float b1 = Vs[(k0+tig+4)*VLD + j*8+gid];
                mma_tf32(O[j], a0,a1,a2,a3, b0,b1);
            }
        }
        __syncthreads();
    }

    float iA = 1.0f/lA, iB = 1.0f/lB;
    float* ob = g_o + ((long long)b*SEQ + t0)*FC;
    #pragma unroll
    for (int j=0;j<12;j++){
        int n = j*8 + 2*tig;
        *(float2*)&ob[(long long)(16*w+gid  )*FC + n] = make_float2(O[j][0]*iA, O[j][1]*iA);
        *(float2*)&ob[(long long)(16*w+gid+8)*FC + n] = make_float2(O[j][2]*iB, O[j][3]*iB);
    }
}

// ---------------- 9. logdet init ----------------
__global__ void init_log_kernel(const float* __restrict__ ldf, float* __restrict__ out_log){
    int b = threadIdx.x;
    if (b < BATCH) out_log[b] = ldf[b];
}

// ---------------- 10. mixture + logit + affine + merge ----------------
__global__ void mixture_kernel(const float* __restrict__ als, const float* __restrict__ ab,
                               float* __restrict__ out_z, float* __restrict__ out_log){
    int b  = blockIdx.x;
    int c0 = blockIdx.y;
    int p  = threadIdx.x;
    const float* P = g_par + (long long)b*COUT2*HWP;

    float aRaw = P[(long long)c0*HWP + p];
    float bRaw = P[(long long)(6+c0)*HWP + p];
    float lp[KMIX], mu[KMIX], ss[KMIX];
    #pragma unroll
    for (int k=0;k<KMIX;k++){
        lp[k] = P[(long long)(12 + k*C0C + c0)*HWP + p];
        mu[k] = P[(long long)(60 + k*C0C + c0)*HWP + p];
        ss[k] = P[(long long)(108+ k*C0C + c0)*HWP + p];
    }
    float a = tanhf(aRaw)*als[0] + ab[0];

    float mx = lp[0];
    #pragma unroll
    for (int k=1;k<KMIX;k++) mx = fmaxf(mx, lp[k]);
    float se = 0.f;
    #pragma unroll
    for (int k=0;k<KMIX;k++) se += __expf(lp[k]-mx);
    float lse = mx + __logf(se);

    float z0v = g_z0[((long long)b*C0C + c0)*HWP + p];
    float tvals[KMIX];
    float xsum = 0.f;
    #pragma unroll
    for (int k=0;k<KMIX;k++){
        float lpn = lp[k] - lse;
        float u   = (z0v - mu[k]) * __expf(-ss[k]);
        xsum += __expf(lpn) * sigf(u);
        tvals[k] = lpn - ss[k] + logsigf(u) + logsigf(-u);
    }
    float tm = tvals[0];
    #pragma unroll
    for (int k=1;k<KMIX;k++) tm = fmaxf(tm, tvals[k]);
    float tse = 0.f;
    #pragma unroll
    for (int k=0;k<KMIX;k++) tse += __expf(tvals[k]-tm);
    float logpdf = tm + __logf(tse);

    float x = fminf(fmaxf(xsum, 1e-6f), 1.0f-1e-6f);
    float lx  = __logf(x);
    float l1x = log1pf(-x);
    float z0n = (lx - l1x) * __expf(a) + bRaw;
    float contrib = logpdf + (-lx - l1x) + a;

    int i = p>>5, j = p&31;
    float z1v = g_z1[((long long)b*C0C + c0)*HWP + p];
    if (c0 < 3){
        float* ob = out_z + ((long long)b*3 + c0)*64*64;
        ob[(2*i)*64 + 2*j    ] = z0n;
        ob[(2*i)*64 + 2*j + 1] = z1v;
    } else {
        float* ob = out_z + ((long long)b*3 + (c0-3))*64*64;
        ob[(2*i+1)*64 + 2*j + 1] = z0n;
        ob[(2*i+1)*64 + 2*j    ] = z1v;
    }

    __shared__ float sh[32];
    int lane = p&31, wid = p>>5;
    float v = warp_sum(contrib);
    if (lane==0) sh[wid]=v;
    __syncthreads();
    if (wid==0){
        float w = (lane<32)? sh[lane] : 0.f;
        w = warp_sum(w);
        if (lane==0) atomicAdd(&out_log[b], w);
    }
}

// ---------------- host launcher ----------------
extern "C" void kernel_launch(void* const* d_in, const int* in_sizes, int n_in,
                              void* d_out, int out_size){
    const float* z        = (const float*)d_in[0];
    const float* log_df   = (const float*)d_in[1];
    const float* conv1_w  = (const float*)d_in[2];
    const float* conv1_b  = (const float*)d_in[3];
    const float* gconv_w  = (const float*)d_in[4];
    const float* gconv_b  = (const float*)d_in[5];
    const float* ln1_g    = (const float*)d_in[6];
    const float* ln1_b    = (const float*)d_in[7];
    const float* qkv_w    = (const float*)d_in[8];
    const float* qkv_b    = (const float*)d_in[9];
    const float* proj_w   = (const float*)d_in[10];
    const float* proj_b   = (const float*)d_in[11];
    const float* ln2_g    = (const float*)d_in[12];
    const float* ln2_b    = (const float*)d_in[13];
    const float* conv2_w  = (const float*)d_in[14];
    const float* conv2_b  = (const float*)d_in[15];
    const float* a_ls     = (const float*)d_in[16];
    const float* a_bias   = (const float*)d_in[17];

    float* out_z   = (float*)d_out;
    float* out_log = (float*)d_out + (long long)BATCH*3*64*64;

    float *p_z1, *p_x1, *p_xg, *p_xf, *p_qkv, *p_o, *p_x2, *p_st1, *p_st2, *p_pr;
    cudaGetSymbolAddress((void**)&p_z1,  g_z1);
    cudaGetSymbolAddress((void**)&p_x1,  g_x1);
    cudaGetSymbolAddress((void**)&p_xg,  g_xg);
    cudaGetSymbolAddress((void**)&p_xf,  g_xf);
    cudaGetSymbolAddress((void**)&p_qkv, g_qkv);
    cudaGetSymbolAddress((void**)&p_o,   g_o);
    cudaGetSymbolAddress((void**)&p_x2,  g_x2);
    cudaGetSymbolAddress((void**)&p_st1, g_st1);
    cudaGetSymbolAddress((void**)&p_st2, g_st2);
    cudaGetSymbolAddress((void**)&p_pr,  g_pr);

    const int FLASH_SMEM = (128*QLD + 64*KLD + 64*VLD)*4;
    const int GCONV_SMEM = 64*SB_LD*4;
    const int CONV2_SMEM = (WS_SZ + TILE_SZ)*4;
    const int GEMM_SMEM  = (64*100 + 96*100)*4;
    static int smem_set = 0;
    if (!smem_set){
        cudaFuncSetAttribute(flash_tf32_kernel, cudaFuncAttributeMaxDynamicSharedMemorySize, FLASH_SMEM);
        cudaFuncSetAttribute(conv_mma_kernel<true>,  cudaFuncAttributeMaxDynamicSharedMemorySize, GCONV_SMEM);
        cudaFuncSetAttribute(conv_mma_kernel<false>, cudaFuncAttributeMaxDynamicSharedMemorySize, CONV2_SMEM);
        cudaFuncSetAttribute(gemm_tf32_kernel, cudaFuncAttributeMaxDynamicSharedMemorySize, GEMM_SMEM);
        smem_set = 1;
    }

    split_kernel<<<(BATCH*3*HWP+255)/256, 256>>>(z);
    conv3x3_kernel<6><<<dim3(12, BATCH), 256>>>(p_z1, conv1_w, conv1_b, p_x1, FC);
    conv_mma_kernel<true><<<dim3(4, 3, BATCH), 256, GCONV_SMEM>>>(gconv_w, gconv_b, nullptr, nullptr);
    ln_stats_kernel<<<BATCH, 1024>>>(p_xg, p_st1);
    ln1_transpose_kernel<<<dim3(32, 3, BATCH), 256>>>(ln1_g, ln1_b);
    gemm_tf32_kernel<<<dim3(3, 16, BATCH), 128, GEMM_SMEM>>>(p_xf, qkv_w, p_qkv, 3*FC, qkv_b);
    flash_tf32_kernel<<<dim3(8, BATCH), 256, FLASH_SMEM>>>();
    gemm_tf32_kernel<<<dim3(2, 16, BATCH), 128, GEMM_SMEM>>>(p_o, proj_w, p_pr, 2*FC, proj_b);
    gate_transpose_kernel<<<dim3(32, 3, BATCH), 256>>>();
    ln_stats_kernel<<<BATCH, 1024>>>(p_x2, p_st2);
    conv_mma_kernel<false><<<dim3(4, 3, BATCH), 256, CONV2_SMEM>>>(conv2_w, conv2_b, ln2_g, ln2_b);
    init_log_kernel<<<1, 64>>>(log_df, out_log);
    mixture_kernel<<<dim3(BATCH, C0C), 1024>>>(a_ls, a_bias, out_z, out_log);
}

// round 9
// speedup vs baseline: 3.9941x; 1.2847x over previous
#include <cuda_runtime.h>
#include <math.h>
#include <stdint.h>

// ---------------- problem constants ----------------
#define BATCH 64
#define C0C   6
#define FC    96
#define KMIX  8
#define HWP   1024
#define SEQ   1024
#define COUT2 156

// ---------------- scratch ----------------
__device__ float g_z0 [BATCH*C0C*HWP];
__device__ float g_z1 [BATCH*C0C*HWP];
__device__ float g_x1 [BATCH*FC*HWP];
__device__ float g_x1t[BATCH*FC*HWP];      // tf32-rounded conv1 out (gconv MMA input)
__device__ float g_xg [BATCH*FC*HWP];
__device__ float g_xf [BATCH*SEQ*FC];
__device__ float g_qkv[BATCH*SEQ*3*FC];
__device__ float g_o  [BATCH*SEQ*FC];
__device__ float g_pr [BATCH*SEQ*2*FC];
__device__ float g_x2 [BATCH*FC*HWP];
__device__ float g_par[BATCH*COUT2*HWP];
__device__ float g_st2[BATCH*2];
__device__ float g_st1[BATCH*2];
__device__ float g_wt1[3*12*4608];         // gconv weights, tf32, smem layout
__device__ float g_wt2[3*12*4608];         // conv2 weights

// ---------------- helpers ----------------
__device__ __forceinline__ float warp_sum(float v){
    #pragma unroll
    for (int o=16;o;o>>=1) v += __shfl_xor_sync(0xffffffffu, v, o);
    return v;
}
__device__ __forceinline__ float sigf(float v){ return 1.0f/(1.0f+__expf(-v)); }
__device__ __forceinline__ float logsigf(float v){ return fminf(v,0.0f) - log1pf(__expf(-fabsf(v))); }
__device__ __forceinline__ float cvt_tf32(float x){
    uint32_t r; asm("cvt.rna.tf32.f32 %0, %1;" : "=r"(r) : "f"(x)); return __uint_as_float(r);
}
__device__ __forceinline__ void mma_tf32(float* c, float a0,float a1,float a2,float a3,
                                         float b0,float b1){
    asm volatile("mma.sync.aligned.m16n8k8.row.col.f32.tf32.tf32.f32 "
        "{%0,%1,%2,%3}, {%4,%5,%6,%7}, {%8,%9}, {%0,%1,%2,%3};\n"
        : "+f"(c[0]),"+f"(c[1]),"+f"(c[2]),"+f"(c[3])
        : "r"(__float_as_uint(a0)),"r"(__float_as_uint(a1)),
          "r"(__float_as_uint(a2)),"r"(__float_as_uint(a3)),
          "r"(__float_as_uint(b0)),"r"(__float_as_uint(b1)));
}
__device__ __forceinline__ void cp16(uint32_t dst, const float* src){
    asm volatile("cp.async.cg.shared.global [%0], [%1], 16;\n" :: "r"(dst), "l"(src));
}
__device__ __forceinline__ void cp4z(uint32_t dst, const float* src, bool valid){
    int sz = valid ? 4 : 0;
    asm volatile("cp.async.ca.shared.global [%0], [%1], 4, %2;\n" :: "r"(dst), "l"(src), "r"(sz));
}
#define CPCOMMIT() asm volatile("cp.async.commit_group;\n")
#define CPWAIT(n)  asm volatile("cp.async.wait_group %0;\n"::"n"(n))

// ---------------- 1. checkerboard split ----------------
__global__ void split_kernel(const float* __restrict__ z){
    int idx = blockIdx.x*blockDim.x + threadIdx.x;
    if (idx >= BATCH*3*HWP) return;
    int j = idx & 31, i = (idx>>5) & 31;
    int c = (idx>>10) % 3;
    int b = idx / (3*HWP);
    const float* zb = z + ((long long)b*3 + c)*64*64;
    float p00 = zb[(2*i  )*64 + 2*j  ];
    float p01 = zb[(2*i  )*64 + 2*j+1];
    float p10 = zb[(2*i+1)*64 + 2*j  ];
    float p11 = zb[(2*i+1)*64 + 2*j+1];
    int base = ((b*C0C)+c)*HWP + i*32 + j;
    g_z0[base]          = p00;
    g_z0[base + 3*HWP]  = p11;
    g_z1[base]          = p01;
    g_z1[base + 3*HWP]  = p10;
}

// ---------------- 2. conv1 (6 -> 96), scalar; writes fp32 + tf32 copies ----------------
__global__ void conv1_kernel(const float* __restrict__ in, const float* __restrict__ w,
                             const float* __restrict__ bias){
    __shared__ float tile[34*34];
    __shared__ float wsh[8][9];
    int b  = blockIdx.y;
    int co0= blockIdx.x*8;
    int tid= threadIdx.x;
    int y  = tid>>3;
    int x0 = (tid&7)*4;
    float acc[8][4];
    #pragma unroll
    for (int a=0;a<8;a++){ acc[a][0]=acc[a][1]=acc[a][2]=acc[a][3]=0.f; }
    const float* inb = in + (long long)b*6*HWP;
    for (int ci=0; ci<6; ci++){
        for (int idx=tid; idx<34*34; idx+=256){
            int ty=idx/34, tx=idx-ty*34;
            int yy=ty-1, xx=tx-1;
            tile[idx] = (yy>=0 && yy<32 && xx>=0 && xx<32) ? inb[ci*HWP + yy*32 + xx] : 0.f;
        }
        if (tid < 72){
            int co=tid/9, j=tid-co*9;
            wsh[co][j] = w[((long long)(co0+co)*6 + ci)*9 + j];
        }
        __syncthreads();
        float v[3][6];
        #pragma unroll
        for (int r=0;r<3;r++)
            #pragma unroll
            for (int c=0;c<6;c++)
                v[r][c] = tile[(y+r)*34 + x0 + c];
        #pragma unroll
        for (int co=0;co<8;co++){
            #pragma unroll
            for (int p=0;p<4;p++){
                float s = acc[co][p];
                #pragma unroll
                for (int dy=0;dy<3;dy++)
                    #pragma unroll
                    for (int dx=0;dx<3;dx++)
                        s += v[dy][p+dx]*wsh[co][dy*3+dx];
                acc[co][p] = s;
            }
        }
        __syncthreads();
    }
    #pragma unroll
    for (int co=0;co<8;co++){
        float bb = bias[co0+co];
        long long off = ((long long)b*FC + co0+co)*HWP + y*32 + x0;
        float4 r = make_float4(acc[co][0]+bb, acc[co][1]+bb, acc[co][2]+bb, acc[co][3]+bb);
        *(float4*)&g_x1[off] = r;
        float4 rt = make_float4(cvt_tf32(r.x), cvt_tf32(r.y), cvt_tf32(r.z), cvt_tf32(r.w));
        *(float4*)&g_x1t[off] = rt;
    }
}

// ---------------- 2b. weight precompute into smem layout ----------------
template<bool GATE>
__global__ void wprep_kernel(const float* __restrict__ w, float* __restrict__ out){
    int i = blockIdx.x*256 + threadIdx.x;
    if (i >= 3*12*4608) return;
    int ct = i/(12*4608); int rem = i - ct*12*4608;
    int chunk = rem/4608;  int r2 = rem - chunk*4608;
    int tap = r2>>9; int j = r2&511; int cil = j>>6; int r = j&63;
    int ci = chunk*8 + cil;
    float v = 0.f;
    if (GATE){
        int co = (r<32) ? (ct*32+r) : (FC + ct*32 + (r-32));
        v = w[((long long)co*FC + ci)*9 + tap];
    } else {
        int co = ct*64 + r;
        if (co < COUT2) v = w[((long long)co*FC + ci)*9 + tap];
    }
    out[i] = cvt_tf32(v);
}

// ---------------- 3. tf32 implicit-GEMM 3x3 conv, cp.async double-buffered ----------------
#define WS_CH 5184      // 9*576 (72-stride rows, 64 payload)
#define TL_CH 2880      // 8*10*36
#define SB_LD 258
template<bool GATE>
__global__ void conv_mma_kernel(const float* __restrict__ wt, const float* __restrict__ bias){
    extern __shared__ float sm[];
    float* wsb[2] = { sm,            sm + WS_CH };
    float* tlb[2] = { sm + 2*WS_CH,  sm + 2*WS_CH + TL_CH };
    uint32_t ws_u32[2], tl_u32[2];
    ws_u32[0] = (uint32_t)__cvta_generic_to_shared(wsb[0]);
    ws_u32[1] = (uint32_t)__cvta_generic_to_shared(wsb[1]);
    tl_u32[0] = (uint32_t)__cvta_generic_to_shared(tlb[0]);
    tl_u32[1] = (uint32_t)__cvta_generic_to_shared(tlb[1]);

    int b   = blockIdx.z;
    int ct  = blockIdx.y;
    int r0  = blockIdx.x*8;
    int tid = threadIdx.x;
    int wp  = tid>>5, lane = tid&31;
    int gid = lane>>2, tig = lane&3;
    int mrow  = (wp&3)*16;
    int nhalf = wp>>2;

    const float* inb  = (GATE ? g_x1t : g_x2) + (long long)b*FC*HWP;
    const float* wsrc = wt + (long long)ct*12*4608;

    auto load_chunk = [&](int chunk, int p){
        const float* wc = wsrc + chunk*4608;
        for (int i=tid; i<1152; i+=256){
            int tap=i>>7, rem=i&127, cil=rem>>4, v=rem&15;
            cp16(ws_u32[p] + (tap*576 + cil*72 + v*4)*4, wc + tap*512 + cil*64 + v*4);
        }
        int ci0 = chunk*8;
        for (int i=tid; i<TL_CH; i+=256){
            int cil = i/360; int rem = i - cil*360;
            int ry = rem/36; int cx = rem - ry*36;
            int iy = r0-1+ry, ix = cx-1;
            bool valid = (cx<34) && (iy>=0) && (iy<32) && (ix>=0) && (ix<32);
            const float* src = inb + (ci0+cil)*HWP + (valid ? iy*32+ix : 0);
            cp4z(tl_u32[p] + i*4, src, valid);
        }
    };

    float c[16][4];
    #pragma unroll
    for (int j=0;j<16;j++){ c[j][0]=c[j][1]=c[j][2]=c[j][3]=0.f; }

    load_chunk(0, 0); CPCOMMIT();
    for (int chunk=0; chunk<12; chunk++){
        int p = chunk&1;
        if (chunk<11){ load_chunk(chunk+1, p^1); CPCOMMIT(); CPWAIT(1); }
        else         { CPWAIT(0); }
        __syncthreads();
        float* ws   = wsb[p];
        float* tile = tlb[p];
        #pragma unroll
        for (int tap=0;tap<9;tap++){
            int dy = tap/3, dx = tap - dy*3;
            float a0 = ws[tap*576 + tig*72     + mrow+gid];
            float a1 = ws[tap*576 + tig*72     + mrow+gid+8];
            float a2 = ws[tap*576 + (tig+4)*72 + mrow+gid];
            float a3 = ws[tap*576 + (tig+4)*72 + mrow+gid+8];
            #pragma unroll
            for (int j=0;j<16;j++){
                int lr = nhalf*4 + (j>>2);
                int cg = (j&3)*8;
                float b0 = tile[tig*360     + (lr+dy)*36 + cg+gid+dx];
                float b1 = tile[(tig+4)*360 + (lr+dy)*36 + cg+gid+dx];
                mma_tf32(c[j], a0,a1,a2,a3, b0,b1);
            }
        }
        __syncthreads();
    }

    if (GATE){
        float* sbuf = sm;   // [64][SB_LD]
        #pragma unroll
        for (int j=0;j<16;j++){
            int lr = nhalf*4 + (j>>2);
            int cg = (j&3)*8;
            int n  = lr*32 + cg + 2*tig;
            *(float2*)&sbuf[(mrow+gid  )*SB_LD + n] = make_float2(c[j][0], c[j][1]);
            *(float2*)&sbuf[(mrow+gid+8)*SB_LD + n] = make_float2(c[j][2], c[j][3]);
        }
        __syncthreads();
        for (int i=tid; i<32*256; i+=256){
            int r = i>>8, n = i&255;
            float val = sbuf[r*SB_LD+n]      + bias[ct*32+r];
            float gat = sbuf[(r+32)*SB_LD+n] + bias[FC+ct*32+r];
            long long off = ((long long)b*FC + ct*32 + r)*HWP + r0*32 + n;
            g_xg[off] = g_x1[off] + val*sigf(gat);
        }
    } else {
        #pragma unroll
        for (int j=0;j<16;j++){
            int lr = nhalf*4 + (j>>2);
            int cg = (j&3)*8;
            int pos = (r0+lr)*32 + cg + 2*tig;
            int row0 = ct*64 + mrow + gid;
            int row1 = row0 + 8;
            if (row0 < COUT2){
                float bb = bias[row0];
                *(float2*)&g_par[((long long)b*COUT2 + row0)*HWP + pos] =
                    make_float2(c[j][0]+bb, c[j][1]+bb);
            }
            if (row1 < COUT2){
                float bb = bias[row1];
                *(float2*)&g_par[((long long)b*COUT2 + row1)*HWP + pos] =
                    make_float2(c[j][2]+bb, c[j][3]+bb);
            }
        }
    }
}

// ---------------- 4. LN stats only ----------------
__global__ void ln_stats_kernel(const float* __restrict__ x, float* __restrict__ st){
    const int N = FC*HWP;
    int b = blockIdx.x;
    const float4* xb = (const float4*)(x + (long long)b*N);
    float s=0.f, s2=0.f;
    for (int i=threadIdx.x;i<N/4;i+=blockDim.x){
        float4 v = xb[i];
        s  += v.x+v.y+v.z+v.w;
        s2 += v.x*v.x+v.y*v.y+v.z*v.z+v.w*v.w;
    }
    __shared__ float shs[32], shs2[32];
    int lane = threadIdx.x&31, wid = threadIdx.x>>5;
    s = warp_sum(s); s2 = warp_sum(s2);
    if (lane==0){ shs[wid]=s; shs2[wid]=s2; }
    __syncthreads();
    int nw = blockDim.x>>5;
    if (wid==0){
        float a = (lane<nw)? shs[lane]:0.f;
        float a2= (lane<nw)? shs2[lane]:0.f;
        a = warp_sum(a); a2 = warp_sum(a2);
        if (lane==0){
            float mean = a/(float)N;
            float var  = a2/(float)N - mean*mean;
            st[2*b]   = mean;
            st[2*b+1] = rsqrtf(var + 1e-5f);
        }
    }
}

// ---------------- 4b. LN2 apply in place (tf32-rounded) ----------------
__global__ void ln_apply_kernel(const float* __restrict__ gam, const float* __restrict__ bet){
    int i = blockIdx.x*256 + threadIdx.x;
    const int PER_B = FC*HWP/4;
    if (i >= BATCH*PER_B) return;
    int r = i % PER_B; int b = i / PER_B;
    float mean = g_st2[2*b], inv = g_st2[2*b+1];
    float4 v  = ((float4*)g_x2)[(long long)b*PER_B + r];
    float4 g  = ((const float4*)gam)[r];
    float4 be = ((const float4*)bet)[r];
    v.x = cvt_tf32((v.x-mean)*inv*g.x + be.x);
    v.y = cvt_tf32((v.y-mean)*inv*g.y + be.y);
    v.z = cvt_tf32((v.z-mean)*inv*g.z + be.z);
    v.w = cvt_tf32((v.w-mean)*inv*g.w + be.w);
    ((float4*)g_x2)[(long long)b*PER_B + r] = v;
}

// ---------------- 5a. ln1 apply + transpose to token-major ----------------
__global__ void ln1_transpose_kernel(const float* __restrict__ gam, const float* __restrict__ bet){
    __shared__ float t[32][33];
    int b  = blockIdx.z;
    int f0 = blockIdx.y*32;
    int p0 = blockIdx.x*32;
    float mean = g_st1[2*b], inv = g_st1[2*b+1];
    int tx = threadIdx.x&31, ty = threadIdx.x>>5;
    #pragma unroll
    for (int k=0;k<4;k++){
        int f = f0 + ty + 8*k;
        int col = p0 + tx;
        float v = g_xg[((long long)b*FC + f)*HWP + col];
        t[ty+8*k][tx] = (v-mean)*inv*gam[f*HWP + col] + bet[f*HWP + col];
    }
    __syncthreads();
    #pragma unroll
    for (int k=0;k<4;k++){
        int p = p0 + ty + 8*k;
        g_xf[((long long)b*SEQ + p)*FC + f0 + tx] = t[tx][ty+8*k];
    }
}

// ---------------- 5b. attn gate + transpose to channel-major ----------------
__global__ void gate_transpose_kernel(){
    __shared__ float t[32][33];
    int b  = blockIdx.z;
    int f0 = blockIdx.y*32;
    int p0 = blockIdx.x*32;
    int tx = threadIdx.x&31, ty = threadIdx.x>>5;
    #pragma unroll
    for (int k=0;k<4;k++){
        int p = p0 + ty + 8*k;
        long long base = ((long long)b*SEQ + p);
        float xv = g_xf[base*FC + f0 + tx];
        float ga = g_pr[base*2*FC + f0 + tx];
        float gb = g_pr[base*2*FC + FC + f0 + tx];
        t[ty+8*k][tx] = xv + ga*sigf(gb);
    }
    __syncthreads();
    #pragma unroll
    for (int k=0;k<4;k++){
        int f = f0 + ty + 8*k;
        g_x2[((long long)b*FC + f)*HWP + p0 + tx] = t[tx][ty+8*k];
    }
}

// ---------------- 6. tf32 MMA GEMM ----------------
__global__ void gemm_tf32_kernel(const float* __restrict__ A, const float* __restrict__ W,
                                 float* __restrict__ C, int N, const float* __restrict__ bias){
    extern __shared__ float sm[];
    float* As = sm;              // [64][100]
    float* Ws = sm + 64*100;     // [96][100]
    int b  = blockIdx.z;
    int m0 = blockIdx.y*64;
    int n0 = blockIdx.x*96;
    A += (long long)b*SEQ*FC;
    C += (long long)b*SEQ*N;
    int tid = threadIdx.x, w = tid>>5, lane = tid&31;
    int gid = lane>>2, tig = lane&3;

    for (int i=tid; i<64*FC; i+=128){
        int m=i/FC, k=i-m*FC;
        As[m*100+k] = cvt_tf32(A[(long long)(m0+m)*FC + k]);
    }
    for (int i=tid; i<96*FC; i+=128){
        int n=i/FC, k=i-n*FC;
        Ws[n*100+k] = cvt_tf32(W[(long long)(n0+n)*FC + k]);
    }
    __syncthreads();

    float c[12][4];
    #pragma unroll
    for (int j=0;j<12;j++){ c[j][0]=c[j][1]=c[j][2]=c[j][3]=0.f; }
    #pragma unroll
    for (int kk=0;kk<12;kk++){
        int k0 = kk*8;
        float a0 = As[(16*w+gid  )*100 + k0+tig];
        float a1 = As[(16*w+gid+8)*100 + k0+tig];
        float a2 = As[(16*w+gid  )*100 + k0+tig+4];
        float a3 = As[(16*w+gid+8)*100 + k0+tig+4];
        #pragma unroll
        for (int j=0;j<12;j++){
            float b0 = Ws[(j*8+gid)*100 + k0+tig];
            float b1 = Ws[(j*8+gid)*100 + k0+tig+4];
            mma_tf32(c[j], a0,a1,a2,a3, b0,b1);
        }
    }

    #pragma unroll
    for (int j=0;j<12;j++){
        int n = n0 + j*8 + 2*tig;
        float b0 = bias[n], b1 = bias[n+1];
        int row0 = m0 + 16*w + gid;
        *(float2*)&C[(long long)row0*N + n]     = make_float2(c[j][0]+b0, c[j][1]+b1);
        *(float2*)&C[(long long)(row0+8)*N + n] = make_float2(c[j][2]+b0, c[j][3]+b1);
    }
}

// ---------------- 7. flash attention v2 ----------------
#define QLD 100
#define KLD 100
#define VLD 104
__global__ void __launch_bounds__(256,2) flash_tf32_kernel(){
    extern __shared__ float sm[];
    float* Qs = sm;                 // [128][QLD]
    float* Ks = Qs + 128*QLD;       // [64][KLD]
    float* Vs = Ks + 64*KLD;        // [64][VLD]

    int b   = blockIdx.y;
    int t0  = blockIdx.x*128;
    int tid = threadIdx.x;
    int w   = tid>>5, lane = tid&31;
    int gid = lane>>2, tig = lane&3;
    int qh  = tig>>1, rp = tig&1;
    int srcLo = gid*4 + qh, srcHi = srcLo + 2;
    const float scale = rsqrtf((float)FC);
    const float* qkvb = g_qkv + (long long)b*SEQ*3*FC;

    for (int i=tid;i<128*FC;i+=256){
        int m=i/FC, k=i-m*FC;
        Qs[m*QLD+k] = cvt_tf32(qkvb[(long long)(t0+m)*3*FC + k]*scale);
    }

    float O[12][4];
    #pragma unroll
    for (int j=0;j<12;j++){ O[j][0]=O[j][1]=O[j][2]=O[j][3]=0.f; }
    float mA=-1e30f, mB=-1e30f, lA=0.f, lB=0.f;
    __syncthreads();

    for (int it=0; it<16; it++){
        int kv0 = it*64;
        for (int i=tid;i<64*FC;i+=256){
            int n=i/FC, k=i-n*FC;
            Ks[n*KLD+k] = cvt_tf32(qkvb[(long long)(kv0+n)*3*FC + FC + k]);
        }
        for (int i=tid;i<64*FC;i+=256){
            int k=i/FC, n=i-k*FC;
            Vs[k*VLD+n] = cvt_tf32(qkvb[(long long)(kv0+k)*3*FC + 2*FC + n]);
        }
        __syncthreads();

        float c[8][4];
        #pragma unroll
        for (int j=0;j<8;j++){ c[j][0]=c[j][1]=c[j][2]=c[j][3]=0.f; }
        #pragma unroll
        for (int kk=0;kk<12;kk++){
            int k0=kk*8;
            float a0 = Qs[(16*w+gid  )*QLD + k0+tig];
            float a1 = Qs[(16*w+gid+8)*QLD + k0+tig];
            float a2 = Qs[(16*w+gid  )*QLD + k0+tig+4];
            float a3 = Qs[(16*w+gid+8)*QLD + k0+tig+4];
            #pragma unroll
            for (int j=0;j<8;j++){
                float b0 = Ks[(j*8+gid)*KLD + k0+tig];
                float b1 = Ks[(j*8+gid)*KLD + k0+tig+4];
                mma_tf32(c[j], a0,a1,a2,a3, b0,b1);
            }
        }

        float mlA=-1e30f, mlB=-1e30f;
        #pragma unroll
        for (int j=0;j<8;j++){
            mlA = fmaxf(mlA, fmaxf(c[j][0],c[j][1]));
            mlB = fmaxf(mlB, fmaxf(c[j][2],c[j][3]));
        }
        mlA = fmaxf(mlA, __shfl_xor_sync(0xffffffffu, mlA, 1));
        mlA = fmaxf(mlA, __shfl_xor_sync(0xffffffffu, mlA, 2));
        mlB = fmaxf(mlB, __shfl_xor_sync(0xffffffffu, mlB, 1));
        mlB = fmaxf(mlB, __shfl_xor_sync(0xffffffffu, mlB, 2));
        float mnA = fmaxf(mA, mlA), mnB = fmaxf(mB, mlB);
        float alA = __expf(mA-mnA), alB = __expf(mB-mnB);
        float sA=0.f, sB=0.f;
        #pragma unroll
        for (int j=0;j<8;j++){
            c[j][0] = __expf(c[j][0]-mnA); sA += c[j][0];
            c[j][1] = __expf(c[j][1]-mnA); sA += c[j][1];
            c[j][2] = __expf(c[j][2]-mnB); sB += c[j][2];
            c[j][3] = __expf(c[j][3]-mnB); sB += c[j][3];
        }
        sA += __shfl_xor_sync(0xffffffffu, sA, 1);
        sA += __shfl_xor_sync(0xffffffffu, sA, 2);
        sB += __shfl_xor_sync(0xffffffffu, sB, 1);
        sB += __shfl_xor_sync(0xffffffffu, sB, 2);
        lA = lA*alA + sA; mA = mnA;
        lB = lB*alB + sB; mB = mnB;
        #pragma unroll
        for (int j=0;j<12;j++){
            O[j][0]*=alA; O[j][1]*=alA; O[j][2]*=alB; O[j][3]*=alB;
        }

        #pragma unroll
        for (int kk=0;kk<8;kk++){
            float v0 = __shfl_sync(0xffffffffu, c[kk][0], srcLo);
            float v1 = __shfl_sync(0xffffffffu, c[kk][1], srcLo);
            float v2 = __shfl_sync(0xffffffffu, c[kk][2], srcLo);
            float v3 = __shfl_sync(0xffffffffu, c[kk][3], srcLo);
            float w0 = __shfl_sync(0xffffffffu, c[kk][0], srcHi);
            float w1 = __shfl_sync(0xffffffffu, c[kk][1], srcHi);
            float w2 = __shfl_sync(0xffffffffu, c[kk][2], srcHi);
            float w3 = __shfl_sync(0xffffffffu, c[kk][3], srcHi);
            float a0 = cvt_tf32(rp ? v1 : v0);
            float a1 = cvt_tf32(rp ? v3 : v2);
            float a2 = cvt_tf32(rp ? w1 : w0);
            float a3 = cvt_tf32(rp ? w3 : w2);
            int k0 = kk*8;
            #pragma unroll
            for (int j=0;j<12;j++){
                float b0 = Vs[(k0+tig  )*VLD + j*8+gid];
                float b1 = Vs[(k0+tig+4)*VLD + j*8+gid];
                mma_tf32(O[j], a0,a1,a2,a3, b0,b1);
            }
        }
        __syncthreads();
    }

    float iA = 1.0f/lA, iB = 1.0f/lB;
    float* ob = g_o + ((long long)b*SEQ + t0)*FC;
    #pragma unroll
    for (int j=0;j<12;j++){
        int n = j*8 + 2*tig;
        *(float2*)&ob[(long long)(16*w+gid  )*FC + n] = make_float2(O[j][0]*iA, O[j][1]*iA);
        *(float2*)&ob[(long long)(16*w+gid+8)*FC + n] = make_float2(O[j][2]*iB, O[j][3]*iB);
    }
}

// ---------------- 9. logdet init ----------------
__global__ void init_log_kernel(const float* __restrict__ ldf, float* __restrict__ out_log){
    int b = threadIdx.x;
    if (b < BATCH) out_log[b] = ldf[b];
}

// ---------------- 10. mixture + logit + affine + merge ----------------
__global__ void mixture_kernel(const float* __restrict__ als, const float* __restrict__ ab,
                               float* __restrict__ out_z, float* __restrict__ out_log){
    int b  = blockIdx.x;
    int c0 = blockIdx.y;
    int p  = threadIdx.x;
    const float* P = g_par + (long long)b*COUT2*HWP;

    float aRaw = P[(long long)c0*HWP + p];
    float bRaw = P[(long long)(6+c0)*HWP + p];
    float lp[KMIX], mu[KMIX], ss[KMIX];
    #pragma unroll
    for (int k=0;k<KMIX;k++){
        lp[k] = P[(long long)(12 + k*C0C + c0)*HWP + p];
        mu[k] = P[(long long)(60 + k*C0C + c0)*HWP + p];
        ss[k] = P[(long long)(108+ k*C0C + c0)*HWP + p];
    }
    float a = tanhf(aRaw)*als[0] + ab[0];

    float mx = lp[0];
    #pragma unroll
    for (int k=1;k<KMIX;k++) mx = fmaxf(mx, lp[k]);
    float se = 0.f;
    #pragma unroll
    for (int k=0;k<KMIX;k++) se += __expf(lp[k]-mx);
    float lse = mx + __logf(se);

    float z0v = g_z0[((long long)b*C0C + c0)*HWP + p];
    float tvals[KMIX];
    float xsum = 0.f;
    #pragma unroll
    for (int k=0;k<KMIX;k++){
        float lpn = lp[k] - lse;
        float u   = (z0v - mu[k]) * __expf(-ss[k]);
        xsum += __expf(lpn) * sigf(u);
        tvals[k] = lpn - ss[k] + logsigf(u) + logsigf(-u);
    }
    float tm = tvals[0];
    #pragma unroll
    for (int k=1;k<KMIX;k++) tm = fmaxf(tm, tvals[k]);
    float tse = 0.f;
    #pragma unroll
    for (int k=0;k<KMIX;k++) tse += __expf(tvals[k]-tm);
    float logpdf = tm + __logf(tse);

    float x = fminf(fmaxf(xsum, 1e-6f), 1.0f-1e-6f);
    float lx  = __logf(x);
    float l1x = log1pf(-x);
    float z0n = (lx - l1x) * __expf(a) + bRaw;
    float contrib = logpdf + (-lx - l1x) + a;

    int i = p>>5, j = p&31;
    float z1v = g_z1[((long long)b*C0C + c0)*HWP + p];
    if (c0 < 3){
        float* ob = out_z + ((long long)b*3 + c0)*64*64;
        ob[(2*i)*64 + 2*j    ] = z0n;
        ob[(2*i)*64 + 2*j + 1] = z1v;
    } else {
        float* ob = out_z + ((long long)b*3 + (c0-3))*64*64;
        ob[(2*i+1)*64 + 2*j + 1] = z0n;
        ob[(2*i+1)*64 + 2*j    ] = z1v;
    }

    __shared__ float sh[32];
    int lane = p&31, wid = p>>5;
    float v = warp_sum(contrib);
    if (lane==0) sh[wid]=v;
    __syncthreads();
    if (wid==0){
        float w = (lane<32)? sh[lane] : 0.f;
        w = warp_sum(w);
        if (lane==0) atomicAdd(&out_log[b], w);
    }
}

// ---------------- host launcher ----------------
extern "C" void kernel_launch(void* const* d_in, const int* in_sizes, int n_in,
                              void* d_out, int out_size){
    const float* z        = (const float*)d_in[0];
    const float* log_df   = (const float*)d_in[1];
    const float* conv1_w  = (const float*)d_in[2];
    const float* conv1_b  = (const float*)d_in[3];
    const float* gconv_w  = (const float*)d_in[4];
    const float* gconv_b  = (const float*)d_in[5];
    const float* ln1_g    = (const float*)d_in[6];
    const float* ln1_b    = (const float*)d_in[7];
    const float* qkv_w    = (const float*)d_in[8];
    const float* qkv_b    = (const float*)d_in[9];
    const float* proj_w   = (const float*)d_in[10];
    const float* proj_b   = (const float*)d_in[11];
    const float* ln2_g    = (const float*)d_in[12];
    const float* ln2_b    = (const float*)d_in[13];
    const float* conv2_w  = (const float*)d_in[14];
    const float* conv2_b  = (const float*)d_in[15];
    const float* a_ls     = (const float*)d_in[16];
    const float* a_bias   = (const float*)d_in[17];

    float* out_z   = (float*)d_out;
    float* out_log = (float*)d_out + (long long)BATCH*3*64*64;

    float *p_z1, *p_xg, *p_xf, *p_qkv, *p_o, *p_x2, *p_st1, *p_st2, *p_pr, *p_wt1, *p_wt2;
    cudaGetSymbolAddress((void**)&p_z1,  g_z1);
    cudaGetSymbolAddress((void**)&p_xg,  g_xg);
    cudaGetSymbolAddress((void**)&p_xf,  g_xf);
    cudaGetSymbolAddress((void**)&p_qkv, g_qkv);
    cudaGetSymbolAddress((void**)&p_o,   g_o);
    cudaGetSymbolAddress((void**)&p_x2,  g_x2);
    cudaGetSymbolAddress((void**)&p_st1, g_st1);
    cudaGetSymbolAddress((void**)&p_st2, g_st2);
    cudaGetSymbolAddress((void**)&p_pr,  g_pr);
    cudaGetSymbolAddress((void**)&p_wt1, g_wt1);
    cudaGetSymbolAddress((void**)&p_wt2, g_wt2);

    const int FLASH_SMEM = (128*QLD + 64*KLD + 64*VLD)*4;
    const int GCONV_SMEM = (64*SB_LD > 2*(WS_CH+TL_CH) ? 64*SB_LD : 2*(WS_CH+TL_CH))*4;
    const int CONV2_SMEM = 2*(WS_CH+TL_CH)*4;
    const int GEMM_SMEM  = (64*100 + 96*100)*4;
    static int smem_set = 0;
    if (!smem_set){
        cudaFuncSetAttribute(flash_tf32_kernel, cudaFuncAttributeMaxDynamicSharedMemorySize, FLASH_SMEM);
        cudaFuncSetAttribute(conv_mma_kernel<true>,  cudaFuncAttributeMaxDynamicSharedMemorySize, GCONV_SMEM);
        cudaFuncSetAttribute(conv_mma_kernel<false>, cudaFuncAttributeMaxDynamicSharedMemorySize, CONV2_SMEM);
        cudaFuncSetAttribute(gemm_tf32_kernel, cudaFuncAttributeMaxDynamicSharedMemorySize, GEMM_SMEM);
        smem_set = 1;
    }

    const int WPREP_BLOCKS = (3*12*4608 + 255)/256;
    wprep_kernel<true><<<WPREP_BLOCKS, 256>>>(gconv_w, p_wt1);
    wprep_kernel<false><<<WPREP_BLOCKS, 256>>>(conv2_w, p_wt2);
    split_kernel<<<(BATCH*3*HWP+255)/256, 256>>>(z);
    conv1_kernel<<<dim3(12, BATCH), 256>>>(p_z1, conv1_w, conv1_b);
    conv_mma_kernel<true><<<dim3(4, 3, BATCH), 256, GCONV_SMEM>>>(p_wt1, gconv_b);
    ln_stats_kernel<<<BATCH, 1024>>>(p_xg, p_st1);
    ln1_transpose_kernel<<<dim3(32, 3, BATCH), 256>>>(ln1_g, ln1_b);
    gemm_tf32_kernel<<<dim3(3, 16, BATCH), 128, GEMM_SMEM>>>(p_xf, qkv_w, p_qkv, 3*FC, qkv_b);
    flash_tf32_kernel<<<dim3(8, BATCH), 256, FLASH_SMEM>>>();
    gemm_tf32_kernel<<<dim3(2, 16, BATCH), 128, GEMM_SMEM>>>(p_o, proj_w, p_pr, 2*FC, proj_b);
    gate_transpose_kernel<<<dim3(32, 3, BATCH), 256>>>();
    ln_stats_kernel<<<BATCH, 1024>>>(p_x2, p_st2);
    ln_apply_kernel<<<(BATCH*FC*HWP/4 + 255)/256, 256>>>(ln2_g, ln2_b);
    conv_mma_kernel<false><<<dim3(4, 3, BATCH), 256, CONV2_SMEM>>>(p_wt2, conv2_b);
    init_log_kernel<<<1, 64>>>(log_df, out_log);
    mixture_kernel<<<dim3(BATCH, C0C), 1024>>>(a_ls, a_bias, out_z, out_log);
}

// round 10
// speedup vs baseline: 4.0721x; 1.0195x over previous
#include <cuda_runtime.h>
#include <math.h>
#include <stdint.h>

// ---------------- problem constants ----------------
#define BATCH 64
#define C0C   6
#define FC    96
#define KMIX  8
#define HWP   1024
#define SEQ   1024
#define COUT2 156

// ---------------- scratch ----------------
__device__ float g_z0 [BATCH*C0C*HWP];
__device__ float g_z1 [BATCH*C0C*HWP];
__device__ float g_x1 [BATCH*FC*HWP];
__device__ float g_x1t[BATCH*FC*HWP];
__device__ float g_xg [BATCH*FC*HWP];
__device__ float g_xf [BATCH*SEQ*FC];
__device__ float g_qkv[BATCH*SEQ*3*FC];
__device__ float g_o  [BATCH*SEQ*FC];
__device__ float g_pr [BATCH*SEQ*2*FC];
__device__ float g_x2 [BATCH*FC*HWP];
__device__ float g_par[BATCH*COUT2*HWP];
__device__ float g_st2[BATCH*2];
__device__ float g_st1[BATCH*2];
__device__ float g_sum1[BATCH*2];          // raw LN1 sums (s, s2)
__device__ float g_sum2[BATCH*2];          // raw LN2 sums
__device__ float g_wt1[3*12*4608];
__device__ float g_wt2[3*12*4608];

// ---------------- helpers ----------------
__device__ __forceinline__ float warp_sum(float v){
    #pragma unroll
    for (int o=16;o;o>>=1) v += __shfl_xor_sync(0xffffffffu, v, o);
    return v;
}
__device__ __forceinline__ float sigf(float v){ return 1.0f/(1.0f+__expf(-v)); }
__device__ __forceinline__ float logsigf(float v){ return fminf(v,0.0f) - log1pf(__expf(-fabsf(v))); }
__device__ __forceinline__ float cvt_tf32(float x){
    uint32_t r; asm("cvt.rna.tf32.f32 %0, %1;" : "=r"(r) : "f"(x)); return __uint_as_float(r);
}
__device__ __forceinline__ void mma_tf32(float* c, float a0,float a1,float a2,float a3,
                                         float b0,float b1){
    asm volatile("mma.sync.aligned.m16n8k8.row.col.f32.tf32.tf32.f32 "
        "{%0,%1,%2,%3}, {%4,%5,%6,%7}, {%8,%9}, {%0,%1,%2,%3};\n"
        : "+f"(c[0]),"+f"(c[1]),"+f"(c[2]),"+f"(c[3])
        : "r"(__float_as_uint(a0)),"r"(__float_as_uint(a1)),
          "r"(__float_as_uint(a2)),"r"(__float_as_uint(a3)),
          "r"(__float_as_uint(b0)),"r"(__float_as_uint(b1)));
}
__device__ __forceinline__ void cp16(uint32_t dst, const float* src){
    asm volatile("cp.async.cg.shared.global [%0], [%1], 16;\n" :: "r"(dst), "l"(src));
}
__device__ __forceinline__ void cp4z(uint32_t dst, const float* src, bool valid){
    int sz = valid ? 4 : 0;
    asm volatile("cp.async.ca.shared.global [%0], [%1], 4, %2;\n" :: "r"(dst), "l"(src), "r"(sz));
}
#define CPCOMMIT() asm volatile("cp.async.commit_group;\n")
#define CPWAIT(n)  asm volatile("cp.async.wait_group %0;\n"::"n"(n))

// block-reduce (s,s2) and atomicAdd into sums[2b],[2b+1]
__device__ __forceinline__ void block_stats_add(float s, float s2, float* sums, int b,
                                                float* red){
    int lane = threadIdx.x&31, wid = threadIdx.x>>5;
    s = warp_sum(s); s2 = warp_sum(s2);
    if (lane==0){ red[wid]=s; red[wid+32]=s2; }
    __syncthreads();
    int nw = blockDim.x>>5;
    if (wid==0){
        float a  = (lane<nw)? red[lane]    : 0.f;
        float a2 = (lane<nw)? red[lane+32] : 0.f;
        a = warp_sum(a); a2 = warp_sum(a2);
        if (lane==0){
            atomicAdd(&sums[2*b],   a);
            atomicAdd(&sums[2*b+1], a2);
        }
    }
}

// ---------------- 0. zero LN accumulators ----------------
__global__ void zero_sums_kernel(){
    int i = threadIdx.x;
    if (i < BATCH*2){ g_sum1[i] = 0.f; g_sum2[i] = 0.f; }
}
__global__ void ln_finalize_kernel(const float* __restrict__ sums, float* __restrict__ st){
    int b = threadIdx.x;
    if (b < BATCH){
        const float N = (float)(FC*HWP);
        float mean = sums[2*b]/N;
        float var  = sums[2*b+1]/N - mean*mean;
        st[2*b]   = mean;
        st[2*b+1] = rsqrtf(var + 1e-5f);
    }
}

// ---------------- 1. checkerboard split ----------------
__global__ void split_kernel(const float* __restrict__ z){
    int idx = blockIdx.x*blockDim.x + threadIdx.x;
    if (idx >= BATCH*3*HWP) return;
    int j = idx & 31, i = (idx>>5) & 31;
    int c = (idx>>10) % 3;
    int b = idx / (3*HWP);
    const float* zb = z + ((long long)b*3 + c)*64*64;
    float p00 = zb[(2*i  )*64 + 2*j  ];
    float p01 = zb[(2*i  )*64 + 2*j+1];
    float p10 = zb[(2*i+1)*64 + 2*j  ];
    float p11 = zb[(2*i+1)*64 + 2*j+1];
    int base = ((b*C0C)+c)*HWP + i*32 + j;
    g_z0[base]          = p00;
    g_z0[base + 3*HWP]  = p11;
    g_z1[base]          = p01;
    g_z1[base + 3*HWP]  = p10;
}

// ---------------- 2. conv1 (6 -> 96): single-stage smem, one sync ----------------
__global__ void conv1_kernel(const float* __restrict__ in, const float* __restrict__ w,
                             const float* __restrict__ bias){
    __shared__ float tile[6][34*34];
    __shared__ float wsh[8][6][9];
    int b  = blockIdx.y;
    int co0= blockIdx.x*8;
    int tid= threadIdx.x;
    int y  = tid>>3;
    int x0 = (tid&7)*4;
    const float* inb = in + (long long)b*6*HWP;
    for (int idx=tid; idx<6*34*34; idx+=256){
        int ci = idx/1156; int r = idx - ci*1156;
        int ty = r/34, tx = r - ty*34;
        int yy=ty-1, xx=tx-1;
        tile[ci][r] = (yy>=0 && yy<32 && xx>=0 && xx<32) ? inb[ci*HWP + yy*32 + xx] : 0.f;
    }
    for (int idx=tid; idx<8*6*9; idx+=256){
        int co = idx/54; int r = idx - co*54;
        int ci = r/9, j = r - ci*9;
        wsh[co][ci][j] = w[((long long)(co0+co)*6 + ci)*9 + j];
    }
    __syncthreads();

    float acc[8][4];
    #pragma unroll
    for (int a=0;a<8;a++){ acc[a][0]=acc[a][1]=acc[a][2]=acc[a][3]=0.f; }
    #pragma unroll
    for (int ci=0; ci<6; ci++){
        float v[3][6];
        #pragma unroll
        for (int r=0;r<3;r++)
            #pragma unroll
            for (int c=0;c<6;c++)
                v[r][c] = tile[ci][(y+r)*34 + x0 + c];
        #pragma unroll
        for (int co=0;co<8;co++){
            #pragma unroll
            for (int p=0;p<4;p++){
                float s = acc[co][p];
                #pragma unroll
                for (int dy=0;dy<3;dy++)
                    #pragma unroll
                    for (int dx=0;dx<3;dx++)
                        s += v[dy][p+dx]*wsh[co][ci][dy*3+dx];
                acc[co][p] = s;
            }
        }
    }
    #pragma unroll
    for (int co=0;co<8;co++){
        float bb = bias[co0+co];
        long long off = ((long long)b*FC + co0+co)*HWP + y*32 + x0;
        float4 r = make_float4(acc[co][0]+bb, acc[co][1]+bb, acc[co][2]+bb, acc[co][3]+bb);
        *(float4*)&g_x1[off] = r;
        float4 rt = make_float4(cvt_tf32(r.x), cvt_tf32(r.y), cvt_tf32(r.z), cvt_tf32(r.w));
        *(float4*)&g_x1t[off] = rt;
    }
}

// ---------------- 2b. weight precompute into smem layout ----------------
template<bool GATE>
__global__ void wprep_kernel(const float* __restrict__ w, float* __restrict__ out){
    int i = blockIdx.x*256 + threadIdx.x;
    if (i >= 3*12*4608) return;
    int ct = i/(12*4608); int rem = i - ct*12*4608;
    int chunk = rem/4608;  int r2 = rem - chunk*4608;
    int tap = r2>>9; int j = r2&511; int cil = j>>6; int r = j&63;
    int ci = chunk*8 + cil;
    float v = 0.f;
    if (GATE){
        int co = (r<32) ? (ct*32+r) : (FC + ct*32 + (r-32));
        v = w[((long long)co*FC + ci)*9 + tap];
    } else {
        int co = ct*64 + r;
        if (co < COUT2) v = w[((long long)co*FC + ci)*9 + tap];
    }
    out[i] = cvt_tf32(v);
}

// ---------------- 3. tf32 implicit-GEMM 3x3 conv, cp.async double-buffered ----------------
#define WS_CH 5184
#define TL_CH 2880
#define SB_LD 258
template<bool GATE>
__global__ void conv_mma_kernel(const float* __restrict__ wt, const float* __restrict__ bias){
    extern __shared__ float sm[];
    __shared__ float red[64];
    float* wsb[2] = { sm,            sm + WS_CH };
    float* tlb[2] = { sm + 2*WS_CH,  sm + 2*WS_CH + TL_CH };
    uint32_t ws_u32[2], tl_u32[2];
    ws_u32[0] = (uint32_t)__cvta_generic_to_shared(wsb[0]);
    ws_u32[1] = (uint32_t)__cvta_generic_to_shared(wsb[1]);
    tl_u32[0] = (uint32_t)__cvta_generic_to_shared(tlb[0]);
    tl_u32[1] = (uint32_t)__cvta_generic_to_shared(tlb[1]);

    int b   = blockIdx.z;
    int ct  = blockIdx.y;
    int r0  = blockIdx.x*8;
    int tid = threadIdx.x;
    int wp  = tid>>5, lane = tid&31;
    int gid = lane>>2, tig = lane&3;
    int mrow  = (wp&3)*16;
    int nhalf = wp>>2;

    const float* inb  = (GATE ? g_x1t : g_x2) + (long long)b*FC*HWP;
    const float* wsrc = wt + (long long)ct*12*4608;

    auto load_chunk = [&](int chunk, int p){
        const float* wc = wsrc + chunk*4608;
        for (int i=tid; i<1152; i+=256){
            int tap=i>>7, rem=i&127, cil=rem>>4, v=rem&15;
            cp16(ws_u32[p] + (tap*576 + cil*72 + v*4)*4, wc + tap*512 + cil*64 + v*4);
        }
        int ci0 = chunk*8;
        for (int i=tid; i<TL_CH; i+=256){
            int cil = i/360; int rem = i - cil*360;
            int ry = rem/36; int cx = rem - ry*36;
            int iy = r0-1+ry, ix = cx-1;
            bool valid = (cx<34) && (iy>=0) && (iy<32) && (ix>=0) && (ix<32);
            const float* src = inb + (ci0+cil)*HWP + (valid ? iy*32+ix : 0);
            cp4z(tl_u32[p] + i*4, src, valid);
        }
    };

    float c[16][4];
    #pragma unroll
    for (int j=0;j<16;j++){ c[j][0]=c[j][1]=c[j][2]=c[j][3]=0.f; }

    load_chunk(0, 0); CPCOMMIT();
    for (int chunk=0; chunk<12; chunk++){
        int p = chunk&1;
        if (chunk<11){ load_chunk(chunk+1, p^1); CPCOMMIT(); CPWAIT(1); }
        else         { CPWAIT(0); }
        __syncthreads();
        float* ws   = wsb[p];
        float* tile = tlb[p];
        #pragma unroll
        for (int tap=0;tap<9;tap++){
            int dy = tap/3, dx = tap - dy*3;
            float a0 = ws[tap*576 + tig*72     + mrow+gid];
            float a1 = ws[tap*576 + tig*72     + mrow+gid+8];
            float a2 = ws[tap*576 + (tig+4)*72 + mrow+gid];
            float a3 = ws[tap*576 + (tig+4)*72 + mrow+gid+8];
            #pragma unroll
            for (int j=0;j<16;j++){
                int lr = nhalf*4 + (j>>2);
                int cg = (j&3)*8;
                float b0 = tile[tig*360     + (lr+dy)*36 + cg+gid+dx];
                float b1 = tile[(tig+4)*360 + (lr+dy)*36 + cg+gid+dx];
                mma_tf32(c[j], a0,a1,a2,a3, b0,b1);
            }
        }
        __syncthreads();
    }

    if (GATE){
        float* sbuf = sm;   // [64][SB_LD]
        #pragma unroll
        for (int j=0;j<16;j++){
            int lr = nhalf*4 + (j>>2);
            int cg = (j&3)*8;
            int n  = lr*32 + cg + 2*tig;
            *(float2*)&sbuf[(mrow+gid  )*SB_LD + n] = make_float2(c[j][0], c[j][1]);
            *(float2*)&sbuf[(mrow+gid+8)*SB_LD + n] = make_float2(c[j][2], c[j][3]);
        }
        __syncthreads();
        float s=0.f, s2=0.f;
        for (int i=tid; i<32*256; i+=256){
            int r = i>>8, n = i&255;
            float val = sbuf[r*SB_LD+n]      + bias[ct*32+r];
            float gat = sbuf[(r+32)*SB_LD+n] + bias[FC+ct*32+r];
            long long off = ((long long)b*FC + ct*32 + r)*HWP + r0*32 + n;
            float o = g_x1[off] + val*sigf(gat);
            g_xg[off] = o;
            s += o; s2 += o*o;
        }
        __syncthreads();
        block_stats_add(s, s2, g_sum1, b, red);
    } else {
        #pragma unroll
        for (int j=0;j<16;j++){
            int lr = nhalf*4 + (j>>2);
            int cg = (j&3)*8;
            int pos = (r0+lr)*32 + cg + 2*tig;
            int row0 = ct*64 + mrow + gid;
            int row1 = row0 + 8;
            if (row0 < COUT2){
                float bb = bias[row0];
                *(float2*)&g_par[((long long)b*COUT2 + row0)*HWP + pos] =
                    make_float2(c[j][0]+bb, c[j][1]+bb);
            }
            if (row1 < COUT2){
                float bb = bias[row1];
                *(float2*)&g_par[((long long)b*COUT2 + row1)*HWP + pos] =
                    make_float2(c[j][2]+bb, c[j][3]+bb);
            }
        }
    }
}

// ---------------- 4b. LN2 apply in place (tf32-rounded) ----------------
__global__ void ln_apply_kernel(const float* __restrict__ gam, const float* __restrict__ bet){
    int i = blockIdx.x*256 + threadIdx.x;
    const int PER_B = FC*HWP/4;
    if (i >= BATCH*PER_B) return;
    int r = i % PER_B; int b = i / PER_B;
    float mean = g_st2[2*b], inv = g_st2[2*b+1];
    float4 v  = ((float4*)g_x2)[(long long)b*PER_B + r];
    float4 g  = ((const float4*)gam)[r];
    float4 be = ((const float4*)bet)[r];
    v.x = cvt_tf32((v.x-mean)*inv*g.x + be.x);
    v.y = cvt_tf32((v.y-mean)*inv*g.y + be.y);
    v.z = cvt_tf32((v.z-mean)*inv*g.z + be.z);
    v.w = cvt_tf32((v.w-mean)*inv*g.w + be.w);
    ((float4*)g_x2)[(long long)b*PER_B + r] = v;
}

// ---------------- 5a. ln1 apply + transpose to token-major ----------------
__global__ void ln1_transpose_kernel(const float* __restrict__ gam, const float* __restrict__ bet){
    __shared__ float t[32][33];
    int b  = blockIdx.z;
    int f0 = blockIdx.y*32;
    int p0 = blockIdx.x*32;
    float mean = g_st1[2*b], inv = g_st1[2*b+1];
    int tx = threadIdx.x&31, ty = threadIdx.x>>5;
    #pragma unroll
    for (int k=0;k<4;k++){
        int f = f0 + ty + 8*k;
        int col = p0 + tx;
        float v = g_xg[((long long)b*FC + f)*HWP + col];
        t[ty+8*k][tx] = (v-mean)*inv*gam[f*HWP + col] + bet[f*HWP + col];
    }
    __syncthreads();
    #pragma unroll
    for (int k=0;k<4;k++){
        int p = p0 + ty + 8*k;
        g_xf[((long long)b*SEQ + p)*FC + f0 + tx] = t[tx][ty+8*k];
    }
}

// ---------------- 5b. attn gate + transpose + LN2 stats ----------------
__global__ void gate_transpose_kernel(){
    __shared__ float t[32][33];
    __shared__ float red[64];
    int b  = blockIdx.z;
    int f0 = blockIdx.y*32;
    int p0 = blockIdx.x*32;
    int tx = threadIdx.x&31, ty = threadIdx.x>>5;
    float s=0.f, s2=0.f;
    #pragma unroll
    for (int k=0;k<4;k++){
        int p = p0 + ty + 8*k;
        long long base = ((long long)b*SEQ + p);
        float xv = g_xf[base*FC + f0 + tx];
        float ga = g_pr[base*2*FC + f0 + tx];
        float gb = g_pr[base*2*FC + FC + f0 + tx];
        float o = xv + ga*sigf(gb);
        t[ty+8*k][tx] = o;
        s += o; s2 += o*o;
    }
    __syncthreads();
    #pragma unroll
    for (int k=0;k<4;k++){
        int f = f0 + ty + 8*k;
        g_x2[((long long)b*FC + f)*HWP + p0 + tx] = t[tx][ty+8*k];
    }
    __syncthreads();
    block_stats_add(s, s2, g_sum2, b, red);
}

// ---------------- 6. tf32 MMA GEMM ----------------
__global__ void gemm_tf32_kernel(const float* __restrict__ A, const float* __restrict__ W,
                                 float* __restrict__ C, int N, const float* __restrict__ bias){
    extern __shared__ float sm[];
    float* As = sm;              // [64][100]
    float* Ws = sm + 64*100;     // [96][100]
    int b  = blockIdx.z;
    int m0 = blockIdx.y*64;
    int n0 = blockIdx.x*96;
    A += (long long)b*SEQ*FC;
    C += (long long)b*SEQ*N;
    int tid = threadIdx.x, w = tid>>5, lane = tid&31;
    int gid = lane>>2, tig = lane&3;

    for (int i=tid; i<64*FC; i+=128){
        int m=i/FC, k=i-m*FC;
        As[m*100+k] = cvt_tf32(A[(long long)(m0+m)*FC + k]);
    }
    for (int i=tid; i<96*FC; i+=128){
        int n=i/FC, k=i-n*FC;
        Ws[n*100+k] = cvt_tf32(W[(long long)(n0+n)*FC + k]);
    }
    __syncthreads();

    float c[12][4];
    #pragma unroll
    for (int j=0;j<12;j++){ c[j][0]=c[j][1]=c[j][2]=c[j][3]=0.f; }
    #pragma unroll
    for (int kk=0;kk<12;kk++){
        int k0 = kk*8;
        float a0 = As[(16*w+gid  )*100 + k0+tig];
        float a1 = As[(16*w+gid+8)*100 + k0+tig];
        float a2 = As[(16*w+gid  )*100 + k0+tig+4];
        float a3 = As[(16*w+gid+8)*100 + k0+tig+4];
        #pragma unroll
        for (int j=0;j<12;j++){
            float b0 = Ws[(j*8+gid)*100 + k0+tig];
            float b1 = Ws[(j*8+gid)*100 + k0+tig+4];
            mma_tf32(c[j], a0,a1,a2,a3, b0,b1);
        }
    }

    #pragma unroll
    for (int j=0;j<12;j++){
        int n = n0 + j*8 + 2*tig;
        float b0 = bias[n], b1 = bias[n+1];
        int row0 = m0 + 16*w + gid;
        *(float2*)&C[(long long)row0*N + n]     = make_float2(c[j][0]+b0, c[j][1]+b1);
        *(float2*)&C[(long long)(row0+8)*N + n] = make_float2(c[j][2]+b0, c[j][3]+b1);
    }
}

// ---------------- 7. flash attention v2 ----------------
#define QLD 100
#define KLD 100
#define VLD 104
__global__ void __launch_bounds__(256,2) flash_tf32_kernel(){
    extern __shared__ float sm[];
    float* Qs = sm;                 // [128][QLD]
    float* Ks = Qs + 128*QLD;       // [64][KLD]
    float* Vs = Ks + 64*KLD;        // [64][VLD]

    int b   = blockIdx.y;
    int t0  = blockIdx.x*128;
    int tid = threadIdx.x;
    int w   = tid>>5, lane = tid&31;
    int gid = lane>>2, tig = lane&3;
    int qh  = tig>>1, rp = tig&1;
    int srcLo = gid*4 + qh, srcHi = srcLo + 2;
    const float scale = rsqrtf((float)FC);
    const float* qkvb = g_qkv + (long long)b*SEQ*3*FC;

    for (int i=tid;i<128*FC;i+=256){
        int m=i/FC, k=i-m*FC;
        Qs[m*QLD+k] = cvt_tf32(qkvb[(long long)(t0+m)*3*FC + k]*scale);
    }

    float O[12][4];
    #pragma unroll
    for (int j=0;j<12;j++){ O[j][0]=O[j][1]=O[j][2]=O[j][3]=0.f; }
    float mA=-1e30f, mB=-1e30f, lA=0.f, lB=0.f;
    __syncthreads();

    for (int it=0; it<16; it++){
        int kv0 = it*64;
        for (int i=tid;i<64*FC;i+=256){
            int n=i/FC, k=i-n*FC;
            Ks[n*KLD+k] = cvt_tf32(qkvb[(long long)(kv0+n)*3*FC + FC + k]);
        }
        for (int i=tid;i<64*FC;i+=256){
            int k=i/FC, n=i-k*FC;
            Vs[k*VLD+n] = cvt_tf32(qkvb[(long long)(kv0+k)*3*FC + 2*FC + n]);
        }
        __syncthreads();

        float c[8][4];
        #pragma unroll
        for (int j=0;j<8;j++){ c[j][0]=c[j][1]=c[j][2]=c[j][3]=0.f; }
        #pragma unroll
        for (int kk=0;kk<12;kk++){
            int k0=kk*8;
            float a0 = Qs[(16*w+gid  )*QLD + k0+tig];
            float a1 = Qs[(16*w+gid+8)*QLD + k0+tig];
            float a2 = Qs[(16*w+gid  )*QLD + k0+tig+4];
            float a3 = Qs[(16*w+gid+8)*QLD + k0+tig+4];
            #pragma unroll
            for (int j=0;j<8;j++){
                float b0 = Ks[(j*8+gid)*KLD + k0+tig];
                float b1 = Ks[(j*8+gid)*KLD + k0+tig+4];
                mma_tf32(c[j], a0,a1,a2,a3, b0,b1);
            }
        }

        float mlA=-1e30f, mlB=-1e30f;
        #pragma unroll
        for (int j=0;j<8;j++){
            mlA = fmaxf(mlA, fmaxf(c[j][0],c[j][1]));
            mlB = fmaxf(mlB, fmaxf(c[j][2],c[j][3]));
        }
        mlA = fmaxf(mlA, __shfl_xor_sync(0xffffffffu, mlA, 1));
        mlA = fmaxf(mlA, __shfl_xor_sync(0xffffffffu, mlA, 2));
        mlB = fmaxf(mlB, __shfl_xor_sync(0xffffffffu, mlB, 1));
        mlB = fmaxf(mlB, __shfl_xor_sync(0xffffffffu, mlB, 2));
        float mnA = fmaxf(mA, mlA), mnB = fmaxf(mB, mlB);
        float alA = __expf(mA-mnA), alB = __expf(mB-mnB);
        float sA=0.f, sB=0.f;
        #pragma unroll
        for (int j=0;j<8;j++){
            c[j][0] = __expf(c[j][0]-mnA); sA += c[j][0];
            c[j][1] = __expf(c[j][1]-mnA); sA += c[j][1];
            c[j][2] = __expf(c[j][2]-mnB); sB += c[j][2];
            c[j][3] = __expf(c[j][3]-mnB); sB += c[j][3];
        }
        sA += __shfl_xor_sync(0xffffffffu, sA, 1);
        sA += __shfl_xor_sync(0xffffffffu, sA, 2);
        sB += __shfl_xor_sync(0xffffffffu, sB, 1);
        sB += __shfl_xor_sync(0xffffffffu, sB, 2);
        lA = lA*alA + sA; mA = mnA;
        lB = lB*alB + sB; mB = mnB;
        #pragma unroll
        for (int j=0;j<12;j++){
            O[j][0]*=alA; O[j][1]*=alA; O[j][2]*=alB; O[j][3]*=alB;
        }

        #pragma unroll
        for (int kk=0;kk<8;kk++){
            float v0 = __shfl_sync(0xffffffffu, c[kk][0], srcLo);
            float v1 = __shfl_sync(0xffffffffu, c[kk][1], srcLo);
            float v2 = __shfl_sync(0xffffffffu, c[kk][2], srcLo);
            float v3 = __shfl_sync(0xffffffffu, c[kk][3], srcLo);
            float w0 = __shfl_sync(0xffffffffu, c[kk][0], srcHi);
            float w1 = __shfl_sync(0xffffffffu, c[kk][1], srcHi);
            float w2 = __shfl_sync(0xffffffffu, c[kk][2], srcHi);
            float w3 = __shfl_sync(0xffffffffu, c[kk][3], srcHi);
            float a0 = cvt_tf32(rp ? v1 : v0);
            float a1 = cvt_tf32(rp ? v3 : v2);
            float a2 = cvt_tf32(rp ? w1 : w0);
            float a3 = cvt_tf32(rp ? w3 : w2);
            int k0 = kk*8;
            #pragma unroll
            for (int j=0;j<12;j++){
                float b0 = Vs[(k0+tig  )*VLD + j*8+gid];
                float b1 = Vs[(k0+tig+4)*VLD + j*8+gid];
                mma_tf32(O[j], a0,a1,a2,a3, b0,b1);
            }
        }
        __syncthreads();
    }

    float iA = 1.0f/lA, iB = 1.0f/lB;
    float* ob = g_o + ((long long)b*SEQ + t0)*FC;
    #pragma unroll
    for (int j=0;j<12;j++){
        int n = j*8 + 2*tig;
        *(float2*)&ob[(long long)(16*w+gid  )*FC + n] = make_float2(O[j][0]*iA, O[j][1]*iA);
        *(float2*)&ob[(long long)(16*w+gid+8)*FC + n] = make_float2(O[j][2]*iB, O[j][3]*iB);
    }
}

// ---------------- 9. logdet init ----------------
__global__ void init_log_kernel(const float* __restrict__ ldf, float* __restrict__ out_log){
    int b = threadIdx.x;
    if (b < BATCH) out_log[b] = ldf[b];
}

// ---------------- 10. mixture + logit + affine + merge ----------------
__global__ void mixture_kernel(const float* __restrict__ als, const float* __restrict__ ab,
                               float* __restrict__ out_z, float* __restrict__ out_log){
    int b  = blockIdx.x;
    int c0 = blockIdx.y;
    int p  = threadIdx.x;
    const float* P = g_par + (long long)b*COUT2*HWP;

    float aRaw = P[(long long)c0*HWP + p];
    float bRaw = P[(long long)(6+c0)*HWP + p];
    float lp[KMIX], mu[KMIX], ss[KMIX];
    #pragma unroll
    for (int k=0;k<KMIX;k++){
        lp[k] = P[(long long)(12 + k*C0C + c0)*HWP + p];
        mu[k] = P[(long long)(60 + k*C0C + c0)*HWP + p];
        ss[k] = P[(long long)(108+ k*C0C + c0)*HWP + p];
    }
    float a = tanhf(aRaw)*als[0] + ab[0];

    float mx = lp[0];
    #pragma unroll
    for (int k=1;k<KMIX;k++) mx = fmaxf(mx, lp[k]);
    float se = 0.f;
    #pragma unroll
    for (int k=0;k<KMIX;k++) se += __expf(lp[k]-mx);
    float lse = mx + __logf(se);

    float z0v = g_z0[((long long)b*C0C + c0)*HWP + p];
    float tvals[KMIX];
    float xsum = 0.f;
    #pragma unroll
    for (int k=0;k<KMIX;k++){
        float lpn = lp[k] - lse;
        float u   = (z0v - mu[k]) * __expf(-ss[k]);
        xsum += __expf(lpn) * sigf(u);
        tvals[k] = lpn - ss[k] + logsigf(u) + logsigf(-u);
    }
    float tm = tvals[0];
    #pragma unroll
    for (int k=1;k<KMIX;k++) tm = fmaxf(tm, tvals[k]);
    float tse = 0.f;
    #pragma unroll
    for (int k=0;k<KMIX;k++) tse += __expf(tvals[k]-tm);
    float logpdf = tm + __logf(tse);

    float x = fminf(fmaxf(xsum, 1e-6f), 1.0f-1e-6f);
    float lx  = __logf(x);
    float l1x = log1pf(-x);
    float z0n = (lx - l1x) * __expf(a) + bRaw;
    float contrib = logpdf + (-lx - l1x) + a;

    int i = p>>5, j = p&31;
    float z1v = g_z1[((long long)b*C0C + c0)*HWP + p];
    if (c0 < 3){
        float* ob = out_z + ((long long)b*3 + c0)*64*64;
        ob[(2*i)*64 + 2*j    ] = z0n;
        ob[(2*i)*64 + 2*j + 1] = z1v;
    } else {
        float* ob = out_z + ((long long)b*3 + (c0-3))*64*64;
        ob[(2*i+1)*64 + 2*j + 1] = z0n;
        ob[(2*i+1)*64 + 2*j    ] = z1v;
    }

    __shared__ float sh[32];
    int lane = p&31, wid = p>>5;
    float v = warp_sum(contrib);
    if (lane==0) sh[wid]=v;
    __syncthreads();
    if (wid==0){
        float w = (lane<32)? sh[lane] : 0.f;
        w = warp_sum(w);
        if (lane==0) atomicAdd(&out_log[b], w);
    }
}

// ---------------- host launcher ----------------
extern "C" void kernel_launch(void* const* d_in, const int* in_sizes, int n_in,
                              void* d_out, int out_size){
    const float* z        = (const float*)d_in[0];
    const float* log_df   = (const float*)d_in[1];
    const float* conv1_w  = (const float*)d_in[2];
    const float* conv1_b  = (const float*)d_in[3];
    const float* gconv_w  = (const float*)d_in[4];
    const float* gconv_b  = (const float*)d_in[5];
    const float* ln1_g    = (const float*)d_in[6];
    const float* ln1_b    = (const float*)d_in[7];
    const float* qkv_w    = (const float*)d_in[8];
    const float* qkv_b    = (const float*)d_in[9];
    const float* proj_w   = (const float*)d_in[10];
    const float* proj_b   = (const float*)d_in[11];
    const float* ln2_g    = (const float*)d_in[12];
    const float* ln2_b    = (const float*)d_in[13];
    const float* conv2_w  = (const float*)d_in[14];
    const float* conv2_b  = (const float*)d_in[15];
    const float* a_ls     = (const float*)d_in[16];
    const float* a_bias   = (const float*)d_in[17];

    float* out_z   = (float*)d_out;
    float* out_log = (float*)d_out + (long long)BATCH*3*64*64;

    float *p_z1, *p_xg, *p_xf, *p_qkv, *p_o, *p_x2, *p_st1, *p_st2, *p_pr, *p_wt1, *p_wt2;
    float *p_sum1, *p_sum2;
    cudaGetSymbolAddress((void**)&p_z1,  g_z1);
    cudaGetSymbolAddress((void**)&p_xg,  g_xg);
    cudaGetSymbolAddress((void**)&p_xf,  g_xf);
    cudaGetSymbolAddress((void**)&p_qkv, g_qkv);
    cudaGetSymbolAddress((void**)&p_o,   g_o);
    cudaGetSymbolAddress((void**)&p_x2,  g_x2);
    cudaGetSymbolAddress((void**)&p_st1, g_st1);
    cudaGetSymbolAddress((void**)&p_st2, g_st2);
    cudaGetSymbolAddress((void**)&p_pr,  g_pr);
    cudaGetSymbolAddress((void**)&p_wt1, g_wt1);
    cudaGetSymbolAddress((void**)&p_wt2, g_wt2);
    cudaGetSymbolAddress((void**)&p_sum1, g_sum1);
    cudaGetSymbolAddress((void**)&p_sum2, g_sum2);

    const int FLASH_SMEM = (128*QLD + 64*KLD + 64*VLD)*4;
    const int GCONV_SMEM = (64*SB_LD > 2*(WS_CH+TL_CH) ? 64*SB_LD : 2*(WS_CH+TL_CH))*4;
    const int CONV2_SMEM = 2*(WS_CH+TL_CH)*4;
    const int GEMM_SMEM  = (64*100 + 96*100)*4;
    static int smem_set = 0;
    if (!smem_set){
        cudaFuncSetAttribute(flash_tf32_kernel, cudaFuncAttributeMaxDynamicSharedMemorySize, FLASH_SMEM);
        cudaFuncSetAttribute(conv_mma_kernel<true>,  cudaFuncAttributeMaxDynamicSharedMemorySize, GCONV_SMEM);
        cudaFuncSetAttribute(conv_mma_kernel<false>, cudaFuncAttributeMaxDynamicSharedMemorySize, CONV2_SMEM);
        cudaFuncSetAttribute(gemm_tf32_kernel, cudaFuncAttributeMaxDynamicSharedMemorySize, GEMM_SMEM);
        smem_set = 1;
    }

    const int WPREP_BLOCKS = (3*12*4608 + 255)/256;
    zero_sums_kernel<<<1, 256>>>();
    wprep_kernel<true><<<WPREP_BLOCKS, 256>>>(gconv_w, p_wt1);
    wprep_kernel<false><<<WPREP_BLOCKS, 256>>>(conv2_w, p_wt2);
    split_kernel<<<(BATCH*3*HWP+255)/256, 256>>>(z);
    conv1_kernel<<<dim3(12, BATCH), 256>>>(p_z1, conv1_w, conv1_b);
    conv_mma_kernel<true><<<dim3(4, 3, BATCH), 256, GCONV_SMEM>>>(p_wt1, gconv_b);
    ln_finalize_kernel<<<1, 64>>>(p_sum1, p_st1);
    ln1_transpose_kernel<<<dim3(32, 3, BATCH), 256>>>(ln1_g, ln1_b);
    gemm_tf32_kernel<<<dim3(3, 16, BATCH), 128, GEMM_SMEM>>>(p_xf, qkv_w, p_qkv, 3*FC, qkv_b);
    flash_tf32_kernel<<<dim3(8, BATCH), 256, FLASH_SMEM>>>();
    gemm_tf32_kernel<<<dim3(2, 16, BATCH), 128, GEMM_SMEM>>>(p_o, proj_w, p_pr, 2*FC, proj_b);
    gate_transpose_kernel<<<dim3(32, 3, BATCH), 256>>>();
    ln_finalize_kernel<<<1, 64>>>(p_sum2, p_st2);
    ln_apply_kernel<<<(BATCH*FC*HWP/4 + 255)/256, 256>>>(ln2_g, ln2_b);
    conv_mma_kernel<false><<<dim3(4, 3, BATCH), 256, CONV2_SMEM>>>(p_wt2, conv2_b);
    init_log_kernel<<<1, 64>>>(log_df, out_log);
    mixture_kernel<<<dim3(BATCH, C0C), 1024>>>(a_ls, a_bias, out_z, out_log);
}